// round 4
// baseline (speedup 1.0000x reference)
#include <cuda_runtime.h>
#include <cuda_bf16.h>
#include <cstdint>

// Problem constants
#define NB 2
#define TT 4096
#define DM 768
#define NH 12
#define DH 64
#define MROWS (NB * TT)   // 8192

typedef unsigned long long ull;

// Scratch in __device__ globals (allocation-free rule)
__device__ float g_q[(size_t)NB * NH * TT * DH];
__device__ float g_k[(size_t)NB * NH * TT * DH];
__device__ float g_v[(size_t)NB * NH * TT * DH];
__device__ float g_a[(size_t)NB * TT * DM];
__device__ float g_maskf[(size_t)NB * TT];

// ---------------------------------------------------------------------------
// Packed f32x2 helpers (FFMA2 path — ptxas never emits these from C++)
// ---------------------------------------------------------------------------
__device__ __forceinline__ ull bc2(float a) {
    ull d; unsigned ai = __float_as_uint(a);
    asm("mov.b64 %0, {%1, %1};" : "=l"(d) : "r"(ai));
    return d;
}
__device__ __forceinline__ ull pk2(float lo, float hi) {
    ull d;
    asm("mov.b64 %0, {%1, %2};" : "=l"(d)
        : "r"(__float_as_uint(lo)), "r"(__float_as_uint(hi)));
    return d;
}
__device__ __forceinline__ void up2(ull v, float& lo, float& hi) {
    unsigned a, b;
    asm("mov.b64 {%0, %1}, %2;" : "=r"(a), "=r"(b) : "l"(v));
    lo = __uint_as_float(a); hi = __uint_as_float(b);
}
__device__ __forceinline__ void fma2(ull& d, ull a, ull b) {
    asm("fma.rn.f32x2 %0, %1, %2, %0;" : "+l"(d) : "l"(a), "l"(b));
}
__device__ __forceinline__ ull fma2n(ull a, ull b, ull c) {
    ull d;
    asm("fma.rn.f32x2 %0, %1, %2, %3;" : "=l"(d) : "l"(a), "l"(b), "l"(c));
    return d;
}
__device__ __forceinline__ ull mul2(ull a, ull b) {
    ull d;
    asm("mul.rn.f32x2 %0, %1, %2;" : "=l"(d) : "l"(a), "l"(b));
    return d;
}

// ---------------------------------------------------------------------------
// Mask (bool serialized as int32) -> additive float bias (0 or -1e30)
// ---------------------------------------------------------------------------
__global__ void mask_to_f_kernel(const int* __restrict__ mask,
                                 float* __restrict__ out, int n) {
    int i = blockIdx.x * blockDim.x + threadIdx.x;
    if (i < n) out[i] = mask[i] ? -1e30f : 0.0f;
}

// ---------------------------------------------------------------------------
// C = A @ B^T + bias with f32x2 math. 128x128 tile, BK=16, 256 threads,
// 8x8 microtile (8 rows x 4 col-pairs of packed accumulators).
// MODE 0: plain [M,768] (output projection). MODE 1: head-split [n,h,t,dh].
// ---------------------------------------------------------------------------
template <int MODE>
__global__ __launch_bounds__(256)
void gemm_abt2_kernel(const float* __restrict__ A, const float* __restrict__ B,
                      const float* __restrict__ bias, float* __restrict__ C) {
    __shared__ float As[16][128];   // As[k][row]
    __shared__ float Bs[16][128];   // Bs[k][col]

    const int tid = threadIdx.x;
    const int tx = tid & 15;   // col group (8 cols)
    const int ty = tid >> 4;   // row group (8 rows)
    const int row0 = blockIdx.x * 128;
    const int col0 = blockIdx.y * 128;

    ull acc2[8][4];
#pragma unroll
    for (int i = 0; i < 8; i++)
#pragma unroll
        for (int j = 0; j < 4; j++) acc2[i][j] = 0ull;

    for (int k0 = 0; k0 < DM; k0 += 16) {
        // Load A,B tiles transposed into smem (scalar STS, lanes hit
        // consecutive rows/cols -> conflict-free).
#pragma unroll
        for (int it = 0; it < 2; it++) {
            int i = tid + it * 256;
            int r = i & 127;
            int kq = (i >> 7) << 2;
            float4 a4 = *reinterpret_cast<const float4*>(
                &A[(size_t)(row0 + r) * DM + k0 + kq]);
            As[kq + 0][r] = a4.x; As[kq + 1][r] = a4.y;
            As[kq + 2][r] = a4.z; As[kq + 3][r] = a4.w;
            float4 b4 = *reinterpret_cast<const float4*>(
                &B[(size_t)(col0 + r) * DM + k0 + kq]);
            Bs[kq + 0][r] = b4.x; Bs[kq + 1][r] = b4.y;
            Bs[kq + 2][r] = b4.z; Bs[kq + 3][r] = b4.w;
        }
        __syncthreads();

#pragma unroll
        for (int k = 0; k < 16; k++) {
            float4 a03 = *reinterpret_cast<const float4*>(&As[k][8 * ty]);
            float4 a47 = *reinterpret_cast<const float4*>(&As[k][8 * ty + 4]);
            ull ab[8] = {bc2(a03.x), bc2(a03.y), bc2(a03.z), bc2(a03.w),
                         bc2(a47.x), bc2(a47.y), bc2(a47.z), bc2(a47.w)};
            ulonglong2 b01 = *reinterpret_cast<const ulonglong2*>(&Bs[k][8 * tx]);
            ulonglong2 b23 = *reinterpret_cast<const ulonglong2*>(&Bs[k][8 * tx + 4]);
            ull bp[4] = {b01.x, b01.y, b23.x, b23.y};
#pragma unroll
            for (int ri = 0; ri < 8; ri++)
#pragma unroll
                for (int cp = 0; cp < 4; cp++) fma2(acc2[ri][cp], ab[ri], bp[cp]);
        }
        __syncthreads();
    }

    // Epilogue
    float bsv[8];
#pragma unroll
    for (int j = 0; j < 8; j++) bsv[j] = bias[col0 + 8 * tx + j];

#pragma unroll
    for (int ri = 0; ri < 8; ri++) {
        int row = row0 + 8 * ty + ri;
        float ov[8];
#pragma unroll
        for (int cp = 0; cp < 4; cp++) {
            float lo, hi; up2(acc2[ri][cp], lo, hi);
            ov[2 * cp] = lo + bsv[2 * cp];
            ov[2 * cp + 1] = hi + bsv[2 * cp + 1];
        }
        float4 r0 = make_float4(ov[0], ov[1], ov[2], ov[3]);
        float4 r1 = make_float4(ov[4], ov[5], ov[6], ov[7]);
        if (MODE == 0) {
            float* cp0 = &C[(size_t)row * DM + col0 + 8 * tx];
            *reinterpret_cast<float4*>(cp0) = r0;
            *reinterpret_cast<float4*>(cp0 + 4) = r1;
        } else {
            int n = row >> 12;
            int t = row & (TT - 1);
            int h = (col0 >> 6) + (tx >> 3);
            size_t base = (((size_t)(n * NH + h)) * TT + t) * DH + 8 * (tx & 7);
            *reinterpret_cast<float4*>(&C[base]) = r0;
            *reinterpret_cast<float4*>(&C[base + 4]) = r1;
        }
    }
}

// ---------------------------------------------------------------------------
// Flash attention, f32x2 packed math. One CTA = 128 queries of one (n,h).
// 128 threads as 16(ty) x 8(tx); thread owns rows 8ty..8ty+7 (as 4 row-pairs)
// x cols 8tx..8tx+7, and O rows x dims 8tx..8tx+7.
// Dynamic smem 96KB: Qt[64][128] | Kt[64][64] | Vs[64][64] | Pt[64][128].
// ---------------------------------------------------------------------------
__global__ __launch_bounds__(128)
void flash_attn2_kernel(const float* __restrict__ Qg, const float* __restrict__ Kg,
                        const float* __restrict__ Vg, const float* __restrict__ mbf,
                        float* __restrict__ Ag) {
    extern __shared__ float sm[];
    float* Qt = sm;                  // [d][r] 32KB
    float* Kt = sm + 64 * 128;       // [d][c] 16KB
    float* Vs = Kt + 64 * 64;        // [c][d] 16KB
    float* Pt = Vs + 64 * 64;        // [c][r] 32KB (row-pair swizzled)

    const int n = blockIdx.z, h = blockIdx.y;
    const int q0 = blockIdx.x * 128;
    const size_t headBase = ((size_t)(n * NH + h)) * TT * DH;
    const float* Qb = Qg + headBase + (size_t)q0 * DH;
    const float* Kb = Kg + headBase;
    const float* Vb = Vg + headBase;
    const float* mb = mbf + (size_t)n * TT;

    const int tid = threadIdx.x;
    const int tx = tid & 7;
    const int ty = tid >> 3;

    // Load Q transposed: Qt[d][r] = Q[r][d] (scalar STS, lanes->consecutive r)
    for (int i = tid; i < 2048; i += 128) {
        int r = i & 127;
        int d0 = (i >> 7) << 2;
        float4 v = *reinterpret_cast<const float4*>(&Qb[(size_t)r * DH + d0]);
        Qt[(d0 + 0) * 128 + r] = v.x;
        Qt[(d0 + 1) * 128 + r] = v.y;
        Qt[(d0 + 2) * 128 + r] = v.z;
        Qt[(d0 + 3) * 128 + r] = v.w;
    }
    __syncthreads();

    ull o2[4][8];
#pragma unroll
    for (int a = 0; a < 4; a++)
#pragma unroll
        for (int b = 0; b < 8; b++) o2[a][b] = 0ull;
    float mrow[8], lrow[8];
#pragma unroll
    for (int i = 0; i < 8; i++) { mrow[i] = -1e30f; lrow[i] = 0.0f; }

    const ull sc2 = 0x3E0000003E000000ull;  // {0.125f, 0.125f}

    for (int kb = 0; kb < TT / 64; kb++) {
        const int c0 = kb * 64;
        // Skip fully-masked key tiles; also the inter-tile barrier.
        float mv = (tid < 64) ? mb[c0 + tid] : -1.0f;
        int alive = __syncthreads_count((tid < 64) && (mv == 0.0f));
        if (alive == 0) continue;

        // Load K transposed, V natural
        for (int i = tid; i < 1024; i += 128) {
            int c = i & 63;
            int d0 = (i >> 6) << 2;
            float4 v = *reinterpret_cast<const float4*>(
                &Kb[(size_t)(c0 + c) * DH + d0]);
            Kt[(d0 + 0) * 64 + c] = v.x;
            Kt[(d0 + 1) * 64 + c] = v.y;
            Kt[(d0 + 2) * 64 + c] = v.z;
            Kt[(d0 + 3) * 64 + c] = v.w;
        }
        for (int i = tid; i < 1024; i += 128) {
            reinterpret_cast<float4*>(Vs)[i] =
                reinterpret_cast<const float4*>(Vb + (size_t)c0 * DH)[i];
        }
        __syncthreads();

        // ---- S = Q K^T (row-pair packed accumulators) ----
        ull s2[4][8];
#pragma unroll
        for (int a = 0; a < 4; a++)
#pragma unroll
            for (int b = 0; b < 8; b++) s2[a][b] = 0ull;

#pragma unroll 1
        for (int d = 0; d < 64; d++) {
            const float* qp = &Qt[d * 128 + 8 * ty];
            ulonglong2 qa = *reinterpret_cast<const ulonglong2*>(qp);
            ulonglong2 qb = *reinterpret_cast<const ulonglong2*>(qp + 4);
            ull qpair[4] = {qa.x, qa.y, qb.x, qb.y};
            const float* kp = &Kt[d * 64 + 8 * tx];
            float4 k03 = *reinterpret_cast<const float4*>(kp);
            float4 k47 = *reinterpret_cast<const float4*>(kp + 4);
            ull kb2[8] = {bc2(k03.x), bc2(k03.y), bc2(k03.z), bc2(k03.w),
                          bc2(k47.x), bc2(k47.y), bc2(k47.z), bc2(k47.w)};
#pragma unroll
            for (int rp = 0; rp < 4; rp++)
#pragma unroll
                for (int ci = 0; ci < 8; ci++) fma2(s2[rp][ci], qpair[rp], kb2[ci]);
        }

        // ---- scale + mask (packed) ----
        float4 m03 = *reinterpret_cast<const float4*>(&mb[c0 + 8 * tx]);
        float4 m47 = *reinterpret_cast<const float4*>(&mb[c0 + 8 * tx + 4]);
        float mcol[8] = {m03.x, m03.y, m03.z, m03.w, m47.x, m47.y, m47.z, m47.w};
#pragma unroll
        for (int ci = 0; ci < 8; ci++) {
            ull madd2 = bc2(mcol[ci]);
#pragma unroll
            for (int rp = 0; rp < 4; rp++)
                s2[rp][ci] = fma2n(s2[rp][ci], sc2, madd2);
        }

        // ---- online softmax (rows: lr = 2rp + half) ----
        float tmax[8];
#pragma unroll
        for (int i = 0; i < 8; i++) tmax[i] = -1e30f;
#pragma unroll
        for (int rp = 0; rp < 4; rp++)
#pragma unroll
            for (int ci = 0; ci < 8; ci++) {
                float lo, hi; up2(s2[rp][ci], lo, hi);
                tmax[2 * rp]     = fmaxf(tmax[2 * rp], lo);
                tmax[2 * rp + 1] = fmaxf(tmax[2 * rp + 1], hi);
            }
        float mn[8], corr[8];
#pragma unroll
        for (int lr = 0; lr < 8; lr++) {
            float t = tmax[lr];
            t = fmaxf(t, __shfl_xor_sync(0xffffffffu, t, 1));
            t = fmaxf(t, __shfl_xor_sync(0xffffffffu, t, 2));
            t = fmaxf(t, __shfl_xor_sync(0xffffffffu, t, 4));
            mn[lr] = fmaxf(mrow[lr], t);
            corr[lr] = __expf(mrow[lr] - mn[lr]);
            mrow[lr] = mn[lr];
        }
        float rs[8];
#pragma unroll
        for (int i = 0; i < 8; i++) rs[i] = 0.0f;
#pragma unroll
        for (int rp = 0; rp < 4; rp++)
#pragma unroll
            for (int ci = 0; ci < 8; ci++) {
                float lo, hi; up2(s2[rp][ci], lo, hi);
                float p0 = __expf(lo - mn[2 * rp]);
                float p1 = __expf(hi - mn[2 * rp + 1]);
                s2[rp][ci] = pk2(p0, p1);
                rs[2 * rp] += p0; rs[2 * rp + 1] += p1;
            }
#pragma unroll
        for (int lr = 0; lr < 8; lr++) {
            float r = rs[lr];
            r += __shfl_xor_sync(0xffffffffu, r, 1);
            r += __shfl_xor_sync(0xffffffffu, r, 2);
            r += __shfl_xor_sync(0xffffffffu, r, 4);
            lrow[lr] = lrow[lr] * corr[lr] + r;
        }
#pragma unroll
        for (int rp = 0; rp < 4; rp++) {
            ull c2 = pk2(corr[2 * rp], corr[2 * rp + 1]);
#pragma unroll
            for (int di = 0; di < 8; di++) o2[rp][di] = mul2(o2[rp][di], c2);
        }

        // ---- store P^T as row-pairs (swizzled by c>>3 == writer's tx) ----
#pragma unroll
        for (int ci = 0; ci < 8; ci++) {
            float* pb = &Pt[(8 * tx + ci) * 128];
            int sw = tx << 2;
#pragma unroll
            for (int rp = 0; rp < 4; rp++)
                *reinterpret_cast<ull*>(&pb[(8 * ty + 2 * rp) ^ sw]) = s2[rp][ci];
        }
        __syncthreads();

        // ---- O += P @ V (row-pair packed) ----
#pragma unroll 1
        for (int c = 0; c < 64; c++) {
            int sw = ((c >> 3) & 7) << 2;
            const float* pb = &Pt[c * 128];
            ull p2[4];
#pragma unroll
            for (int rp = 0; rp < 4; rp++)
                p2[rp] = *reinterpret_cast<const ull*>(&pb[(8 * ty + 2 * rp) ^ sw]);
            const float* vp = &Vs[c * 64 + 8 * tx];
            float4 v03 = *reinterpret_cast<const float4*>(vp);
            float4 v47 = *reinterpret_cast<const float4*>(vp + 4);
            ull vb2[8] = {bc2(v03.x), bc2(v03.y), bc2(v03.z), bc2(v03.w),
                          bc2(v47.x), bc2(v47.y), bc2(v47.z), bc2(v47.w)};
#pragma unroll
            for (int rp = 0; rp < 4; rp++)
#pragma unroll
                for (int di = 0; di < 8; di++) fma2(o2[rp][di], p2[rp], vb2[di]);
        }
    }

    // ---- normalize + write [n, t, h*64 + d] ----
#pragma unroll
    for (int rp = 0; rp < 4; rp++) {
        float inv0 = 1.0f / lrow[2 * rp];
        float inv1 = 1.0f / lrow[2 * rp + 1];
        float out0[8], out1[8];
#pragma unroll
        for (int di = 0; di < 8; di++) {
            float lo, hi; up2(o2[rp][di], lo, hi);
            out0[di] = lo * inv0;
            out1[di] = hi * inv1;
        }
        size_t b0 = ((size_t)n * TT + q0 + 8 * ty + 2 * rp) * DM + h * DH + 8 * tx;
        *reinterpret_cast<float4*>(&Ag[b0]) =
            make_float4(out0[0], out0[1], out0[2], out0[3]);
        *reinterpret_cast<float4*>(&Ag[b0 + 4]) =
            make_float4(out0[4], out0[5], out0[6], out0[7]);
        size_t b1 = b0 + DM;
        *reinterpret_cast<float4*>(&Ag[b1]) =
            make_float4(out1[0], out1[1], out1[2], out1[3]);
        *reinterpret_cast<float4*>(&Ag[b1 + 4]) =
            make_float4(out1[4], out1[5], out1[6], out1[7]);
    }
}

// ---------------------------------------------------------------------------
// Launch
// ---------------------------------------------------------------------------
extern "C" void kernel_launch(void* const* d_in, const int* in_sizes, int n_in,
                              void* d_out, int out_size) {
    const float* x  = (const float*)d_in[0];
    const int*   mask = (const int*)d_in[1];
    const float* Wq = (const float*)d_in[2];
    const float* bq = (const float*)d_in[3];
    const float* Wk = (const float*)d_in[4];
    const float* bk = (const float*)d_in[5];
    const float* Wv = (const float*)d_in[6];
    const float* bv = (const float*)d_in[7];
    const float* Wo = (const float*)d_in[8];
    const float* bo = (const float*)d_in[9];
    float* out = (float*)d_out;

    float *q, *k, *v, *a, *mf;
    cudaGetSymbolAddress((void**)&q,  g_q);
    cudaGetSymbolAddress((void**)&k,  g_k);
    cudaGetSymbolAddress((void**)&v,  g_v);
    cudaGetSymbolAddress((void**)&a,  g_a);
    cudaGetSymbolAddress((void**)&mf, g_maskf);

    cudaFuncSetAttribute(flash_attn2_kernel,
                         cudaFuncAttributeMaxDynamicSharedMemorySize, 98304);

    mask_to_f_kernel<<<(NB * TT + 255) / 256, 256>>>(mask, mf, NB * TT);

    dim3 ggrid(MROWS / 128, DM / 128);
    gemm_abt2_kernel<1><<<ggrid, 256>>>(x, Wq, bq, q);
    gemm_abt2_kernel<1><<<ggrid, 256>>>(x, Wk, bk, k);
    gemm_abt2_kernel<1><<<ggrid, 256>>>(x, Wv, bv, v);

    dim3 agrid(TT / 128, NH, NB);
    flash_attn2_kernel<<<agrid, 128, 98304>>>(q, k, v, mf, a);

    gemm_abt2_kernel<0><<<ggrid, 256>>>(a, Wo, bo, out);
}

// round 7
// speedup vs baseline: 3.0547x; 3.0547x over previous
#include <cuda_runtime.h>
#include <cuda_bf16.h>
#include <cstdint>

#define NB 2
#define TT 4096
#define DM 768
#define NH 12
#define DH 64
#define MROWS (NB * TT)   // 8192

typedef uint32_t u32;

// Scratch in __device__ globals (allocation-free rule)
__device__ __nv_bfloat16 g_qh[(size_t)MROWS * DM];
__device__ __nv_bfloat16 g_ql[(size_t)MROWS * DM];
__device__ __nv_bfloat16 g_kh[(size_t)MROWS * DM];
__device__ __nv_bfloat16 g_kl[(size_t)MROWS * DM];
__device__ __nv_bfloat16 g_vh[(size_t)MROWS * DM];
__device__ __nv_bfloat16 g_vl[(size_t)MROWS * DM];
__device__ float g_a[(size_t)MROWS * DM];
__device__ float g_maskf[(size_t)NB * TT];

// ---------------------------------------------------------------------------
// MMA / ldmatrix helpers
// ---------------------------------------------------------------------------
__device__ __forceinline__ u32 s2u(const void* p) {
    return (u32)__cvta_generic_to_shared(p);
}
__device__ __forceinline__ void ldsm4(u32& r0, u32& r1, u32& r2, u32& r3, u32 a) {
    asm volatile("ldmatrix.sync.aligned.m8n8.x4.shared.b16 {%0,%1,%2,%3},[%4];"
                 : "=r"(r0), "=r"(r1), "=r"(r2), "=r"(r3) : "r"(a));
}
__device__ __forceinline__ void ldsm4t(u32& r0, u32& r1, u32& r2, u32& r3, u32 a) {
    asm volatile("ldmatrix.sync.aligned.m8n8.x4.trans.shared.b16 {%0,%1,%2,%3},[%4];"
                 : "=r"(r0), "=r"(r1), "=r"(r2), "=r"(r3) : "r"(a));
}
__device__ __forceinline__ void mma16816(float* c, u32 a0, u32 a1, u32 a2, u32 a3,
                                         u32 b0, u32 b1) {
    asm volatile(
        "mma.sync.aligned.m16n8k16.row.col.f32.bf16.bf16.f32 "
        "{%0,%1,%2,%3},{%4,%5,%6,%7},{%8,%9},{%0,%1,%2,%3};"
        : "+f"(c[0]), "+f"(c[1]), "+f"(c[2]), "+f"(c[3])
        : "r"(a0), "r"(a1), "r"(a2), "r"(a3), "r"(b0), "r"(b1));
}
__device__ __forceinline__ u32 pkbf(float lo, float hi) {
    __nv_bfloat162 t = __floats2bfloat162_rn(lo, hi);
    return *reinterpret_cast<u32*>(&t);
}
// Swizzled byte offset in a tile with 128B rows (8x 16B chunks per row)
__device__ __forceinline__ u32 swz(int row, int chunk) {
    return (u32)(row * 128 + ((chunk ^ (row & 7)) << 4));
}
// ldmatrix.x4 per-lane address for a 16-row x 2-chunk region at (r0, c0)
__device__ __forceinline__ u32 frag_addr(u32 base, int r0, int c0, int lane) {
    return base + swz(r0 + (lane & 15), c0 + (lane >> 4));
}

// ---------------------------------------------------------------------------
// Mask (bool serialized as int32) -> additive float bias (0 or -1e30)
// ---------------------------------------------------------------------------
__global__ void mask_to_f_kernel(const int* __restrict__ mask,
                                 float* __restrict__ out, int n) {
    int i = blockIdx.x * blockDim.x + threadIdx.x;
    if (i < n) out[i] = mask[i] ? -1e30f : 0.0f;
}

// ---------------------------------------------------------------------------
// C = A @ B^T + bias via mma.sync bf16x3 (hi*hi + hi*lo + lo*hi).
// 128x128 tile, BK=64, 256 threads (8 warps as 2m x 4n, warp tile 64x32).
// MODE 0: fp32 [M,768] to C.  MODE 1: split bf16 hi/lo head-split [n,h,t,dh].
// Dynamic smem 64KB: Ah/Al/Bh/Bl each [128 rows][64 bf16] (128B rows, SW128).
// ---------------------------------------------------------------------------
template <int MODE>
__global__ __launch_bounds__(256, 2)
void gemm_mma_kernel(const float* __restrict__ A, const float* __restrict__ B,
                     const float* __restrict__ bias, float* __restrict__ C,
                     __nv_bfloat16* __restrict__ Ch, __nv_bfloat16* __restrict__ Cl) {
    extern __shared__ char smraw[];
    char* Ah = smraw;            // 16KB
    char* Al = smraw + 16384;
    char* Bh = smraw + 32768;
    char* Bl = smraw + 49152;
    const u32 AhB = s2u(Ah), AlB = s2u(Al), BhB = s2u(Bh), BlB = s2u(Bl);

    const int tid = threadIdx.x, lane = tid & 31, wid = tid >> 5;
    const int wm = wid >> 2, wn = wid & 3;
    const int row0 = blockIdx.x * 128, col0 = blockIdx.y * 128;

    float acc[4][4][4];
#pragma unroll
    for (int a = 0; a < 4; a++)
#pragma unroll
        for (int b = 0; b < 4; b++)
#pragma unroll
            for (int c = 0; c < 4; c++) acc[a][b][c] = 0.0f;

    for (int k0 = 0; k0 < DM; k0 += 64) {
        // Stage + split A and B tiles (fp32 -> bf16 hi/lo, swizzled)
        for (int i = tid; i < 2048; i += 256) {
            int r = i >> 4, c4 = (i & 15) << 2;
            u32 off = swz(r, c4 >> 3) + ((c4 & 7) << 1);
            float4 av = *reinterpret_cast<const float4*>(
                &A[(size_t)(row0 + r) * DM + k0 + c4]);
            __nv_bfloat162 h01 = __floats2bfloat162_rn(av.x, av.y);
            __nv_bfloat162 h23 = __floats2bfloat162_rn(av.z, av.w);
            float2 f01 = __bfloat1622float2(h01);
            float2 f23 = __bfloat1622float2(h23);
            __nv_bfloat162 l01 = __floats2bfloat162_rn(av.x - f01.x, av.y - f01.y);
            __nv_bfloat162 l23 = __floats2bfloat162_rn(av.z - f23.x, av.w - f23.y);
            *reinterpret_cast<uint2*>(Ah + off) =
                make_uint2(*(u32*)&h01, *(u32*)&h23);
            *reinterpret_cast<uint2*>(Al + off) =
                make_uint2(*(u32*)&l01, *(u32*)&l23);

            float4 bv = *reinterpret_cast<const float4*>(
                &B[(size_t)(col0 + r) * DM + k0 + c4]);
            __nv_bfloat162 bh01 = __floats2bfloat162_rn(bv.x, bv.y);
            __nv_bfloat162 bh23 = __floats2bfloat162_rn(bv.z, bv.w);
            float2 g01 = __bfloat1622float2(bh01);
            float2 g23 = __bfloat1622float2(bh23);
            __nv_bfloat162 bl01 = __floats2bfloat162_rn(bv.x - g01.x, bv.y - g01.y);
            __nv_bfloat162 bl23 = __floats2bfloat162_rn(bv.z - g23.x, bv.w - g23.y);
            *reinterpret_cast<uint2*>(Bh + off) =
                make_uint2(*(u32*)&bh01, *(u32*)&bh23);
            *reinterpret_cast<uint2*>(Bl + off) =
                make_uint2(*(u32*)&bl01, *(u32*)&bl23);
        }
        __syncthreads();

#pragma unroll
        for (int kt = 0; kt < 4; kt++) {
            u32 bh[4][2], bl[4][2];
#pragma unroll
            for (int half = 0; half < 2; half++) {
                u32 r0, r1, r2, r3;
                ldsm4(r0, r1, r2, r3, frag_addr(BhB, wn * 32 + half * 16, kt * 2, lane));
                bh[2 * half][0] = r0; bh[2 * half + 1][0] = r1;
                bh[2 * half][1] = r2; bh[2 * half + 1][1] = r3;
                ldsm4(r0, r1, r2, r3, frag_addr(BlB, wn * 32 + half * 16, kt * 2, lane));
                bl[2 * half][0] = r0; bl[2 * half + 1][0] = r1;
                bl[2 * half][1] = r2; bl[2 * half + 1][1] = r3;
            }
#pragma unroll
            for (int mt = 0; mt < 4; mt++) {
                u32 ah[4], al[4];
                ldsm4(ah[0], ah[1], ah[2], ah[3],
                      frag_addr(AhB, wm * 64 + mt * 16, kt * 2, lane));
                ldsm4(al[0], al[1], al[2], al[3],
                      frag_addr(AlB, wm * 64 + mt * 16, kt * 2, lane));
#pragma unroll
                for (int nt = 0; nt < 4; nt++) {
                    mma16816(acc[mt][nt], ah[0], ah[1], ah[2], ah[3], bh[nt][0], bh[nt][1]);
                    mma16816(acc[mt][nt], ah[0], ah[1], ah[2], ah[3], bl[nt][0], bl[nt][1]);
                    mma16816(acc[mt][nt], al[0], al[1], al[2], al[3], bh[nt][0], bh[nt][1]);
                }
            }
        }
        __syncthreads();
    }

    // Epilogue
    const int g = lane >> 2, t4 = lane & 3;
#pragma unroll
    for (int mt = 0; mt < 4; mt++)
#pragma unroll
        for (int nt = 0; nt < 4; nt++) {
            int col = col0 + wn * 32 + nt * 8 + t4 * 2;
            float bv0 = bias[col], bv1 = bias[col + 1];
#pragma unroll
            for (int half = 0; half < 2; half++) {
                int row = row0 + wm * 64 + mt * 16 + g + half * 8;
                float c0 = acc[mt][nt][2 * half] + bv0;
                float c1 = acc[mt][nt][2 * half + 1] + bv1;
                if (MODE == 0) {
                    *reinterpret_cast<float2*>(&C[(size_t)row * DM + col]) =
                        make_float2(c0, c1);
                } else {
                    int n = row >> 12, t = row & (TT - 1);
                    int h = col >> 6, d = col & 63;
                    size_t idx = (((size_t)(n * NH + h)) * TT + t) * DH + d;
                    __nv_bfloat162 hi = __floats2bfloat162_rn(c0, c1);
                    float2 hf = __bfloat1622float2(hi);
                    __nv_bfloat162 lo = __floats2bfloat162_rn(c0 - hf.x, c1 - hf.y);
                    *reinterpret_cast<__nv_bfloat162*>(&Ch[idx]) = hi;
                    *reinterpret_cast<__nv_bfloat162*>(&Cl[idx]) = lo;
                }
            }
        }
}

// ---------------------------------------------------------------------------
// Flash attention via mma.sync bf16x3. CTA = 128 queries of one (n,h),
// 8 warps, warp owns 16 query rows. K-tile = 64 keys per iteration.
// smem: Qh/Ql [128][64] bf16 (16KB ea) + Kh/Kl/Vh/Vl [64][64] (8KB ea) + mask.
// ---------------------------------------------------------------------------
__global__ __launch_bounds__(256, 2)
void flash_mma_kernel(const __nv_bfloat16* __restrict__ Qhg,
                      const __nv_bfloat16* __restrict__ Qlg,
                      const __nv_bfloat16* __restrict__ Khg,
                      const __nv_bfloat16* __restrict__ Klg,
                      const __nv_bfloat16* __restrict__ Vhg,
                      const __nv_bfloat16* __restrict__ Vlg,
                      const float* __restrict__ mbf, float* __restrict__ Ag) {
    extern __shared__ char smraw[];
    char* Qh = smraw;              // 16KB
    char* Ql = smraw + 16384;      // 16KB
    char* Kh = smraw + 32768;      // 8KB
    char* Kl = smraw + 40960;
    char* Vh = smraw + 49152;
    char* Vl = smraw + 57344;
    float* msm = reinterpret_cast<float*>(smraw + 65536);  // 64 floats
    const u32 QhB = s2u(Qh), QlB = s2u(Ql), KhB = s2u(Kh), KlB = s2u(Kl);
    const u32 VhB = s2u(Vh), VlB = s2u(Vl);

    const int n = blockIdx.z, h = blockIdx.y;
    const int q0 = blockIdx.x * 128;
    const size_t hb = ((size_t)(n * NH + h)) * TT * DH;
    const float* mb = mbf + (size_t)n * TT;

    const int tid = threadIdx.x, lane = tid & 31, wid = tid >> 5;
    const int g = lane >> 2, t4 = lane & 3;

    // Stage Q hi/lo (once): rows are already 64 bf16 = 128B
    for (int i = tid; i < 1024; i += 256) {
        int r = i >> 3, c = i & 7;
        u32 off = swz(r, c);
        *reinterpret_cast<float4*>(Qh + off) = *reinterpret_cast<const float4*>(
            &Qhg[hb + (size_t)(q0 + r) * DH + c * 8]);
        *reinterpret_cast<float4*>(Ql + off) = *reinterpret_cast<const float4*>(
            &Qlg[hb + (size_t)(q0 + r) * DH + c * 8]);
    }

    float oacc[8][4];
#pragma unroll
    for (int a = 0; a < 8; a++)
#pragma unroll
        for (int b = 0; b < 4; b++) oacc[a][b] = 0.0f;
    float mrow0 = -1e30f, mrow1 = -1e30f, lrow0 = 0.0f, lrow1 = 0.0f;

    for (int kb = 0; kb < TT / 64; kb++) {
        const int c0 = kb * 64;
        float mv = (tid < 64) ? mb[c0 + tid] : -1.0f;
        if (tid < 64) msm[tid] = mv;
        int alive = __syncthreads_count((tid < 64) && (mv == 0.0f));
        if (alive == 0) continue;

        // Stage K,V hi/lo tiles
        for (int i = tid; i < 512; i += 256) {
            int r = i >> 3, c = i & 7;
            u32 off = swz(r, c);
            size_t gsrc = hb + (size_t)(c0 + r) * DH + c * 8;
            *reinterpret_cast<float4*>(Kh + off) =
                *reinterpret_cast<const float4*>(&Khg[gsrc]);
            *reinterpret_cast<float4*>(Kl + off) =
                *reinterpret_cast<const float4*>(&Klg[gsrc]);
            *reinterpret_cast<float4*>(Vh + off) =
                *reinterpret_cast<const float4*>(&Vhg[gsrc]);
            *reinterpret_cast<float4*>(Vl + off) =
                *reinterpret_cast<const float4*>(&Vlg[gsrc]);
        }
        __syncthreads();

        // ---- S = Q K^T ----
        float sacc[8][4];
#pragma unroll
        for (int a = 0; a < 8; a++)
#pragma unroll
            for (int b = 0; b < 4; b++) sacc[a][b] = 0.0f;

#pragma unroll
        for (int kt = 0; kt < 4; kt++) {
            u32 qh[4], ql[4];
            ldsm4(qh[0], qh[1], qh[2], qh[3], frag_addr(QhB, wid * 16, kt * 2, lane));
            ldsm4(ql[0], ql[1], ql[2], ql[3], frag_addr(QlB, wid * 16, kt * 2, lane));
#pragma unroll
            for (int half = 0; half < 4; half += 2) {  // key rows half*... 0,16,32,48
                // region rows = half*16? iterate two regions per loop body
            }
#pragma unroll
            for (int hf = 0; hf < 4; hf++) {   // 4 regions of 16 keys
                u32 k0r, k1r, k2r, k3r, l0r, l1r, l2r, l3r;
                ldsm4(k0r, k1r, k2r, k3r, frag_addr(KhB, hf * 16, kt * 2, lane));
                ldsm4(l0r, l1r, l2r, l3r, frag_addr(KlB, hf * 16, kt * 2, lane));
                mma16816(sacc[2 * hf],     qh[0], qh[1], qh[2], qh[3], k0r, k2r);
                mma16816(sacc[2 * hf],     qh[0], qh[1], qh[2], qh[3], l0r, l2r);
                mma16816(sacc[2 * hf],     ql[0], ql[1], ql[2], ql[3], k0r, k2r);
                mma16816(sacc[2 * hf + 1], qh[0], qh[1], qh[2], qh[3], k1r, k3r);
                mma16816(sacc[2 * hf + 1], qh[0], qh[1], qh[2], qh[3], l1r, l3r);
                mma16816(sacc[2 * hf + 1], ql[0], ql[1], ql[2], ql[3], k1r, k3r);
            }
        }

        // ---- scale + mask ----
#pragma unroll
        for (int nt = 0; nt < 8; nt++) {
            float mk0 = msm[nt * 8 + t4 * 2];
            float mk1 = msm[nt * 8 + t4 * 2 + 1];
            sacc[nt][0] = sacc[nt][0] * 0.125f + mk0;
            sacc[nt][1] = sacc[nt][1] * 0.125f + mk1;
            sacc[nt][2] = sacc[nt][2] * 0.125f + mk0;
            sacc[nt][3] = sacc[nt][3] * 0.125f + mk1;
        }

        // ---- online softmax (rows g and g+8 of this warp's 16) ----
        float rmax0 = -1e30f, rmax1 = -1e30f;
#pragma unroll
        for (int nt = 0; nt < 8; nt++) {
            rmax0 = fmaxf(rmax0, fmaxf(sacc[nt][0], sacc[nt][1]));
            rmax1 = fmaxf(rmax1, fmaxf(sacc[nt][2], sacc[nt][3]));
        }
        rmax0 = fmaxf(rmax0, __shfl_xor_sync(0xffffffffu, rmax0, 1));
        rmax0 = fmaxf(rmax0, __shfl_xor_sync(0xffffffffu, rmax0, 2));
        rmax1 = fmaxf(rmax1, __shfl_xor_sync(0xffffffffu, rmax1, 1));
        rmax1 = fmaxf(rmax1, __shfl_xor_sync(0xffffffffu, rmax1, 2));
        float mn0 = fmaxf(mrow0, rmax0), mn1 = fmaxf(mrow1, rmax1);
        float corr0 = __expf(mrow0 - mn0), corr1 = __expf(mrow1 - mn1);
        mrow0 = mn0; mrow1 = mn1;
        float rs0 = 0.0f, rs1 = 0.0f;
#pragma unroll
        for (int nt = 0; nt < 8; nt++) {
            sacc[nt][0] = __expf(sacc[nt][0] - mn0);
            sacc[nt][1] = __expf(sacc[nt][1] - mn0);
            sacc[nt][2] = __expf(sacc[nt][2] - mn1);
            sacc[nt][3] = __expf(sacc[nt][3] - mn1);
            rs0 += sacc[nt][0] + sacc[nt][1];
            rs1 += sacc[nt][2] + sacc[nt][3];
        }
        rs0 += __shfl_xor_sync(0xffffffffu, rs0, 1);
        rs0 += __shfl_xor_sync(0xffffffffu, rs0, 2);
        rs1 += __shfl_xor_sync(0xffffffffu, rs1, 1);
        rs1 += __shfl_xor_sync(0xffffffffu, rs1, 2);
        lrow0 = lrow0 * corr0 + rs0;
        lrow1 = lrow1 * corr1 + rs1;
#pragma unroll
        for (int dt = 0; dt < 8; dt++) {
            oacc[dt][0] *= corr0; oacc[dt][1] *= corr0;
            oacc[dt][2] *= corr1; oacc[dt][3] *= corr1;
        }

        // ---- O += P V ----
#pragma unroll
        for (int j = 0; j < 4; j++) {  // key k-tiles of 16
            u32 pa_h[4], pa_l[4];
            {
                __nv_bfloat162 h0 = __floats2bfloat162_rn(sacc[2 * j][0], sacc[2 * j][1]);
                __nv_bfloat162 h1 = __floats2bfloat162_rn(sacc[2 * j][2], sacc[2 * j][3]);
                __nv_bfloat162 h2 = __floats2bfloat162_rn(sacc[2 * j + 1][0], sacc[2 * j + 1][1]);
                __nv_bfloat162 h3 = __floats2bfloat162_rn(sacc[2 * j + 1][2], sacc[2 * j + 1][3]);
                float2 f0 = __bfloat1622float2(h0), f1 = __bfloat1622float2(h1);
                float2 f2 = __bfloat1622float2(h2), f3 = __bfloat1622float2(h3);
                pa_h[0] = *(u32*)&h0; pa_h[1] = *(u32*)&h1;
                pa_h[2] = *(u32*)&h2; pa_h[3] = *(u32*)&h3;
                pa_l[0] = pkbf(sacc[2 * j][0] - f0.x, sacc[2 * j][1] - f0.y);
                pa_l[1] = pkbf(sacc[2 * j][2] - f1.x, sacc[2 * j][3] - f1.y);
                pa_l[2] = pkbf(sacc[2 * j + 1][0] - f2.x, sacc[2 * j + 1][1] - f2.y);
                pa_l[3] = pkbf(sacc[2 * j + 1][2] - f3.x, sacc[2 * j + 1][3] - f3.y);
            }
#pragma unroll
            for (int c = 0; c < 4; c++) {  // d chunk pairs -> d-tiles 2c, 2c+1
                u32 v0, v1, v2, v3, w0, w1, w2, w3;
                ldsm4t(v0, v1, v2, v3, frag_addr(VhB, j * 16, c * 2, lane));
                ldsm4t(w0, w1, w2, w3, frag_addr(VlB, j * 16, c * 2, lane));
                mma16816(oacc[2 * c],     pa_h[0], pa_h[1], pa_h[2], pa_h[3], v0, v1);
                mma16816(oacc[2 * c],     pa_h[0], pa_h[1], pa_h[2], pa_h[3], w0, w1);
                mma16816(oacc[2 * c],     pa_l[0], pa_l[1], pa_l[2], pa_l[3], v0, v1);
                mma16816(oacc[2 * c + 1], pa_h[0], pa_h[1], pa_h[2], pa_h[3], v2, v3);
                mma16816(oacc[2 * c + 1], pa_h[0], pa_h[1], pa_h[2], pa_h[3], w2, w3);
                mma16816(oacc[2 * c + 1], pa_l[0], pa_l[1], pa_l[2], pa_l[3], v2, v3);
            }
        }
        // next iteration's __syncthreads_count protects smem reuse
    }

    // ---- normalize + write [n, t, h*64 + d] ----
    float inv0 = 1.0f / lrow0, inv1 = 1.0f / lrow1;
#pragma unroll
    for (int dt = 0; dt < 8; dt++) {
        int col = h * DH + dt * 8 + t4 * 2;
        size_t r1 = (size_t)n * TT + q0 + wid * 16 + g;
        *reinterpret_cast<float2*>(&Ag[r1 * DM + col]) =
            make_float2(oacc[dt][0] * inv0, oacc[dt][1] * inv0);
        *reinterpret_cast<float2*>(&Ag[(r1 + 8) * DM + col]) =
            make_float2(oacc[dt][2] * inv1, oacc[dt][3] * inv1);
    }
}

// ---------------------------------------------------------------------------
// Launch
// ---------------------------------------------------------------------------
extern "C" void kernel_launch(void* const* d_in, const int* in_sizes, int n_in,
                              void* d_out, int out_size) {
    const float* x  = (const float*)d_in[0];
    const int*   mask = (const int*)d_in[1];
    const float* Wq = (const float*)d_in[2];
    const float* bq = (const float*)d_in[3];
    const float* Wk = (const float*)d_in[4];
    const float* bk = (const float*)d_in[5];
    const float* Wv = (const float*)d_in[6];
    const float* bv = (const float*)d_in[7];
    const float* Wo = (const float*)d_in[8];
    const float* bo = (const float*)d_in[9];
    float* out = (float*)d_out;

    __nv_bfloat16 *qh, *ql, *kh, *kl, *vh, *vl;
    float *a, *mf;
    cudaGetSymbolAddress((void**)&qh, g_qh);
    cudaGetSymbolAddress((void**)&ql, g_ql);
    cudaGetSymbolAddress((void**)&kh, g_kh);
    cudaGetSymbolAddress((void**)&kl, g_kl);
    cudaGetSymbolAddress((void**)&vh, g_vh);
    cudaGetSymbolAddress((void**)&vl, g_vl);
    cudaGetSymbolAddress((void**)&a,  g_a);
    cudaGetSymbolAddress((void**)&mf, g_maskf);

    cudaFuncSetAttribute(gemm_mma_kernel<0>,
                         cudaFuncAttributeMaxDynamicSharedMemorySize, 65536);
    cudaFuncSetAttribute(gemm_mma_kernel<1>,
                         cudaFuncAttributeMaxDynamicSharedMemorySize, 65536);
    cudaFuncSetAttribute(flash_mma_kernel,
                         cudaFuncAttributeMaxDynamicSharedMemorySize, 65536 + 256);

    mask_to_f_kernel<<<(NB * TT + 255) / 256, 256>>>(mask, mf, NB * TT);

    dim3 ggrid(MROWS / 128, DM / 128);
    gemm_mma_kernel<1><<<ggrid, 256, 65536>>>(x, Wq, bq, nullptr, qh, ql);
    gemm_mma_kernel<1><<<ggrid, 256, 65536>>>(x, Wk, bk, nullptr, kh, kl);
    gemm_mma_kernel<1><<<ggrid, 256, 65536>>>(x, Wv, bv, nullptr, vh, vl);

    dim3 agrid(TT / 128, NH, NB);
    flash_mma_kernel<<<agrid, 256, 65536 + 256>>>(qh, ql, kh, kl, vh, vl, mf, a);

    gemm_mma_kernel<0><<<ggrid, 256, 65536>>>(a, Wo, bo, out, nullptr, nullptr);
}

// round 8
// speedup vs baseline: 3.2235x; 1.0553x over previous
#include <cuda_runtime.h>
#include <cuda_bf16.h>
#include <cstdint>

#define NB 2
#define TT 4096
#define DM 768
#define NH 12
#define DH 64
#define MROWS (NB * TT)   // 8192

typedef uint32_t u32;
typedef __nv_bfloat16 bf16;
typedef __nv_bfloat162 bf162;

// ---------------------------------------------------------------------------
// Scratch in __device__ globals (allocation-free rule)
// ---------------------------------------------------------------------------
__device__ bf16 g_xh[(size_t)MROWS * DM];
__device__ bf16 g_xl[(size_t)MROWS * DM];
__device__ bf16 g_wqh[(size_t)DM * DM];
__device__ bf16 g_wql[(size_t)DM * DM];
__device__ bf16 g_wkh[(size_t)DM * DM];
__device__ bf16 g_wkl[(size_t)DM * DM];
__device__ bf16 g_wvh[(size_t)DM * DM];
__device__ bf16 g_wvl[(size_t)DM * DM];
__device__ bf16 g_woh[(size_t)DM * DM];
__device__ bf16 g_wol[(size_t)DM * DM];
__device__ bf16 g_qh[(size_t)MROWS * DM];
__device__ bf16 g_ql[(size_t)MROWS * DM];
__device__ bf16 g_kh[(size_t)MROWS * DM];
__device__ bf16 g_kl[(size_t)MROWS * DM];
__device__ bf16 g_vh[(size_t)MROWS * DM];
__device__ bf16 g_vl[(size_t)MROWS * DM];
__device__ bf16 g_ah[(size_t)MROWS * DM];
__device__ bf16 g_al[(size_t)MROWS * DM];
__device__ float g_maskf[(size_t)NB * TT];

// ---------------------------------------------------------------------------
// Helpers
// ---------------------------------------------------------------------------
__device__ __forceinline__ u32 s2u(const void* p) {
    return (u32)__cvta_generic_to_shared(p);
}
__device__ __forceinline__ void cpa16(u32 dst, const void* src) {
    asm volatile("cp.async.ca.shared.global [%0], [%1], 16;" :: "r"(dst), "l"(src));
}
#define CP_COMMIT()  asm volatile("cp.async.commit_group;")
#define CP_WAIT(N)   asm volatile("cp.async.wait_group %0;" :: "n"(N))

__device__ __forceinline__ void ldsm4(u32& r0, u32& r1, u32& r2, u32& r3, u32 a) {
    asm volatile("ldmatrix.sync.aligned.m8n8.x4.shared.b16 {%0,%1,%2,%3},[%4];"
                 : "=r"(r0), "=r"(r1), "=r"(r2), "=r"(r3) : "r"(a));
}
__device__ __forceinline__ void ldsm4t(u32& r0, u32& r1, u32& r2, u32& r3, u32 a) {
    asm volatile("ldmatrix.sync.aligned.m8n8.x4.trans.shared.b16 {%0,%1,%2,%3},[%4];"
                 : "=r"(r0), "=r"(r1), "=r"(r2), "=r"(r3) : "r"(a));
}
__device__ __forceinline__ void mma16816(float* c, u32 a0, u32 a1, u32 a2, u32 a3,
                                         u32 b0, u32 b1) {
    asm volatile(
        "mma.sync.aligned.m16n8k16.row.col.f32.bf16.bf16.f32 "
        "{%0,%1,%2,%3},{%4,%5,%6,%7},{%8,%9},{%0,%1,%2,%3};"
        : "+f"(c[0]), "+f"(c[1]), "+f"(c[2]), "+f"(c[3])
        : "r"(a0), "r"(a1), "r"(a2), "r"(a3), "r"(b0), "r"(b1));
}
__device__ __forceinline__ u32 pkbf(float lo, float hi) {
    bf162 t = __floats2bfloat162_rn(lo, hi);
    return *reinterpret_cast<u32*>(&t);
}
// Swizzled byte offset in a tile with 128B rows (8x 16B chunks per row)
__device__ __forceinline__ u32 swz(int row, int chunk) {
    return (u32)(row * 128 + ((chunk ^ (row & 7)) << 4));
}
__device__ __forceinline__ u32 frag_addr(u32 base, int r0, int c0, int lane) {
    return base + swz(r0 + (lane & 15), c0 + (lane >> 4));
}

// ---------------------------------------------------------------------------
// Mask (bool serialized as int32) -> additive float bias (0 or -1e30)
// ---------------------------------------------------------------------------
__global__ void mask_to_f_kernel(const int* __restrict__ mask,
                                 float* __restrict__ out, int n) {
    int i = blockIdx.x * blockDim.x + threadIdx.x;
    if (i < n) out[i] = mask[i] ? -1e30f : 0.0f;
}

// ---------------------------------------------------------------------------
// fp32 -> bf16 hi/lo split (one pass)
// ---------------------------------------------------------------------------
__global__ void split_kernel(const float* __restrict__ in, bf16* __restrict__ h,
                             bf16* __restrict__ l, int n4) {
    int i = blockIdx.x * blockDim.x + threadIdx.x;
    if (i >= n4) return;
    float4 v = reinterpret_cast<const float4*>(in)[i];
    bf162 h01 = __floats2bfloat162_rn(v.x, v.y);
    bf162 h23 = __floats2bfloat162_rn(v.z, v.w);
    float2 f01 = __bfloat1622float2(h01);
    float2 f23 = __bfloat1622float2(h23);
    bf162 l01 = __floats2bfloat162_rn(v.x - f01.x, v.y - f01.y);
    bf162 l23 = __floats2bfloat162_rn(v.z - f23.x, v.w - f23.y);
    reinterpret_cast<uint2*>(h)[i] = make_uint2(*(u32*)&h01, *(u32*)&h23);
    reinterpret_cast<uint2*>(l)[i] = make_uint2(*(u32*)&l01, *(u32*)&l23);
}

// ---------------------------------------------------------------------------
// C = A @ B^T + bias via mma.sync bf16x3, pre-split bf16 inputs, cp.async
// double-buffered. 128x128 tile, BK=32, 256 threads (8 warps: 2m x 4n).
// smem per stage: A 16KB + B 16KB (row = [32 hi | 32 lo] bf16 = 128B, SW128).
// MODE 0: fp32 C [M,768].  MODE 1: split bf16 hi/lo head-split [n,h,t,dh].
// ---------------------------------------------------------------------------
template <int MODE>
__global__ __launch_bounds__(256, 2)
void gemm_mma_kernel(const bf16* __restrict__ Ah, const bf16* __restrict__ Al,
                     const bf16* __restrict__ Bh, const bf16* __restrict__ Bl,
                     const float* __restrict__ bias, float* __restrict__ C,
                     bf16* __restrict__ Ch, bf16* __restrict__ Cl) {
    extern __shared__ char smraw[];
    const int tid = threadIdx.x, lane = tid & 31, wid = tid >> 5;
    const int wm = wid >> 2, wn = wid & 3;
    const int row0 = blockIdx.x * 128, col0 = blockIdx.y * 128;

    float acc[4][4][4];
#pragma unroll
    for (int a = 0; a < 4; a++)
#pragma unroll
        for (int b = 0; b < 4; b++)
#pragma unroll
            for (int c = 0; c < 4; c++) acc[a][b][c] = 0.0f;

    auto load_stage = [&](int s) {
        char* base = smraw + (s & 1) * 32768;
        u32 ab = s2u(base), bb = ab + 16384;
        int k0 = s * 32;
#pragma unroll
        for (int i = tid; i < 1024; i += 256) {
            int r = i >> 3, c = i & 7;
            const bf16* asrc = (c < 4)
                ? &Ah[(size_t)(row0 + r) * DM + k0 + c * 8]
                : &Al[(size_t)(row0 + r) * DM + k0 + (c - 4) * 8];
            cpa16(ab + swz(r, c), asrc);
            const bf16* bsrc = (c < 4)
                ? &Bh[(size_t)(col0 + r) * DM + k0 + c * 8]
                : &Bl[(size_t)(col0 + r) * DM + k0 + (c - 4) * 8];
            cpa16(bb + swz(r, c), bsrc);
        }
    };

    load_stage(0);
    CP_COMMIT();

    const int NS = DM / 32;  // 24
#pragma unroll 1
    for (int s = 0; s < NS; s++) {
        if (s + 1 < NS) {
            load_stage(s + 1);
            CP_COMMIT();
            CP_WAIT(1);
        } else {
            CP_WAIT(0);
        }
        __syncthreads();

        u32 ab = s2u(smraw + (s & 1) * 32768), bb = ab + 16384;
#pragma unroll
        for (int kt = 0; kt < 2; kt++) {
            const int ch = 2 * kt, cl = 4 + 2 * kt;
            u32 bhf[4][2], blf[4][2];
#pragma unroll
            for (int half = 0; half < 2; half++) {
                u32 r0, r1, r2, r3;
                ldsm4(r0, r1, r2, r3, frag_addr(bb, wn * 32 + half * 16, ch, lane));
                bhf[2 * half][0] = r0; bhf[2 * half + 1][0] = r1;
                bhf[2 * half][1] = r2; bhf[2 * half + 1][1] = r3;
                ldsm4(r0, r1, r2, r3, frag_addr(bb, wn * 32 + half * 16, cl, lane));
                blf[2 * half][0] = r0; blf[2 * half + 1][0] = r1;
                blf[2 * half][1] = r2; blf[2 * half + 1][1] = r3;
            }
#pragma unroll
            for (int mt = 0; mt < 4; mt++) {
                u32 ah4[4], al4[4];
                ldsm4(ah4[0], ah4[1], ah4[2], ah4[3],
                      frag_addr(ab, wm * 64 + mt * 16, ch, lane));
                ldsm4(al4[0], al4[1], al4[2], al4[3],
                      frag_addr(ab, wm * 64 + mt * 16, cl, lane));
#pragma unroll
                for (int nt = 0; nt < 4; nt++) {
                    mma16816(acc[mt][nt], ah4[0], ah4[1], ah4[2], ah4[3],
                             bhf[nt][0], bhf[nt][1]);
                    mma16816(acc[mt][nt], ah4[0], ah4[1], ah4[2], ah4[3],
                             blf[nt][0], blf[nt][1]);
                    mma16816(acc[mt][nt], al4[0], al4[1], al4[2], al4[3],
                             bhf[nt][0], bhf[nt][1]);
                }
            }
        }
        __syncthreads();
    }

    // Epilogue
    const int g = lane >> 2, t4 = lane & 3;
#pragma unroll
    for (int mt = 0; mt < 4; mt++)
#pragma unroll
        for (int nt = 0; nt < 4; nt++) {
            int col = col0 + wn * 32 + nt * 8 + t4 * 2;
            float bv0 = bias[col], bv1 = bias[col + 1];
#pragma unroll
            for (int half = 0; half < 2; half++) {
                int row = row0 + wm * 64 + mt * 16 + g + half * 8;
                float c0 = acc[mt][nt][2 * half] + bv0;
                float c1 = acc[mt][nt][2 * half + 1] + bv1;
                if (MODE == 0) {
                    *reinterpret_cast<float2*>(&C[(size_t)row * DM + col]) =
                        make_float2(c0, c1);
                } else {
                    int n = row >> 12, t = row & (TT - 1);
                    int h = col >> 6, d = col & 63;
                    size_t idx = (((size_t)(n * NH + h)) * TT + t) * DH + d;
                    bf162 hi = __floats2bfloat162_rn(c0, c1);
                    float2 hf = __bfloat1622float2(hi);
                    bf162 lo = __floats2bfloat162_rn(c0 - hf.x, c1 - hf.y);
                    *reinterpret_cast<bf162*>(&Ch[idx]) = hi;
                    *reinterpret_cast<bf162*>(&Cl[idx]) = lo;
                }
            }
        }
}

// ---------------------------------------------------------------------------
// Flash attention via mma.sync bf16x3, cp.async double-buffered K/V tiles.
// CTA = 128 queries of one (n,h), 8 warps (16 q rows each), 64-key tiles.
// smem: Qh/Ql 32KB | 2 KV stages (Kh,Kl,Vh,Vl 8KB each) 64KB | act flags.
// Output written pre-split (bf16 hi/lo) for the final projection.
// ---------------------------------------------------------------------------
__global__ __launch_bounds__(256, 2)
void flash_mma_kernel(const bf16* __restrict__ Qhg, const bf16* __restrict__ Qlg,
                      const bf16* __restrict__ Khg, const bf16* __restrict__ Klg,
                      const bf16* __restrict__ Vhg, const bf16* __restrict__ Vlg,
                      const float* __restrict__ mbf,
                      bf16* __restrict__ Aho, bf16* __restrict__ Alo) {
    extern __shared__ char smraw[];
    int* act = reinterpret_cast<int*>(smraw + 98304);   // [64]
    int* sna = reinterpret_cast<int*>(smraw + 98304 + 256);
    const u32 QhB = s2u(smraw), QlB = QhB + 16384;

    const int n = blockIdx.z, h = blockIdx.y;
    const int q0 = blockIdx.x * 128;
    const size_t hb = ((size_t)(n * NH + h)) * TT * DH;
    const float* mb = mbf + (size_t)n * TT;

    const int tid = threadIdx.x, lane = tid & 31, wid = tid >> 5;
    const int g = lane >> 2, t4 = lane & 3;

    // Stage Q hi/lo via cp.async (group 0)
#pragma unroll
    for (int i = tid; i < 2048; i += 256) {
        int arr = i >> 10, r = (i >> 3) & 127, c = i & 7;
        const bf16* src = (arr ? Qlg : Qhg) + hb + (size_t)(q0 + r) * DH + c * 8;
        cpa16(QhB + arr * 16384 + swz(r, c), src);
    }
    CP_COMMIT();

    // Active-tile table (skip fully-masked key tiles; required numerically)
    if (tid < 64) {
        bool any = false;
        for (int j = 0; j < 64; j++) any |= (mb[tid * 64 + j] == 0.0f);
        act[tid] = any ? 1 : 0;
    }
    __syncthreads();
    if (tid == 0) {
        int na = 0;
        for (int j = 0; j < 64; j++)
            if (act[j]) na = j + 1;
        *sna = na;
    }
    __syncthreads();
    const int na = *sna;

    auto load_kv = [&](int kb) {
        u32 base = s2u(smraw + 32768 + (kb & 1) * 32768);
        int c0 = kb * 64;
#pragma unroll
        for (int i = tid; i < 2048; i += 256) {
            int arr = i >> 9, r = (i >> 3) & 63, c = i & 7;
            const bf16* gsrc = (arr == 0) ? Khg : (arr == 1) ? Klg
                             : (arr == 2) ? Vhg : Vlg;
            cpa16(base + arr * 8192 + swz(r, c),
                  gsrc + hb + (size_t)(c0 + r) * DH + c * 8);
        }
    };

    float oacc[8][4];
#pragma unroll
    for (int a = 0; a < 8; a++)
#pragma unroll
        for (int b = 0; b < 4; b++) oacc[a][b] = 0.0f;
    float mrow0 = -1e30f, mrow1 = -1e30f, lrow0 = 0.0f, lrow1 = 0.0f;

    if (na > 0) {
        load_kv(0);
        CP_COMMIT();
    }

#pragma unroll 1
    for (int kb = 0; kb < na; kb++) {
        if (kb + 1 < na) {
            load_kv(kb + 1);
            CP_COMMIT();
            CP_WAIT(1);
        } else {
            CP_WAIT(0);
        }
        __syncthreads();

        if (act[kb]) {
            const int c0 = kb * 64;
            u32 KhB = s2u(smraw + 32768 + (kb & 1) * 32768);
            u32 KlB = KhB + 8192, VhB = KhB + 16384, VlB = KhB + 24576;

            // ---- S = Q K^T ----
            float sacc[8][4];
#pragma unroll
            for (int a = 0; a < 8; a++)
#pragma unroll
                for (int b = 0; b < 4; b++) sacc[a][b] = 0.0f;

#pragma unroll
            for (int kt = 0; kt < 4; kt++) {
                u32 qh[4], ql[4];
                ldsm4(qh[0], qh[1], qh[2], qh[3],
                      frag_addr(QhB, wid * 16, kt * 2, lane));
                ldsm4(ql[0], ql[1], ql[2], ql[3],
                      frag_addr(QlB, wid * 16, kt * 2, lane));
#pragma unroll
                for (int hf = 0; hf < 4; hf++) {
                    u32 k0r, k1r, k2r, k3r, l0r, l1r, l2r, l3r;
                    ldsm4(k0r, k1r, k2r, k3r,
                          frag_addr(KhB, hf * 16, kt * 2, lane));
                    ldsm4(l0r, l1r, l2r, l3r,
                          frag_addr(KlB, hf * 16, kt * 2, lane));
                    mma16816(sacc[2 * hf],     qh[0], qh[1], qh[2], qh[3], k0r, k2r);
                    mma16816(sacc[2 * hf],     qh[0], qh[1], qh[2], qh[3], l0r, l2r);
                    mma16816(sacc[2 * hf],     ql[0], ql[1], ql[2], ql[3], k0r, k2r);
                    mma16816(sacc[2 * hf + 1], qh[0], qh[1], qh[2], qh[3], k1r, k3r);
                    mma16816(sacc[2 * hf + 1], qh[0], qh[1], qh[2], qh[3], l1r, l3r);
                    mma16816(sacc[2 * hf + 1], ql[0], ql[1], ql[2], ql[3], k1r, k3r);
                }
            }

            // ---- scale + mask ----
#pragma unroll
            for (int nt = 0; nt < 8; nt++) {
                float2 mk = *reinterpret_cast<const float2*>(
                    &mb[c0 + nt * 8 + t4 * 2]);
                sacc[nt][0] = sacc[nt][0] * 0.125f + mk.x;
                sacc[nt][1] = sacc[nt][1] * 0.125f + mk.y;
                sacc[nt][2] = sacc[nt][2] * 0.125f + mk.x;
                sacc[nt][3] = sacc[nt][3] * 0.125f + mk.y;
            }

            // ---- online softmax ----
            float rmax0 = -1e30f, rmax1 = -1e30f;
#pragma unroll
            for (int nt = 0; nt < 8; nt++) {
                rmax0 = fmaxf(rmax0, fmaxf(sacc[nt][0], sacc[nt][1]));
                rmax1 = fmaxf(rmax1, fmaxf(sacc[nt][2], sacc[nt][3]));
            }
            rmax0 = fmaxf(rmax0, __shfl_xor_sync(0xffffffffu, rmax0, 1));
            rmax0 = fmaxf(rmax0, __shfl_xor_sync(0xffffffffu, rmax0, 2));
            rmax1 = fmaxf(rmax1, __shfl_xor_sync(0xffffffffu, rmax1, 1));
            rmax1 = fmaxf(rmax1, __shfl_xor_sync(0xffffffffu, rmax1, 2));
            float mn0 = fmaxf(mrow0, rmax0), mn1 = fmaxf(mrow1, rmax1);
            float corr0 = __expf(mrow0 - mn0), corr1 = __expf(mrow1 - mn1);
            mrow0 = mn0; mrow1 = mn1;
            float rs0 = 0.0f, rs1 = 0.0f;
#pragma unroll
            for (int nt = 0; nt < 8; nt++) {
                sacc[nt][0] = __expf(sacc[nt][0] - mn0);
                sacc[nt][1] = __expf(sacc[nt][1] - mn0);
                sacc[nt][2] = __expf(sacc[nt][2] - mn1);
                sacc[nt][3] = __expf(sacc[nt][3] - mn1);
                rs0 += sacc[nt][0] + sacc[nt][1];
                rs1 += sacc[nt][2] + sacc[nt][3];
            }
            rs0 += __shfl_xor_sync(0xffffffffu, rs0, 1);
            rs0 += __shfl_xor_sync(0xffffffffu, rs0, 2);
            rs1 += __shfl_xor_sync(0xffffffffu, rs1, 1);
            rs1 += __shfl_xor_sync(0xffffffffu, rs1, 2);
            lrow0 = lrow0 * corr0 + rs0;
            lrow1 = lrow1 * corr1 + rs1;
#pragma unroll
            for (int dt = 0; dt < 8; dt++) {
                oacc[dt][0] *= corr0; oacc[dt][1] *= corr0;
                oacc[dt][2] *= corr1; oacc[dt][3] *= corr1;
            }

            // ---- O += P V ----
#pragma unroll
            for (int j = 0; j < 4; j++) {
                u32 pa_h[4], pa_l[4];
                {
                    bf162 h0 = __floats2bfloat162_rn(sacc[2 * j][0], sacc[2 * j][1]);
                    bf162 h1 = __floats2bfloat162_rn(sacc[2 * j][2], sacc[2 * j][3]);
                    bf162 h2 = __floats2bfloat162_rn(sacc[2 * j + 1][0], sacc[2 * j + 1][1]);
                    bf162 h3 = __floats2bfloat162_rn(sacc[2 * j + 1][2], sacc[2 * j + 1][3]);
                    float2 f0 = __bfloat1622float2(h0), f1 = __bfloat1622float2(h1);
                    float2 f2 = __bfloat1622float2(h2), f3 = __bfloat1622float2(h3);
                    pa_h[0] = *(u32*)&h0; pa_h[1] = *(u32*)&h1;
                    pa_h[2] = *(u32*)&h2; pa_h[3] = *(u32*)&h3;
                    pa_l[0] = pkbf(sacc[2 * j][0] - f0.x, sacc[2 * j][1] - f0.y);
                    pa_l[1] = pkbf(sacc[2 * j][2] - f1.x, sacc[2 * j][3] - f1.y);
                    pa_l[2] = pkbf(sacc[2 * j + 1][0] - f2.x, sacc[2 * j + 1][1] - f2.y);
                    pa_l[3] = pkbf(sacc[2 * j + 1][2] - f3.x, sacc[2 * j + 1][3] - f3.y);
                }
#pragma unroll
                for (int c = 0; c < 4; c++) {
                    u32 v0, v1, v2, v3, w0, w1, w2, w3;
                    ldsm4t(v0, v1, v2, v3, frag_addr(VhB, j * 16, c * 2, lane));
                    ldsm4t(w0, w1, w2, w3, frag_addr(VlB, j * 16, c * 2, lane));
                    mma16816(oacc[2 * c],     pa_h[0], pa_h[1], pa_h[2], pa_h[3], v0, v1);
                    mma16816(oacc[2 * c],     pa_h[0], pa_h[1], pa_h[2], pa_h[3], w0, w1);
                    mma16816(oacc[2 * c],     pa_l[0], pa_l[1], pa_l[2], pa_l[3], v0, v1);
                    mma16816(oacc[2 * c + 1], pa_h[0], pa_h[1], pa_h[2], pa_h[3], v2, v3);
                    mma16816(oacc[2 * c + 1], pa_h[0], pa_h[1], pa_h[2], pa_h[3], w2, w3);
                    mma16816(oacc[2 * c + 1], pa_l[0], pa_l[1], pa_l[2], pa_l[3], v2, v3);
                }
            }
        }
        __syncthreads();
    }

    // ---- normalize + split-write [n, t, h*64 + d] as bf16 hi/lo ----
    float inv0 = 1.0f / lrow0, inv1 = 1.0f / lrow1;
#pragma unroll
    for (int dt = 0; dt < 8; dt++) {
        int col = h * DH + dt * 8 + t4 * 2;
        size_t r1 = (size_t)n * TT + q0 + wid * 16 + g;
        float a0 = oacc[dt][0] * inv0, a1 = oacc[dt][1] * inv0;
        float b0 = oacc[dt][2] * inv1, b1 = oacc[dt][3] * inv1;
        bf162 ha = __floats2bfloat162_rn(a0, a1);
        float2 fa = __bfloat1622float2(ha);
        bf162 la = __floats2bfloat162_rn(a0 - fa.x, a1 - fa.y);
        bf162 hbv = __floats2bfloat162_rn(b0, b1);
        float2 fb = __bfloat1622float2(hbv);
        bf162 lb = __floats2bfloat162_rn(b0 - fb.x, b1 - fb.y);
        *reinterpret_cast<bf162*>(&Aho[r1 * DM + col]) = ha;
        *reinterpret_cast<bf162*>(&Alo[r1 * DM + col]) = la;
        *reinterpret_cast<bf162*>(&Aho[(r1 + 8) * DM + col]) = hbv;
        *reinterpret_cast<bf162*>(&Alo[(r1 + 8) * DM + col]) = lb;
    }
}

// ---------------------------------------------------------------------------
// Launch
// ---------------------------------------------------------------------------
extern "C" void kernel_launch(void* const* d_in, const int* in_sizes, int n_in,
                              void* d_out, int out_size) {
    const float* x  = (const float*)d_in[0];
    const int*   mask = (const int*)d_in[1];
    const float* Wq = (const float*)d_in[2];
    const float* bq = (const float*)d_in[3];
    const float* Wk = (const float*)d_in[4];
    const float* bk = (const float*)d_in[5];
    const float* Wv = (const float*)d_in[6];
    const float* bv = (const float*)d_in[7];
    const float* Wo = (const float*)d_in[8];
    const float* bo = (const float*)d_in[9];
    float* out = (float*)d_out;

    bf16 *xh, *xl, *wqh, *wql, *wkh, *wkl, *wvh, *wvl, *woh, *wol;
    bf16 *qh, *ql, *kh, *kl, *vh, *vl, *ah, *al;
    float *mf;
    cudaGetSymbolAddress((void**)&xh, g_xh);
    cudaGetSymbolAddress((void**)&xl, g_xl);
    cudaGetSymbolAddress((void**)&wqh, g_wqh);
    cudaGetSymbolAddress((void**)&wql, g_wql);
    cudaGetSymbolAddress((void**)&wkh, g_wkh);
    cudaGetSymbolAddress((void**)&wkl, g_wkl);
    cudaGetSymbolAddress((void**)&wvh, g_wvh);
    cudaGetSymbolAddress((void**)&wvl, g_wvl);
    cudaGetSymbolAddress((void**)&woh, g_woh);
    cudaGetSymbolAddress((void**)&wol, g_wol);
    cudaGetSymbolAddress((void**)&qh, g_qh);
    cudaGetSymbolAddress((void**)&ql, g_ql);
    cudaGetSymbolAddress((void**)&kh, g_kh);
    cudaGetSymbolAddress((void**)&kl, g_kl);
    cudaGetSymbolAddress((void**)&vh, g_vh);
    cudaGetSymbolAddress((void**)&vl, g_vl);
    cudaGetSymbolAddress((void**)&ah, g_ah);
    cudaGetSymbolAddress((void**)&al, g_al);
    cudaGetSymbolAddress((void**)&mf, g_maskf);

    cudaFuncSetAttribute(gemm_mma_kernel<0>,
                         cudaFuncAttributeMaxDynamicSharedMemorySize, 65536);
    cudaFuncSetAttribute(gemm_mma_kernel<1>,
                         cudaFuncAttributeMaxDynamicSharedMemorySize, 65536);
    cudaFuncSetAttribute(flash_mma_kernel,
                         cudaFuncAttributeMaxDynamicSharedMemorySize, 98816);

    mask_to_f_kernel<<<(NB * TT + 255) / 256, 256>>>(mask, mf, NB * TT);

    const int xn4 = MROWS * DM / 4;      // 1,572,864
    const int wn4 = DM * DM / 4;         // 147,456
    split_kernel<<<(xn4 + 255) / 256, 256>>>(x, xh, xl, xn4);
    split_kernel<<<(wn4 + 255) / 256, 256>>>(Wq, wqh, wql, wn4);
    split_kernel<<<(wn4 + 255) / 256, 256>>>(Wk, wkh, wkl, wn4);
    split_kernel<<<(wn4 + 255) / 256, 256>>>(Wv, wvh, wvl, wn4);
    split_kernel<<<(wn4 + 255) / 256, 256>>>(Wo, woh, wol, wn4);

    dim3 ggrid(MROWS / 128, DM / 128);
    gemm_mma_kernel<1><<<ggrid, 256, 65536>>>(xh, xl, wqh, wql, bq, nullptr, qh, ql);
    gemm_mma_kernel<1><<<ggrid, 256, 65536>>>(xh, xl, wkh, wkl, bk, nullptr, kh, kl);
    gemm_mma_kernel<1><<<ggrid, 256, 65536>>>(xh, xl, wvh, wvl, bv, nullptr, vh, vl);

    dim3 agrid(TT / 128, NH, NB);
    flash_mma_kernel<<<agrid, 256, 98816>>>(qh, ql, kh, kl, vh, vl, mf, ah, al);

    gemm_mma_kernel<0><<<ggrid, 256, 65536>>>(ah, al, woh, wol, bo, out, nullptr, nullptr);
}

// round 10
// speedup vs baseline: 3.3213x; 1.0303x over previous
#include <cuda_runtime.h>
#include <cuda_bf16.h>
#include <cstdint>

#define NB 2
#define TT 4096
#define DM 768
#define NH 12
#define DH 64
#define MROWS (NB * TT)   // 8192

typedef uint32_t u32;
typedef __nv_bfloat16 bf16;
typedef __nv_bfloat162 bf162;

#define LOG2E 1.4426950408889634f
#define QSCALE 0.18033688011112042f   // 0.125 * log2(e)

// ---------------------------------------------------------------------------
// Scratch in __device__ globals (allocation-free rule)
// ---------------------------------------------------------------------------
__device__ bf16 g_xh[(size_t)MROWS * DM];
__device__ bf16 g_xl[(size_t)MROWS * DM];
__device__ bf16 g_wqh[(size_t)DM * DM];
__device__ bf16 g_wql[(size_t)DM * DM];
__device__ bf16 g_wkh[(size_t)DM * DM];
__device__ bf16 g_wkl[(size_t)DM * DM];
__device__ bf16 g_wvh[(size_t)DM * DM];
__device__ bf16 g_wvl[(size_t)DM * DM];
__device__ bf16 g_woh[(size_t)DM * DM];
__device__ bf16 g_wol[(size_t)DM * DM];
__device__ bf16 g_qh[(size_t)MROWS * DM];
__device__ bf16 g_ql[(size_t)MROWS * DM];
__device__ bf16 g_kh[(size_t)MROWS * DM];
__device__ bf16 g_kl[(size_t)MROWS * DM];
__device__ bf16 g_vh[(size_t)MROWS * DM];
__device__ bf16 g_vl[(size_t)MROWS * DM];
__device__ bf16 g_ah[(size_t)MROWS * DM];
__device__ bf16 g_al[(size_t)MROWS * DM];
__device__ float g_maskf[(size_t)NB * TT];   // t-domain: 0 or -1e30*log2e
__device__ int   g_act[NB * 64];             // 0=skip, 1=partial, 2=full
__device__ int   g_na[NB];                   // last active tile + 1

// ---------------------------------------------------------------------------
// Helpers
// ---------------------------------------------------------------------------
__device__ __forceinline__ u32 s2u(const void* p) {
    return (u32)__cvta_generic_to_shared(p);
}
__device__ __forceinline__ void cpa16(u32 dst, const void* src) {
    asm volatile("cp.async.ca.shared.global [%0], [%1], 16;" :: "r"(dst), "l"(src));
}
#define CP_COMMIT()  asm volatile("cp.async.commit_group;")
#define CP_WAIT(N)   asm volatile("cp.async.wait_group %0;" :: "n"(N))

__device__ __forceinline__ void ldsm4(u32& r0, u32& r1, u32& r2, u32& r3, u32 a) {
    asm volatile("ldmatrix.sync.aligned.m8n8.x4.shared.b16 {%0,%1,%2,%3},[%4];"
                 : "=r"(r0), "=r"(r1), "=r"(r2), "=r"(r3) : "r"(a));
}
__device__ __forceinline__ void ldsm4t(u32& r0, u32& r1, u32& r2, u32& r3, u32 a) {
    asm volatile("ldmatrix.sync.aligned.m8n8.x4.trans.shared.b16 {%0,%1,%2,%3},[%4];"
                 : "=r"(r0), "=r"(r1), "=r"(r2), "=r"(r3) : "r"(a));
}
__device__ __forceinline__ void mma16816(float* c, u32 a0, u32 a1, u32 a2, u32 a3,
                                         u32 b0, u32 b1) {
    asm volatile(
        "mma.sync.aligned.m16n8k16.row.col.f32.bf16.bf16.f32 "
        "{%0,%1,%2,%3},{%4,%5,%6,%7},{%8,%9},{%0,%1,%2,%3};"
        : "+f"(c[0]), "+f"(c[1]), "+f"(c[2]), "+f"(c[3])
        : "r"(a0), "r"(a1), "r"(a2), "r"(a3), "r"(b0), "r"(b1));
}
__device__ __forceinline__ u32 pkbf(float lo, float hi) {
    bf162 t = __floats2bfloat162_rn(lo, hi);
    return *reinterpret_cast<u32*>(&t);
}
__device__ __forceinline__ float ex2(float x) {
    float y;
    asm("ex2.approx.ftz.f32 %0, %1;" : "=f"(y) : "f"(x));
    return y;
}
// Swizzled byte offset in a tile with 128B rows (8x 16B chunks per row)
__device__ __forceinline__ u32 swz(int row, int chunk) {
    return (u32)(row * 128 + ((chunk ^ (row & 7)) << 4));
}
__device__ __forceinline__ u32 frag_addr(u32 base, int r0, int c0, int lane) {
    return base + swz(r0 + (lane & 15), c0 + (lane >> 4));
}

// ---------------------------------------------------------------------------
// Mask prep: int32 bool -> t-domain additive bias, per-tile activity flags.
// One block per batch, 64 threads (one per 64-key tile).
// ---------------------------------------------------------------------------
__global__ void prep_mask_kernel(const int* __restrict__ mask,
                                 float* __restrict__ out,
                                 int* __restrict__ actg, int* __restrict__ nag) {
    __shared__ int s_any[64];
    const int n = blockIdx.x, t = threadIdx.x;
    bool any = false, all = true;
#pragma unroll 8
    for (int j = 0; j < 64; j++) {
        int m = mask[n * TT + t * 64 + j];
        out[n * TT + t * 64 + j] = m ? -1.4426950e30f : 0.0f;
        any |= (m == 0);
        all &= (m == 0);
    }
    actg[n * 64 + t] = any ? (all ? 2 : 1) : 0;
    s_any[t] = any ? 1 : 0;
    __syncthreads();
    if (t == 0) {
        int na = 0;
        for (int j = 0; j < 64; j++)
            if (s_any[j]) na = j + 1;
        nag[n] = na;
    }
}

// ---------------------------------------------------------------------------
// fp32 -> bf16 hi/lo split (x)
// ---------------------------------------------------------------------------
__device__ __forceinline__ void split4(float4 v, uint2& h, uint2& l) {
    bf162 h01 = __floats2bfloat162_rn(v.x, v.y);
    bf162 h23 = __floats2bfloat162_rn(v.z, v.w);
    float2 f01 = __bfloat1622float2(h01);
    float2 f23 = __bfloat1622float2(h23);
    bf162 l01 = __floats2bfloat162_rn(v.x - f01.x, v.y - f01.y);
    bf162 l23 = __floats2bfloat162_rn(v.z - f23.x, v.w - f23.y);
    h = make_uint2(*(u32*)&h01, *(u32*)&h23);
    l = make_uint2(*(u32*)&l01, *(u32*)&l23);
}

__global__ void split_kernel(const float* __restrict__ in, bf16* __restrict__ h,
                             bf16* __restrict__ l, int n4) {
    int i = blockIdx.x * blockDim.x + threadIdx.x;
    if (i >= n4) return;
    uint2 hh, ll;
    split4(reinterpret_cast<const float4*>(in)[i], hh, ll);
    reinterpret_cast<uint2*>(h)[i] = hh;
    reinterpret_cast<uint2*>(l)[i] = ll;
}

// All four weights in one launch
__global__ void split4w_kernel(const float* __restrict__ W0, const float* __restrict__ W1,
                               const float* __restrict__ W2, const float* __restrict__ W3,
                               bf16* __restrict__ h0, bf16* __restrict__ l0,
                               bf16* __restrict__ h1, bf16* __restrict__ l1,
                               bf16* __restrict__ h2, bf16* __restrict__ l2,
                               bf16* __restrict__ h3, bf16* __restrict__ l3, int n4) {
    int i = blockIdx.x * blockDim.x + threadIdx.x;
    int w = i / n4, j = i - w * n4;
    if (w >= 4) return;
    const float* in = (w == 0) ? W0 : (w == 1) ? W1 : (w == 2) ? W2 : W3;
    bf16* h = (w == 0) ? h0 : (w == 1) ? h1 : (w == 2) ? h2 : h3;
    bf16* l = (w == 0) ? l0 : (w == 1) ? l1 : (w == 2) ? l2 : l3;
    uint2 hh, ll;
    split4(reinterpret_cast<const float4*>(in)[j], hh, ll);
    reinterpret_cast<uint2*>(h)[j] = hh;
    reinterpret_cast<uint2*>(l)[j] = ll;
}

// ---------------------------------------------------------------------------
// C = A @ B^T + bias via mma.sync bf16x3, 3-stage cp.async pipeline.
// 128x128 tile, BK=32, 256 threads (8 warps: 2m x 4n).
// Stage (32KB): A 16K + B 16K, row = [32 hi | 32 lo] bf16 = 128B swizzled.
// MODE 0: fp32 C [M,768].  MODE 1: (acc+bias)*cscale split bf16 head-split.
// ---------------------------------------------------------------------------
template <int MODE>
__global__ __launch_bounds__(256, 2)
void gemm_mma_kernel(const bf16* __restrict__ Ah, const bf16* __restrict__ Al,
                     const bf16* __restrict__ Bh, const bf16* __restrict__ Bl,
                     const float* __restrict__ bias, float cscale,
                     float* __restrict__ C,
                     bf16* __restrict__ Ch, bf16* __restrict__ Cl) {
    extern __shared__ char smraw[];
    const int tid = threadIdx.x, lane = tid & 31, wid = tid >> 5;
    const int wm = wid >> 2, wn = wid & 3;
    const int row0 = blockIdx.x * 128, col0 = blockIdx.y * 128;

    float acc[4][4][4];
#pragma unroll
    for (int a = 0; a < 4; a++)
#pragma unroll
        for (int b = 0; b < 4; b++)
#pragma unroll
            for (int c = 0; c < 4; c++) acc[a][b][c] = 0.0f;

    auto load_stage = [&](int s) {
        char* base = smraw + (s % 3) * 32768;
        u32 ab = s2u(base), bb = ab + 16384;
        int k0 = s * 32;
#pragma unroll
        for (int i = tid; i < 1024; i += 256) {
            int r = i >> 3, c = i & 7;
            const bf16* asrc = (c < 4)
                ? &Ah[(size_t)(row0 + r) * DM + k0 + c * 8]
                : &Al[(size_t)(row0 + r) * DM + k0 + (c - 4) * 8];
            cpa16(ab + swz(r, c), asrc);
            const bf16* bsrc = (c < 4)
                ? &Bh[(size_t)(col0 + r) * DM + k0 + c * 8]
                : &Bl[(size_t)(col0 + r) * DM + k0 + (c - 4) * 8];
            cpa16(bb + swz(r, c), bsrc);
        }
    };

    load_stage(0); CP_COMMIT();
    load_stage(1); CP_COMMIT();

    const int NS = DM / 32;  // 24
#pragma unroll 1
    for (int s = 0; s < NS; s++) {
        if (s + 1 < NS) { CP_WAIT(1); } else { CP_WAIT(0); }
        __syncthreads();

        u32 ab = s2u(smraw + (s % 3) * 32768), bb = ab + 16384;
#pragma unroll
        for (int kt = 0; kt < 2; kt++) {
            const int ch = 2 * kt, cl = 4 + 2 * kt;
            u32 bhf[4][2], blf[4][2];
#pragma unroll
            for (int half = 0; half < 2; half++) {
                u32 r0, r1, r2, r3;
                ldsm4(r0, r1, r2, r3, frag_addr(bb, wn * 32 + half * 16, ch, lane));
                bhf[2 * half][0] = r0; bhf[2 * half + 1][0] = r1;
                bhf[2 * half][1] = r2; bhf[2 * half + 1][1] = r3;
                ldsm4(r0, r1, r2, r3, frag_addr(bb, wn * 32 + half * 16, cl, lane));
                blf[2 * half][0] = r0; blf[2 * half + 1][0] = r1;
                blf[2 * half][1] = r2; blf[2 * half + 1][1] = r3;
            }
#pragma unroll
            for (int mt = 0; mt < 4; mt++) {
                u32 ah4[4], al4[4];
                ldsm4(ah4[0], ah4[1], ah4[2], ah4[3],
                      frag_addr(ab, wm * 64 + mt * 16, ch, lane));
                ldsm4(al4[0], al4[1], al4[2], al4[3],
                      frag_addr(ab, wm * 64 + mt * 16, cl, lane));
#pragma unroll
                for (int nt = 0; nt < 4; nt++) {
                    mma16816(acc[mt][nt], ah4[0], ah4[1], ah4[2], ah4[3],
                             bhf[nt][0], bhf[nt][1]);
                    mma16816(acc[mt][nt], ah4[0], ah4[1], ah4[2], ah4[3],
                             blf[nt][0], blf[nt][1]);
                    mma16816(acc[mt][nt], al4[0], al4[1], al4[2], al4[3],
                             bhf[nt][0], bhf[nt][1]);
                }
            }
        }
        if (s + 2 < NS) { load_stage(s + 2); CP_COMMIT(); }
    }

    // Epilogue
    const int g = lane >> 2, t4 = lane & 3;
#pragma unroll
    for (int mt = 0; mt < 4; mt++)
#pragma unroll
        for (int nt = 0; nt < 4; nt++) {
            int col = col0 + wn * 32 + nt * 8 + t4 * 2;
            float bv0 = bias[col], bv1 = bias[col + 1];
#pragma unroll
            for (int half = 0; half < 2; half++) {
                int row = row0 + wm * 64 + mt * 16 + g + half * 8;
                float c0 = acc[mt][nt][2 * half] + bv0;
                float c1 = acc[mt][nt][2 * half + 1] + bv1;
                if (MODE == 0) {
                    *reinterpret_cast<float2*>(&C[(size_t)row * DM + col]) =
                        make_float2(c0, c1);
                } else {
                    c0 *= cscale; c1 *= cscale;
                    int n = row >> 12, t = row & (TT - 1);
                    int h = col >> 6, d = col & 63;
                    size_t idx = (((size_t)(n * NH + h)) * TT + t) * DH + d;
                    bf162 hi = __floats2bfloat162_rn(c0, c1);
                    float2 hf = __bfloat1622float2(hi);
                    bf162 lo = __floats2bfloat162_rn(c0 - hf.x, c1 - hf.y);
                    *reinterpret_cast<bf162*>(&Ch[idx]) = hi;
                    *reinterpret_cast<bf162*>(&Cl[idx]) = lo;
                }
            }
        }
}

// ---------------------------------------------------------------------------
// Flash attention via mma.sync bf16x3, cp.async double-buffered K/V tiles.
// Q pre-scaled by 0.125*log2e (t-domain scores); mask bias pre-scaled too.
// CTA = 128 queries of one (n,h), 8 warps (16 q rows each), 64-key tiles.
// smem: Qh/Ql 32KB | 2 KV stages (Kh,Kl,Vh,Vl 8KB each) 64KB.
// ---------------------------------------------------------------------------
__global__ __launch_bounds__(256, 2)
void flash_mma_kernel(const bf16* __restrict__ Qhg, const bf16* __restrict__ Qlg,
                      const bf16* __restrict__ Khg, const bf16* __restrict__ Klg,
                      const bf16* __restrict__ Vhg, const bf16* __restrict__ Vlg,
                      const float* __restrict__ mbf,
                      const int* __restrict__ actg, const int* __restrict__ nag,
                      bf16* __restrict__ Aho, bf16* __restrict__ Alo) {
    extern __shared__ char smraw[];
    __shared__ int act_s[64];
    const u32 QhB = s2u(smraw), QlB = QhB + 16384;

    const int n = blockIdx.z, h = blockIdx.y;
    const int q0 = blockIdx.x * 128;
    const size_t hb = ((size_t)(n * NH + h)) * TT * DH;
    const float* mb = mbf + (size_t)n * TT;

    const int tid = threadIdx.x, lane = tid & 31, wid = tid >> 5;
    const int g = lane >> 2, t4 = lane & 3;

    // Stage Q hi/lo via cp.async
#pragma unroll
    for (int i = tid; i < 2048; i += 256) {
        int arr = i >> 10, r = (i >> 3) & 127, c = i & 7;
        const bf16* src = (arr ? Qlg : Qhg) + hb + (size_t)(q0 + r) * DH + c * 8;
        cpa16(QhB + arr * 16384 + swz(r, c), src);
    }
    CP_COMMIT();

    if (tid < 64) act_s[tid] = actg[n * 64 + tid];
    const int na = nag[n];
    __syncthreads();

    auto load_kv = [&](int kb) {
        u32 base = s2u(smraw + 32768 + (kb & 1) * 32768);
        int c0 = kb * 64;
#pragma unroll
        for (int i = tid; i < 2048; i += 256) {
            int arr = i >> 9, r = (i >> 3) & 63, c = i & 7;
            const bf16* gsrc = (arr == 0) ? Khg : (arr == 1) ? Klg
                             : (arr == 2) ? Vhg : Vlg;
            cpa16(base + arr * 8192 + swz(r, c),
                  gsrc + hb + (size_t)(c0 + r) * DH + c * 8);
        }
    };

    float oacc[8][4];
#pragma unroll
    for (int a = 0; a < 8; a++)
#pragma unroll
        for (int b = 0; b < 4; b++) oacc[a][b] = 0.0f;
    float mrow0 = -1e30f, mrow1 = -1e30f, lrow0 = 0.0f, lrow1 = 0.0f;

    if (na > 0) {
        load_kv(0);
        CP_COMMIT();
    }

#pragma unroll 1
    for (int kb = 0; kb < na; kb++) {
        if (kb + 1 < na) {
            load_kv(kb + 1);
            CP_COMMIT();
            CP_WAIT(1);
        } else {
            CP_WAIT(0);
        }
        __syncthreads();

        const int af = act_s[kb];
        if (af) {
            const int c0 = kb * 64;
            u32 KhB = s2u(smraw + 32768 + (kb & 1) * 32768);
            u32 KlB = KhB + 8192, VhB = KhB + 16384, VlB = KhB + 24576;

            // ---- S = Q K^T (t-domain: Q carries 0.125*log2e) ----
            float sacc[8][4];
#pragma unroll
            for (int a = 0; a < 8; a++)
#pragma unroll
                for (int b = 0; b < 4; b++) sacc[a][b] = 0.0f;

#pragma unroll
            for (int kt = 0; kt < 4; kt++) {
                u32 qh[4], ql[4];
                ldsm4(qh[0], qh[1], qh[2], qh[3],
                      frag_addr(QhB, wid * 16, kt * 2, lane));
                ldsm4(ql[0], ql[1], ql[2], ql[3],
                      frag_addr(QlB, wid * 16, kt * 2, lane));
#pragma unroll
                for (int hf = 0; hf < 4; hf++) {
                    u32 k0r, k1r, k2r, k3r, l0r, l1r, l2r, l3r;
                    ldsm4(k0r, k1r, k2r, k3r,
                          frag_addr(KhB, hf * 16, kt * 2, lane));
                    ldsm4(l0r, l1r, l2r, l3r,
                          frag_addr(KlB, hf * 16, kt * 2, lane));
                    mma16816(sacc[2 * hf],     qh[0], qh[1], qh[2], qh[3], k0r, k2r);
                    mma16816(sacc[2 * hf],     qh[0], qh[1], qh[2], qh[3], l0r, l2r);
                    mma16816(sacc[2 * hf],     ql[0], ql[1], ql[2], ql[3], k0r, k2r);
                    mma16816(sacc[2 * hf + 1], qh[0], qh[1], qh[2], qh[3], k1r, k3r);
                    mma16816(sacc[2 * hf + 1], qh[0], qh[1], qh[2], qh[3], l1r, l3r);
                    mma16816(sacc[2 * hf + 1], ql[0], ql[1], ql[2], ql[3], k1r, k3r);
                }
            }

            // ---- mask only on partial tiles (t-domain additive) ----
            if (af == 1) {
#pragma unroll
                for (int nt = 0; nt < 8; nt++) {
                    float2 mk = *reinterpret_cast<const float2*>(
                        &mb[c0 + nt * 8 + t4 * 2]);
                    sacc[nt][0] += mk.x;
                    sacc[nt][1] += mk.y;
                    sacc[nt][2] += mk.x;
                    sacc[nt][3] += mk.y;
                }
            }

            // ---- online softmax (base-2 domain) ----
            float rmax0 = -1e30f, rmax1 = -1e30f;
#pragma unroll
            for (int nt = 0; nt < 8; nt++) {
                rmax0 = fmaxf(rmax0, fmaxf(sacc[nt][0], sacc[nt][1]));
                rmax1 = fmaxf(rmax1, fmaxf(sacc[nt][2], sacc[nt][3]));
            }
            rmax0 = fmaxf(rmax0, __shfl_xor_sync(0xffffffffu, rmax0, 1));
            rmax0 = fmaxf(rmax0, __shfl_xor_sync(0xffffffffu, rmax0, 2));
            rmax1 = fmaxf(rmax1, __shfl_xor_sync(0xffffffffu, rmax1, 1));
            rmax1 = fmaxf(rmax1, __shfl_xor_sync(0xffffffffu, rmax1, 2));
            float mp0 = mrow0, mp1 = mrow1;
            float mn0 = fmaxf(mrow0, rmax0), mn1 = fmaxf(mrow1, rmax1);
            float corr0 = ex2(mp0 - mn0), corr1 = ex2(mp1 - mn1);
            mrow0 = mn0; mrow1 = mn1;
            float rs0 = 0.0f, rs1 = 0.0f;
#pragma unroll
            for (int nt = 0; nt < 8; nt++) {
                sacc[nt][0] = ex2(sacc[nt][0] - mn0);
                sacc[nt][1] = ex2(sacc[nt][1] - mn0);
                sacc[nt][2] = ex2(sacc[nt][2] - mn1);
                sacc[nt][3] = ex2(sacc[nt][3] - mn1);
                rs0 += sacc[nt][0] + sacc[nt][1];
                rs1 += sacc[nt][2] + sacc[nt][3];
            }
            rs0 += __shfl_xor_sync(0xffffffffu, rs0, 1);
            rs0 += __shfl_xor_sync(0xffffffffu, rs0, 2);
            rs1 += __shfl_xor_sync(0xffffffffu, rs1, 1);
            rs1 += __shfl_xor_sync(0xffffffffu, rs1, 2);
            lrow0 = lrow0 * corr0 + rs0;
            lrow1 = lrow1 * corr1 + rs1;
            if (mn0 != mp0 || mn1 != mp1) {
#pragma unroll
                for (int dt = 0; dt < 8; dt++) {
                    oacc[dt][0] *= corr0; oacc[dt][1] *= corr0;
                    oacc[dt][2] *= corr1; oacc[dt][3] *= corr1;
                }
            }

            // ---- O += P V ----
#pragma unroll
            for (int j = 0; j < 4; j++) {
                u32 pa_h[4], pa_l[4];
                {
                    bf162 h0 = __floats2bfloat162_rn(sacc[2 * j][0], sacc[2 * j][1]);
                    bf162 h1 = __floats2bfloat162_rn(sacc[2 * j][2], sacc[2 * j][3]);
                    bf162 h2 = __floats2bfloat162_rn(sacc[2 * j + 1][0], sacc[2 * j + 1][1]);
                    bf162 h3 = __floats2bfloat162_rn(sacc[2 * j + 1][2], sacc[2 * j + 1][3]);
                    float2 f0 = __bfloat1622float2(h0), f1 = __bfloat1622float2(h1);
                    float2 f2 = __bfloat1622float2(h2), f3 = __bfloat1622float2(h3);
                    pa_h[0] = *(u32*)&h0; pa_h[1] = *(u32*)&h1;
                    pa_h[2] = *(u32*)&h2; pa_h[3] = *(u32*)&h3;
                    pa_l[0] = pkbf(sacc[2 * j][0] - f0.x, sacc[2 * j][1] - f0.y);
                    pa_l[1] = pkbf(sacc[2 * j][2] - f1.x, sacc[2 * j][3] - f1.y);
                    pa_l[2] = pkbf(sacc[2 * j + 1][0] - f2.x, sacc[2 * j + 1][1] - f2.y);
                    pa_l[3] = pkbf(sacc[2 * j + 1][2] - f3.x, sacc[2 * j + 1][3] - f3.y);
                }
#pragma unroll
                for (int c = 0; c < 4; c++) {
                    u32 v0, v1, v2, v3, w0, w1, w2, w3;
                    ldsm4t(v0, v1, v2, v3, frag_addr(VhB, j * 16, c * 2, lane));
                    ldsm4t(w0, w1, w2, w3, frag_addr(VlB, j * 16, c * 2, lane));
                    mma16816(oacc[2 * c],     pa_h[0], pa_h[1], pa_h[2], pa_h[3], v0, v1);
                    mma16816(oacc[2 * c],     pa_h[0], pa_h[1], pa_h[2], pa_h[3], w0, w1);
                    mma16816(oacc[2 * c],     pa_l[0], pa_l[1], pa_l[2], pa_l[3], v0, v1);
                    mma16816(oacc[2 * c + 1], pa_h[0], pa_h[1], pa_h[2], pa_h[3], v2, v3);
                    mma16816(oacc[2 * c + 1], pa_h[0], pa_h[1], pa_h[2], pa_h[3], w2, w3);
                    mma16816(oacc[2 * c + 1], pa_l[0], pa_l[1], pa_l[2], pa_l[3], v2, v3);
                }
            }
        }
        __syncthreads();
    }

    // ---- normalize + split-write [n, t, h*64 + d] as bf16 hi/lo ----
    float inv0 = 1.0f / lrow0, inv1 = 1.0f / lrow1;
#pragma unroll
    for (int dt = 0; dt < 8; dt++) {
        int col = h * DH + dt * 8 + t4 * 2;
        size_t r1 = (size_t)n * TT + q0 + wid * 16 + g;
        float a0 = oacc[dt][0] * inv0, a1 = oacc[dt][1] * inv0;
        float b0 = oacc[dt][2] * inv1, b1 = oacc[dt][3] * inv1;
        bf162 ha = __floats2bfloat162_rn(a0, a1);
        float2 fa = __bfloat1622float2(ha);
        bf162 la = __floats2bfloat162_rn(a0 - fa.x, a1 - fa.y);
        bf162 hbv = __floats2bfloat162_rn(b0, b1);
        float2 fb = __bfloat1622float2(hbv);
        bf162 lb = __floats2bfloat162_rn(b0 - fb.x, b1 - fb.y);
        *reinterpret_cast<bf162*>(&Aho[r1 * DM + col]) = ha;
        *reinterpret_cast<bf162*>(&Alo[r1 * DM + col]) = la;
        *reinterpret_cast<bf162*>(&Aho[(r1 + 8) * DM + col]) = hbv;
        *reinterpret_cast<bf162*>(&Alo[(r1 + 8) * DM + col]) = lb;
    }
}

// ---------------------------------------------------------------------------
// Launch
// ---------------------------------------------------------------------------
extern "C" void kernel_launch(void* const* d_in, const int* in_sizes, int n_in,
                              void* d_out, int out_size) {
    const float* x  = (const float*)d_in[0];
    const int*   mask = (const int*)d_in[1];
    const float* Wq = (const float*)d_in[2];
    const float* bq = (const float*)d_in[3];
    const float* Wk = (const float*)d_in[4];
    const float* bk = (const float*)d_in[5];
    const float* Wv = (const float*)d_in[6];
    const float* bv = (const float*)d_in[7];
    const float* Wo = (const float*)d_in[8];
    const float* bo = (const float*)d_in[9];
    float* out = (float*)d_out;

    bf16 *xh, *xl, *wqh, *wql, *wkh, *wkl, *wvh, *wvl, *woh, *wol;
    bf16 *qh, *ql, *kh, *kl, *vh, *vl, *ah, *al;
    float *mf;
    int *actg, *nag;
    cudaGetSymbolAddress((void**)&xh, g_xh);
    cudaGetSymbolAddress((void**)&xl, g_xl);
    cudaGetSymbolAddress((void**)&wqh, g_wqh);
    cudaGetSymbolAddress((void**)&wql, g_wql);
    cudaGetSymbolAddress((void**)&wkh, g_wkh);
    cudaGetSymbolAddress((void**)&wkl, g_wkl);
    cudaGetSymbolAddress((void**)&wvh, g_wvh);
    cudaGetSymbolAddress((void**)&wvl, g_wvl);
    cudaGetSymbolAddress((void**)&woh, g_woh);
    cudaGetSymbolAddress((void**)&wol, g_wol);
    cudaGetSymbolAddress((void**)&qh, g_qh);
    cudaGetSymbolAddress((void**)&ql, g_ql);
    cudaGetSymbolAddress((void**)&kh, g_kh);
    cudaGetSymbolAddress((void**)&kl, g_kl);
    cudaGetSymbolAddress((void**)&vh, g_vh);
    cudaGetSymbolAddress((void**)&vl, g_vl);
    cudaGetSymbolAddress((void**)&ah, g_ah);
    cudaGetSymbolAddress((void**)&al, g_al);
    cudaGetSymbolAddress((void**)&mf, g_maskf);
    cudaGetSymbolAddress((void**)&actg, g_act);
    cudaGetSymbolAddress((void**)&nag, g_na);

    cudaFuncSetAttribute(gemm_mma_kernel<0>,
                         cudaFuncAttributeMaxDynamicSharedMemorySize, 98304);
    cudaFuncSetAttribute(gemm_mma_kernel<1>,
                         cudaFuncAttributeMaxDynamicSharedMemorySize, 98304);
    cudaFuncSetAttribute(flash_mma_kernel,
                         cudaFuncAttributeMaxDynamicSharedMemorySize, 98304);

    prep_mask_kernel<<<NB, 64>>>(mask, mf, actg, nag);

    const int xn4 = MROWS * DM / 4;
    const int wn4 = DM * DM / 4;
    split_kernel<<<(xn4 + 255) / 256, 256>>>(x, xh, xl, xn4);
    split4w_kernel<<<(4 * wn4 + 255) / 256, 256>>>(
        Wq, Wk, Wv, Wo, wqh, wql, wkh, wkl, wvh, wvl, woh, wol, wn4);

    dim3 ggrid(MROWS / 128, DM / 128);
    gemm_mma_kernel<1><<<ggrid, 256, 98304>>>(xh, xl, wqh, wql, bq, QSCALE,
                                              nullptr, qh, ql);
    gemm_mma_kernel<1><<<ggrid, 256, 98304>>>(xh, xl, wkh, wkl, bk, 1.0f,
                                              nullptr, kh, kl);
    gemm_mma_kernel<1><<<ggrid, 256, 98304>>>(xh, xl, wvh, wvl, bv, 1.0f,
                                              nullptr, vh, vl);

    dim3 agrid(TT / 128, NH, NB);
    flash_mma_kernel<<<agrid, 256, 98304>>>(qh, ql, kh, kl, vh, vl, mf,
                                            actg, nag, ah, al);

    gemm_mma_kernel<0><<<ggrid, 256, 98304>>>(ah, al, woh, wol, bo, 1.0f,
                                              out, nullptr, nullptr);
}

// round 11
// speedup vs baseline: 3.4289x; 1.0324x over previous
#include <cuda_runtime.h>
#include <cuda_bf16.h>
#include <cstdint>

#define NB 2
#define TT 4096
#define DM 768
#define NH 12
#define DH 64
#define MROWS (NB * TT)   // 8192

typedef uint32_t u32;
typedef __nv_bfloat16 bf16;
typedef __nv_bfloat162 bf162;

#define QSCALE 0.18033688011112042f   // 0.125 * log2(e)

// ---------------------------------------------------------------------------
// Scratch in __device__ globals (allocation-free rule)
// ---------------------------------------------------------------------------
__device__ bf16 g_xh[(size_t)MROWS * DM];
__device__ bf16 g_xl[(size_t)MROWS * DM];
__device__ bf16 g_wqh[(size_t)DM * DM];
__device__ bf16 g_wql[(size_t)DM * DM];
__device__ bf16 g_wkh[(size_t)DM * DM];
__device__ bf16 g_wkl[(size_t)DM * DM];
__device__ bf16 g_wvh[(size_t)DM * DM];
__device__ bf16 g_wvl[(size_t)DM * DM];
__device__ bf16 g_woh[(size_t)DM * DM];
__device__ bf16 g_wol[(size_t)DM * DM];
__device__ bf16 g_qh[(size_t)MROWS * DM];
__device__ bf16 g_ql[(size_t)MROWS * DM];
__device__ bf16 g_kh[(size_t)MROWS * DM];
__device__ bf16 g_kl[(size_t)MROWS * DM];
__device__ bf16 g_vh[(size_t)MROWS * DM];
__device__ bf16 g_vl[(size_t)MROWS * DM];
__device__ bf16 g_ah[(size_t)MROWS * DM];
__device__ bf16 g_al[(size_t)MROWS * DM];
__device__ float g_maskf[(size_t)NB * TT];   // t-domain: 0 or -1e30*log2e
__device__ int   g_act[NB * 64];             // 0=skip, 1=partial, 2=full
__device__ int   g_na[NB];                   // last active tile + 1

// ---------------------------------------------------------------------------
// Helpers
// ---------------------------------------------------------------------------
__device__ __forceinline__ u32 s2u(const void* p) {
    return (u32)__cvta_generic_to_shared(p);
}
__device__ __forceinline__ void cpa16(u32 dst, const void* src) {
    asm volatile("cp.async.ca.shared.global [%0], [%1], 16;" :: "r"(dst), "l"(src));
}
#define CP_COMMIT()  asm volatile("cp.async.commit_group;")
#define CP_WAIT(N)   asm volatile("cp.async.wait_group %0;" :: "n"(N))

__device__ __forceinline__ void ldsm4(u32& r0, u32& r1, u32& r2, u32& r3, u32 a) {
    asm volatile("ldmatrix.sync.aligned.m8n8.x4.shared.b16 {%0,%1,%2,%3},[%4];"
                 : "=r"(r0), "=r"(r1), "=r"(r2), "=r"(r3) : "r"(a));
}
__device__ __forceinline__ void ldsm4t(u32& r0, u32& r1, u32& r2, u32& r3, u32 a) {
    asm volatile("ldmatrix.sync.aligned.m8n8.x4.trans.shared.b16 {%0,%1,%2,%3},[%4];"
                 : "=r"(r0), "=r"(r1), "=r"(r2), "=r"(r3) : "r"(a));
}
__device__ __forceinline__ void mma16816(float* c, u32 a0, u32 a1, u32 a2, u32 a3,
                                         u32 b0, u32 b1) {
    asm volatile(
        "mma.sync.aligned.m16n8k16.row.col.f32.bf16.bf16.f32 "
        "{%0,%1,%2,%3},{%4,%5,%6,%7},{%8,%9},{%0,%1,%2,%3};"
        : "+f"(c[0]), "+f"(c[1]), "+f"(c[2]), "+f"(c[3])
        : "r"(a0), "r"(a1), "r"(a2), "r"(a3), "r"(b0), "r"(b1));
}
__device__ __forceinline__ u32 pkbf(float lo, float hi) {
    bf162 t = __floats2bfloat162_rn(lo, hi);
    return *reinterpret_cast<u32*>(&t);
}
__device__ __forceinline__ float ex2(float x) {
    float y;
    asm("ex2.approx.ftz.f32 %0, %1;" : "=f"(y) : "f"(x));
    return y;
}
// Swizzled byte offset in a tile with 128B rows (8x 16B chunks per row)
__device__ __forceinline__ u32 swz(int row, int chunk) {
    return (u32)(row * 128 + ((chunk ^ (row & 7)) << 4));
}
__device__ __forceinline__ u32 frag_addr(u32 base, int r0, int c0, int lane) {
    return base + swz(r0 + (lane & 15), c0 + (lane >> 4));
}

// ---------------------------------------------------------------------------
// Mask prep: int32 bool -> t-domain additive bias, per-tile activity flags.
// ---------------------------------------------------------------------------
__global__ void prep_mask_kernel(const int* __restrict__ mask,
                                 float* __restrict__ out,
                                 int* __restrict__ actg, int* __restrict__ nag) {
    __shared__ int s_any[64];
    const int n = blockIdx.x, t = threadIdx.x;
    bool any = false, all = true;
#pragma unroll 8
    for (int j = 0; j < 64; j++) {
        int m = mask[n * TT + t * 64 + j];
        out[n * TT + t * 64 + j] = m ? -1.4426950e30f : 0.0f;
        any |= (m == 0);
        all &= (m == 0);
    }
    actg[n * 64 + t] = any ? (all ? 2 : 1) : 0;
    s_any[t] = any ? 1 : 0;
    __syncthreads();
    if (t == 0) {
        int na = 0;
        for (int j = 0; j < 64; j++)
            if (s_any[j]) na = j + 1;
        nag[n] = na;
    }
}

// ---------------------------------------------------------------------------
// fp32 -> bf16 hi/lo split
// ---------------------------------------------------------------------------
__device__ __forceinline__ void split4(float4 v, uint2& h, uint2& l) {
    bf162 h01 = __floats2bfloat162_rn(v.x, v.y);
    bf162 h23 = __floats2bfloat162_rn(v.z, v.w);
    float2 f01 = __bfloat1622float2(h01);
    float2 f23 = __bfloat1622float2(h23);
    bf162 l01 = __floats2bfloat162_rn(v.x - f01.x, v.y - f01.y);
    bf162 l23 = __floats2bfloat162_rn(v.z - f23.x, v.w - f23.y);
    h = make_uint2(*(u32*)&h01, *(u32*)&h23);
    l = make_uint2(*(u32*)&l01, *(u32*)&l23);
}

__global__ void split_kernel(const float* __restrict__ in, bf16* __restrict__ h,
                             bf16* __restrict__ l, int n4) {
    int i = blockIdx.x * blockDim.x + threadIdx.x;
    if (i >= n4) return;
    uint2 hh, ll;
    split4(reinterpret_cast<const float4*>(in)[i], hh, ll);
    reinterpret_cast<uint2*>(h)[i] = hh;
    reinterpret_cast<uint2*>(l)[i] = ll;
}

__global__ void split4w_kernel(const float* __restrict__ W0, const float* __restrict__ W1,
                               const float* __restrict__ W2, const float* __restrict__ W3,
                               bf16* __restrict__ h0, bf16* __restrict__ l0,
                               bf16* __restrict__ h1, bf16* __restrict__ l1,
                               bf16* __restrict__ h2, bf16* __restrict__ l2,
                               bf16* __restrict__ h3, bf16* __restrict__ l3, int n4) {
    int i = blockIdx.x * blockDim.x + threadIdx.x;
    int w = i / n4, j = i - w * n4;
    if (w >= 4) return;
    const float* in = (w == 0) ? W0 : (w == 1) ? W1 : (w == 2) ? W2 : W3;
    bf16* h = (w == 0) ? h0 : (w == 1) ? h1 : (w == 2) ? h2 : h3;
    bf16* l = (w == 0) ? l0 : (w == 1) ? l1 : (w == 2) ? l2 : l3;
    uint2 hh, ll;
    split4(reinterpret_cast<const float4*>(in)[j], hh, ll);
    reinterpret_cast<uint2*>(h)[j] = hh;
    reinterpret_cast<uint2*>(l)[j] = ll;
}

// ---------------------------------------------------------------------------
// Shared GEMM mainloop body (bf16x3, 3-stage cp.async, 128x128, BK=32).
// Returns accumulators; caller does the epilogue.
// ---------------------------------------------------------------------------
struct GemmCore {
    float acc[4][4][4];

    __device__ __forceinline__ void run(char* smraw, int tid, int lane,
                                        int wm, int wn, int row0, int col0,
                                        const bf16* Ah, const bf16* Al,
                                        const bf16* Bh, const bf16* Bl) {
#pragma unroll
        for (int a = 0; a < 4; a++)
#pragma unroll
            for (int b = 0; b < 4; b++)
#pragma unroll
                for (int c = 0; c < 4; c++) acc[a][b][c] = 0.0f;

        auto load_stage = [&](int s) {
            char* base = smraw + (s % 3) * 32768;
            u32 ab = s2u(base), bb = ab + 16384;
            int k0 = s * 32;
#pragma unroll
            for (int i = tid; i < 1024; i += 256) {
                int r = i >> 3, c = i & 7;
                const bf16* asrc = (c < 4)
                    ? &Ah[(size_t)(row0 + r) * DM + k0 + c * 8]
                    : &Al[(size_t)(row0 + r) * DM + k0 + (c - 4) * 8];
                cpa16(ab + swz(r, c), asrc);
                const bf16* bsrc = (c < 4)
                    ? &Bh[(size_t)(col0 + r) * DM + k0 + c * 8]
                    : &Bl[(size_t)(col0 + r) * DM + k0 + (c - 4) * 8];
                cpa16(bb + swz(r, c), bsrc);
            }
        };

        load_stage(0); CP_COMMIT();
        load_stage(1); CP_COMMIT();

        const int NS = DM / 32;  // 24
#pragma unroll 1
        for (int s = 0; s < NS; s++) {
            if (s + 1 < NS) { CP_WAIT(1); } else { CP_WAIT(0); }
            __syncthreads();

            u32 ab = s2u(smraw + (s % 3) * 32768), bb = ab + 16384;
#pragma unroll
            for (int kt = 0; kt < 2; kt++) {
                const int ch = 2 * kt, cl = 4 + 2 * kt;
                u32 bhf[4][2], blf[4][2];
#pragma unroll
                for (int half = 0; half < 2; half++) {
                    u32 r0, r1, r2, r3;
                    ldsm4(r0, r1, r2, r3, frag_addr(bb, wn * 32 + half * 16, ch, lane));
                    bhf[2 * half][0] = r0; bhf[2 * half + 1][0] = r1;
                    bhf[2 * half][1] = r2; bhf[2 * half + 1][1] = r3;
                    ldsm4(r0, r1, r2, r3, frag_addr(bb, wn * 32 + half * 16, cl, lane));
                    blf[2 * half][0] = r0; blf[2 * half + 1][0] = r1;
                    blf[2 * half][1] = r2; blf[2 * half + 1][1] = r3;
                }
#pragma unroll
                for (int mt = 0; mt < 4; mt++) {
                    u32 ah4[4], al4[4];
                    ldsm4(ah4[0], ah4[1], ah4[2], ah4[3],
                          frag_addr(ab, wm * 64 + mt * 16, ch, lane));
                    ldsm4(al4[0], al4[1], al4[2], al4[3],
                          frag_addr(ab, wm * 64 + mt * 16, cl, lane));
#pragma unroll
                    for (int nt = 0; nt < 4; nt++) {
                        mma16816(acc[mt][nt], ah4[0], ah4[1], ah4[2], ah4[3],
                                 bhf[nt][0], bhf[nt][1]);
                        mma16816(acc[mt][nt], ah4[0], ah4[1], ah4[2], ah4[3],
                                 blf[nt][0], blf[nt][1]);
                        mma16816(acc[mt][nt], al4[0], al4[1], al4[2], al4[3],
                                 bhf[nt][0], bhf[nt][1]);
                    }
                }
            }
            if (s + 2 < NS) { load_stage(s + 2); CP_COMMIT(); }
        }
    }
};

// ---------------------------------------------------------------------------
// Fused Q/K/V projection: blockIdx.z selects weight/bias/scale/output.
// Epilogue: (acc + bias) * cscale -> bf16 hi/lo head-split [n,h,t,dh].
// ---------------------------------------------------------------------------
__global__ __launch_bounds__(256, 2)
void gemm_qkv_kernel(const bf16* __restrict__ Xh, const bf16* __restrict__ Xl,
                     const bf16* __restrict__ Wqh, const bf16* __restrict__ Wql,
                     const bf16* __restrict__ Wkh, const bf16* __restrict__ Wkl,
                     const bf16* __restrict__ Wvh, const bf16* __restrict__ Wvl,
                     const float* __restrict__ bq, const float* __restrict__ bk,
                     const float* __restrict__ bv,
                     bf16* __restrict__ Qh, bf16* __restrict__ Ql,
                     bf16* __restrict__ Kh, bf16* __restrict__ Kl,
                     bf16* __restrict__ Vh, bf16* __restrict__ Vl) {
    extern __shared__ char smraw[];
    const int tid = threadIdx.x, lane = tid & 31, wid = tid >> 5;
    const int wm = wid >> 2, wn = wid & 3;
    const int row0 = blockIdx.x * 128, col0 = blockIdx.y * 128;
    const int w = blockIdx.z;

    const bf16* Bh = (w == 0) ? Wqh : (w == 1) ? Wkh : Wvh;
    const bf16* Bl = (w == 0) ? Wql : (w == 1) ? Wkl : Wvl;
    const float* bias = (w == 0) ? bq : (w == 1) ? bk : bv;
    bf16* Ch = (w == 0) ? Qh : (w == 1) ? Kh : Vh;
    bf16* Cl = (w == 0) ? Ql : (w == 1) ? Kl : Vl;
    const float cscale = (w == 0) ? QSCALE : 1.0f;

    GemmCore core;
    core.run(smraw, tid, lane, wm, wn, row0, col0, Xh, Xl, Bh, Bl);

    const int g = lane >> 2, t4 = lane & 3;
#pragma unroll
    for (int mt = 0; mt < 4; mt++)
#pragma unroll
        for (int nt = 0; nt < 4; nt++) {
            int col = col0 + wn * 32 + nt * 8 + t4 * 2;
            float bv0 = bias[col], bv1 = bias[col + 1];
#pragma unroll
            for (int half = 0; half < 2; half++) {
                int row = row0 + wm * 64 + mt * 16 + g + half * 8;
                float c0 = (core.acc[mt][nt][2 * half] + bv0) * cscale;
                float c1 = (core.acc[mt][nt][2 * half + 1] + bv1) * cscale;
                int n = row >> 12, t = row & (TT - 1);
                int h = col >> 6, d = col & 63;
                size_t idx = (((size_t)(n * NH + h)) * TT + t) * DH + d;
                bf162 hi = __floats2bfloat162_rn(c0, c1);
                float2 hf = __bfloat1622float2(hi);
                bf162 lo = __floats2bfloat162_rn(c0 - hf.x, c1 - hf.y);
                *reinterpret_cast<bf162*>(&Ch[idx]) = hi;
                *reinterpret_cast<bf162*>(&Cl[idx]) = lo;
            }
        }
}

// ---------------------------------------------------------------------------
// Output projection: fp32 epilogue to C [M,768].
// ---------------------------------------------------------------------------
__global__ __launch_bounds__(256, 2)
void gemm_out_kernel(const bf16* __restrict__ Ahg, const bf16* __restrict__ Alg,
                     const bf16* __restrict__ Bh, const bf16* __restrict__ Bl,
                     const float* __restrict__ bias, float* __restrict__ C) {
    extern __shared__ char smraw[];
    const int tid = threadIdx.x, lane = tid & 31, wid = tid >> 5;
    const int wm = wid >> 2, wn = wid & 3;
    const int row0 = blockIdx.x * 128, col0 = blockIdx.y * 128;

    GemmCore core;
    core.run(smraw, tid, lane, wm, wn, row0, col0, Ahg, Alg, Bh, Bl);

    const int g = lane >> 2, t4 = lane & 3;
#pragma unroll
    for (int mt = 0; mt < 4; mt++)
#pragma unroll
        for (int nt = 0; nt < 4; nt++) {
            int col = col0 + wn * 32 + nt * 8 + t4 * 2;
            float bv0 = bias[col], bv1 = bias[col + 1];
#pragma unroll
            for (int half = 0; half < 2; half++) {
                int row = row0 + wm * 64 + mt * 16 + g + half * 8;
                float c0 = core.acc[mt][nt][2 * half] + bv0;
                float c1 = core.acc[mt][nt][2 * half + 1] + bv1;
                *reinterpret_cast<float2*>(&C[(size_t)row * DM + col]) =
                    make_float2(c0, c1);
            }
        }
}

// ---------------------------------------------------------------------------
// Flash attention via mma.sync bf16x3, cp.async double-buffered K/V tiles.
// (unchanged from R10 — passing at rel_err 1.73e-5)
// ---------------------------------------------------------------------------
__global__ __launch_bounds__(256, 2)
void flash_mma_kernel(const bf16* __restrict__ Qhg, const bf16* __restrict__ Qlg,
                      const bf16* __restrict__ Khg, const bf16* __restrict__ Klg,
                      const bf16* __restrict__ Vhg, const bf16* __restrict__ Vlg,
                      const float* __restrict__ mbf,
                      const int* __restrict__ actg, const int* __restrict__ nag,
                      bf16* __restrict__ Aho, bf16* __restrict__ Alo) {
    extern __shared__ char smraw[];
    __shared__ int act_s[64];
    const u32 QhB = s2u(smraw), QlB = QhB + 16384;

    const int n = blockIdx.z, h = blockIdx.y;
    const int q0 = blockIdx.x * 128;
    const size_t hb = ((size_t)(n * NH + h)) * TT * DH;
    const float* mb = mbf + (size_t)n * TT;

    const int tid = threadIdx.x, lane = tid & 31, wid = tid >> 5;
    const int g = lane >> 2, t4 = lane & 3;

#pragma unroll
    for (int i = tid; i < 2048; i += 256) {
        int arr = i >> 10, r = (i >> 3) & 127, c = i & 7;
        const bf16* src = (arr ? Qlg : Qhg) + hb + (size_t)(q0 + r) * DH + c * 8;
        cpa16(QhB + arr * 16384 + swz(r, c), src);
    }
    CP_COMMIT();

    if (tid < 64) act_s[tid] = actg[n * 64 + tid];
    const int na = nag[n];
    __syncthreads();

    auto load_kv = [&](int kb) {
        u32 base = s2u(smraw + 32768 + (kb & 1) * 32768);
        int c0 = kb * 64;
#pragma unroll
        for (int i = tid; i < 2048; i += 256) {
            int arr = i >> 9, r = (i >> 3) & 63, c = i & 7;
            const bf16* gsrc = (arr == 0) ? Khg : (arr == 1) ? Klg
                             : (arr == 2) ? Vhg : Vlg;
            cpa16(base + arr * 8192 + swz(r, c),
                  gsrc + hb + (size_t)(c0 + r) * DH + c * 8);
        }
    };

    float oacc[8][4];
#pragma unroll
    for (int a = 0; a < 8; a++)
#pragma unroll
        for (int b = 0; b < 4; b++) oacc[a][b] = 0.0f;
    float mrow0 = -1e30f, mrow1 = -1e30f, lrow0 = 0.0f, lrow1 = 0.0f;

    if (na > 0) {
        load_kv(0);
        CP_COMMIT();
    }

#pragma unroll 1
    for (int kb = 0; kb < na; kb++) {
        if (kb + 1 < na) {
            load_kv(kb + 1);
            CP_COMMIT();
            CP_WAIT(1);
        } else {
            CP_WAIT(0);
        }
        __syncthreads();

        const int af = act_s[kb];
        if (af) {
            const int c0 = kb * 64;
            u32 KhB = s2u(smraw + 32768 + (kb & 1) * 32768);
            u32 KlB = KhB + 8192, VhB = KhB + 16384, VlB = KhB + 24576;

            float sacc[8][4];
#pragma unroll
            for (int a = 0; a < 8; a++)
#pragma unroll
                for (int b = 0; b < 4; b++) sacc[a][b] = 0.0f;

#pragma unroll
            for (int kt = 0; kt < 4; kt++) {
                u32 qh[4], ql[4];
                ldsm4(qh[0], qh[1], qh[2], qh[3],
                      frag_addr(QhB, wid * 16, kt * 2, lane));
                ldsm4(ql[0], ql[1], ql[2], ql[3],
                      frag_addr(QlB, wid * 16, kt * 2, lane));
#pragma unroll
                for (int hf = 0; hf < 4; hf++) {
                    u32 k0r, k1r, k2r, k3r, l0r, l1r, l2r, l3r;
                    ldsm4(k0r, k1r, k2r, k3r,
                          frag_addr(KhB, hf * 16, kt * 2, lane));
                    ldsm4(l0r, l1r, l2r, l3r,
                          frag_addr(KlB, hf * 16, kt * 2, lane));
                    mma16816(sacc[2 * hf],     qh[0], qh[1], qh[2], qh[3], k0r, k2r);
                    mma16816(sacc[2 * hf],     qh[0], qh[1], qh[2], qh[3], l0r, l2r);
                    mma16816(sacc[2 * hf],     ql[0], ql[1], ql[2], ql[3], k0r, k2r);
                    mma16816(sacc[2 * hf + 1], qh[0], qh[1], qh[2], qh[3], k1r, k3r);
                    mma16816(sacc[2 * hf + 1], qh[0], qh[1], qh[2], qh[3], l1r, l3r);
                    mma16816(sacc[2 * hf + 1], ql[0], ql[1], ql[2], ql[3], k1r, k3r);
                }
            }

            if (af == 1) {
#pragma unroll
                for (int nt = 0; nt < 8; nt++) {
                    float2 mk = *reinterpret_cast<const float2*>(
                        &mb[c0 + nt * 8 + t4 * 2]);
                    sacc[nt][0] += mk.x;
                    sacc[nt][1] += mk.y;
                    sacc[nt][2] += mk.x;
                    sacc[nt][3] += mk.y;
                }
            }

            float rmax0 = -1e30f, rmax1 = -1e30f;
#pragma unroll
            for (int nt = 0; nt < 8; nt++) {
                rmax0 = fmaxf(rmax0, fmaxf(sacc[nt][0], sacc[nt][1]));
                rmax1 = fmaxf(rmax1, fmaxf(sacc[nt][2], sacc[nt][3]));
            }
            rmax0 = fmaxf(rmax0, __shfl_xor_sync(0xffffffffu, rmax0, 1));
            rmax0 = fmaxf(rmax0, __shfl_xor_sync(0xffffffffu, rmax0, 2));
            rmax1 = fmaxf(rmax1, __shfl_xor_sync(0xffffffffu, rmax1, 1));
            rmax1 = fmaxf(rmax1, __shfl_xor_sync(0xffffffffu, rmax1, 2));
            float mp0 = mrow0, mp1 = mrow1;
            float mn0 = fmaxf(mrow0, rmax0), mn1 = fmaxf(mrow1, rmax1);
            float corr0 = ex2(mp0 - mn0), corr1 = ex2(mp1 - mn1);
            mrow0 = mn0; mrow1 = mn1;
            float rs0 = 0.0f, rs1 = 0.0f;
#pragma unroll
            for (int nt = 0; nt < 8; nt++) {
                sacc[nt][0] = ex2(sacc[nt][0] - mn0);
                sacc[nt][1] = ex2(sacc[nt][1] - mn0);
                sacc[nt][2] = ex2(sacc[nt][2] - mn1);
                sacc[nt][3] = ex2(sacc[nt][3] - mn1);
                rs0 += sacc[nt][0] + sacc[nt][1];
                rs1 += sacc[nt][2] + sacc[nt][3];
            }
            rs0 += __shfl_xor_sync(0xffffffffu, rs0, 1);
            rs0 += __shfl_xor_sync(0xffffffffu, rs0, 2);
            rs1 += __shfl_xor_sync(0xffffffffu, rs1, 1);
            rs1 += __shfl_xor_sync(0xffffffffu, rs1, 2);
            lrow0 = lrow0 * corr0 + rs0;
            lrow1 = lrow1 * corr1 + rs1;
            if (mn0 != mp0 || mn1 != mp1) {
#pragma unroll
                for (int dt = 0; dt < 8; dt++) {
                    oacc[dt][0] *= corr0; oacc[dt][1] *= corr0;
                    oacc[dt][2] *= corr1; oacc[dt][3] *= corr1;
                }
            }

#pragma unroll
            for (int j = 0; j < 4; j++) {
                u32 pa_h[4], pa_l[4];
                {
                    bf162 h0 = __floats2bfloat162_rn(sacc[2 * j][0], sacc[2 * j][1]);
                    bf162 h1 = __floats2bfloat162_rn(sacc[2 * j][2], sacc[2 * j][3]);
                    bf162 h2 = __floats2bfloat162_rn(sacc[2 * j + 1][0], sacc[2 * j + 1][1]);
                    bf162 h3 = __floats2bfloat162_rn(sacc[2 * j + 1][2], sacc[2 * j + 1][3]);
                    float2 f0 = __bfloat1622float2(h0), f1 = __bfloat1622float2(h1);
                    float2 f2 = __bfloat1622float2(h2), f3 = __bfloat1622float2(h3);
                    pa_h[0] = *(u32*)&h0; pa_h[1] = *(u32*)&h1;
                    pa_h[2] = *(u32*)&h2; pa_h[3] = *(u32*)&h3;
                    pa_l[0] = pkbf(sacc[2 * j][0] - f0.x, sacc[2 * j][1] - f0.y);
                    pa_l[1] = pkbf(sacc[2 * j][2] - f1.x, sacc[2 * j][3] - f1.y);
                    pa_l[2] = pkbf(sacc[2 * j + 1][0] - f2.x, sacc[2 * j + 1][1] - f2.y);
                    pa_l[3] = pkbf(sacc[2 * j + 1][2] - f3.x, sacc[2 * j + 1][3] - f3.y);
                }
#pragma unroll
                for (int c = 0; c < 4; c++) {
                    u32 v0, v1, v2, v3, w0, w1, w2, w3;
                    ldsm4t(v0, v1, v2, v3, frag_addr(VhB, j * 16, c * 2, lane));
                    ldsm4t(w0, w1, w2, w3, frag_addr(VlB, j * 16, c * 2, lane));
                    mma16816(oacc[2 * c],     pa_h[0], pa_h[1], pa_h[2], pa_h[3], v0, v1);
                    mma16816(oacc[2 * c],     pa_h[0], pa_h[1], pa_h[2], pa_h[3], w0, w1);
                    mma16816(oacc[2 * c],     pa_l[0], pa_l[1], pa_l[2], pa_l[3], v0, v1);
                    mma16816(oacc[2 * c + 1], pa_h[0], pa_h[1], pa_h[2], pa_h[3], v2, v3);
                    mma16816(oacc[2 * c + 1], pa_h[0], pa_h[1], pa_h[2], pa_h[3], w2, w3);
                    mma16816(oacc[2 * c + 1], pa_l[0], pa_l[1], pa_l[2], pa_l[3], v2, v3);
                }
            }
        }
        __syncthreads();
    }

    float inv0 = 1.0f / lrow0, inv1 = 1.0f / lrow1;
#pragma unroll
    for (int dt = 0; dt < 8; dt++) {
        int col = h * DH + dt * 8 + t4 * 2;
        size_t r1 = (size_t)n * TT + q0 + wid * 16 + g;
        float a0 = oacc[dt][0] * inv0, a1 = oacc[dt][1] * inv0;
        float b0 = oacc[dt][2] * inv1, b1 = oacc[dt][3] * inv1;
        bf162 ha = __floats2bfloat162_rn(a0, a1);
        float2 fa = __bfloat1622float2(ha);
        bf162 la = __floats2bfloat162_rn(a0 - fa.x, a1 - fa.y);
        bf162 hbv = __floats2bfloat162_rn(b0, b1);
        float2 fb = __bfloat1622float2(hbv);
        bf162 lb = __floats2bfloat162_rn(b0 - fb.x, b1 - fb.y);
        *reinterpret_cast<bf162*>(&Aho[r1 * DM + col]) = ha;
        *reinterpret_cast<bf162*>(&Alo[r1 * DM + col]) = la;
        *reinterpret_cast<bf162*>(&Aho[(r1 + 8) * DM + col]) = hbv;
        *reinterpret_cast<bf162*>(&Alo[(r1 + 8) * DM + col]) = lb;
    }
}

// ---------------------------------------------------------------------------
// Launch
// ---------------------------------------------------------------------------
extern "C" void kernel_launch(void* const* d_in, const int* in_sizes, int n_in,
                              void* d_out, int out_size) {
    const float* x  = (const float*)d_in[0];
    const int*   mask = (const int*)d_in[1];
    const float* Wq = (const float*)d_in[2];
    const float* bq = (const float*)d_in[3];
    const float* Wk = (const float*)d_in[4];
    const float* bk = (const float*)d_in[5];
    const float* Wv = (const float*)d_in[6];
    const float* bv = (const float*)d_in[7];
    const float* Wo = (const float*)d_in[8];
    const float* bo = (const float*)d_in[9];
    float* out = (float*)d_out;

    bf16 *xh, *xl, *wqh, *wql, *wkh, *wkl, *wvh, *wvl, *woh, *wol;
    bf16 *qh, *ql, *kh, *kl, *vh, *vl, *ah, *al;
    float *mf;
    int *actg, *nag;
    cudaGetSymbolAddress((void**)&xh, g_xh);
    cudaGetSymbolAddress((void**)&xl, g_xl);
    cudaGetSymbolAddress((void**)&wqh, g_wqh);
    cudaGetSymbolAddress((void**)&wql, g_wql);
    cudaGetSymbolAddress((void**)&wkh, g_wkh);
    cudaGetSymbolAddress((void**)&wkl, g_wkl);
    cudaGetSymbolAddress((void**)&wvh, g_wvh);
    cudaGetSymbolAddress((void**)&wvl, g_wvl);
    cudaGetSymbolAddress((void**)&woh, g_woh);
    cudaGetSymbolAddress((void**)&wol, g_wol);
    cudaGetSymbolAddress((void**)&qh, g_qh);
    cudaGetSymbolAddress((void**)&ql, g_ql);
    cudaGetSymbolAddress((void**)&kh, g_kh);
    cudaGetSymbolAddress((void**)&kl, g_kl);
    cudaGetSymbolAddress((void**)&vh, g_vh);
    cudaGetSymbolAddress((void**)&vl, g_vl);
    cudaGetSymbolAddress((void**)&ah, g_ah);
    cudaGetSymbolAddress((void**)&al, g_al);
    cudaGetSymbolAddress((void**)&mf, g_maskf);
    cudaGetSymbolAddress((void**)&actg, g_act);
    cudaGetSymbolAddress((void**)&nag, g_na);

    cudaFuncSetAttribute(gemm_qkv_kernel,
                         cudaFuncAttributeMaxDynamicSharedMemorySize, 98304);
    cudaFuncSetAttribute(gemm_out_kernel,
                         cudaFuncAttributeMaxDynamicSharedMemorySize, 98304);
    cudaFuncSetAttribute(flash_mma_kernel,
                         cudaFuncAttributeMaxDynamicSharedMemorySize, 98304);

    prep_mask_kernel<<<NB, 64>>>(mask, mf, actg, nag);

    const int xn4 = MROWS * DM / 4;
    const int wn4 = DM * DM / 4;
    split_kernel<<<(xn4 + 255) / 256, 256>>>(x, xh, xl, xn4);
    split4w_kernel<<<(4 * wn4 + 255) / 256, 256>>>(
        Wq, Wk, Wv, Wo, wqh, wql, wkh, wkl, wvh, wvl, woh, wol, wn4);

    dim3 qkvgrid(MROWS / 128, DM / 128, 3);
    gemm_qkv_kernel<<<qkvgrid, 256, 98304>>>(
        xh, xl, wqh, wql, wkh, wkl, wvh, wvl, bq, bk, bv,
        qh, ql, kh, kl, vh, vl);

    dim3 agrid(TT / 128, NH, NB);
    flash_mma_kernel<<<agrid, 256, 98304>>>(qh, ql, kh, kl, vh, vl, mf,
                                            actg, nag, ah, al);

    dim3 ogrid(MROWS / 128, DM / 128);
    gemm_out_kernel<<<ogrid, 256, 98304>>>(ah, al, woh, wol, bo, out);
}

// round 12
// speedup vs baseline: 3.6466x; 1.0635x over previous
#include <cuda_runtime.h>
#include <cuda_bf16.h>
#include <cstdint>

#define NB 2
#define TT 4096
#define DM 768
#define NH 12
#define DH 64
#define MROWS (NB * TT)   // 8192

typedef uint32_t u32;
typedef __nv_bfloat16 bf16;
typedef __nv_bfloat162 bf162;

#define QSCALE 0.18033688011112042f   // 0.125 * log2(e)

// ---------------------------------------------------------------------------
// Scratch in __device__ globals (allocation-free rule)
// ---------------------------------------------------------------------------
__device__ bf16 g_xh[(size_t)MROWS * DM];
__device__ bf16 g_xl[(size_t)MROWS * DM];
__device__ bf16 g_wqh[(size_t)DM * DM];
__device__ bf16 g_wql[(size_t)DM * DM];
__device__ bf16 g_wkh[(size_t)DM * DM];
__device__ bf16 g_wkl[(size_t)DM * DM];
__device__ bf16 g_wvh[(size_t)DM * DM];
__device__ bf16 g_wvl[(size_t)DM * DM];
__device__ bf16 g_woh[(size_t)DM * DM];
__device__ bf16 g_wol[(size_t)DM * DM];
__device__ bf16 g_qh[(size_t)MROWS * DM];
__device__ bf16 g_ql[(size_t)MROWS * DM];
__device__ bf16 g_kh[(size_t)MROWS * DM];
__device__ bf16 g_kl[(size_t)MROWS * DM];
__device__ bf16 g_vh[(size_t)MROWS * DM];
__device__ bf16 g_vl[(size_t)MROWS * DM];
__device__ bf16 g_ah[(size_t)MROWS * DM];
__device__ bf16 g_al[(size_t)MROWS * DM];
__device__ float g_maskf[(size_t)NB * TT];   // t-domain: 0 or -1e30*log2e
__device__ int   g_act[NB * 64];             // 0=skip, 1=partial, 2=full
__device__ int   g_na[NB];                   // last active tile + 1

// ---------------------------------------------------------------------------
// Helpers
// ---------------------------------------------------------------------------
__device__ __forceinline__ u32 s2u(const void* p) {
    return (u32)__cvta_generic_to_shared(p);
}
// L2-only (cg) 16B async copy — staged tiles are stream-once, keep them out of L1
__device__ __forceinline__ void cpa16(u32 dst, const void* src) {
    asm volatile("cp.async.cg.shared.global [%0], [%1], 16;" :: "r"(dst), "l"(src));
}
#define CP_COMMIT()  asm volatile("cp.async.commit_group;")
#define CP_WAIT(N)   asm volatile("cp.async.wait_group %0;" :: "n"(N))

__device__ __forceinline__ void ldsm4(u32& r0, u32& r1, u32& r2, u32& r3, u32 a) {
    asm volatile("ldmatrix.sync.aligned.m8n8.x4.shared.b16 {%0,%1,%2,%3},[%4];"
                 : "=r"(r0), "=r"(r1), "=r"(r2), "=r"(r3) : "r"(a));
}
__device__ __forceinline__ void ldsm4t(u32& r0, u32& r1, u32& r2, u32& r3, u32 a) {
    asm volatile("ldmatrix.sync.aligned.m8n8.x4.trans.shared.b16 {%0,%1,%2,%3},[%4];"
                 : "=r"(r0), "=r"(r1), "=r"(r2), "=r"(r3) : "r"(a));
}
__device__ __forceinline__ void mma16816(float* c, u32 a0, u32 a1, u32 a2, u32 a3,
                                         u32 b0, u32 b1) {
    asm volatile(
        "mma.sync.aligned.m16n8k16.row.col.f32.bf16.bf16.f32 "
        "{%0,%1,%2,%3},{%4,%5,%6,%7},{%8,%9},{%0,%1,%2,%3};"
        : "+f"(c[0]), "+f"(c[1]), "+f"(c[2]), "+f"(c[3])
        : "r"(a0), "r"(a1), "r"(a2), "r"(a3), "r"(b0), "r"(b1));
}
__device__ __forceinline__ u32 pkbf(float lo, float hi) {
    bf162 t = __floats2bfloat162_rn(lo, hi);
    return *reinterpret_cast<u32*>(&t);
}
__device__ __forceinline__ float ex2(float x) {
    float y;
    asm("ex2.approx.ftz.f32 %0, %1;" : "=f"(y) : "f"(x));
    return y;
}
// Swizzled byte offset in a tile with 128B rows (8x 16B chunks per row)
__device__ __forceinline__ u32 swz(int row, int chunk) {
    return (u32)(row * 128 + ((chunk ^ (row & 7)) << 4));
}
__device__ __forceinline__ u32 frag_addr(u32 base, int r0, int c0, int lane) {
    return base + swz(r0 + (lane & 15), c0 + (lane >> 4));
}

// ---------------------------------------------------------------------------
// Mask prep: int32 bool -> t-domain additive bias, per-tile activity flags.
// ---------------------------------------------------------------------------
__global__ void prep_mask_kernel(const int* __restrict__ mask,
                                 float* __restrict__ out,
                                 int* __restrict__ actg, int* __restrict__ nag) {
    __shared__ int s_any[64];
    const int n = blockIdx.x, t = threadIdx.x;
    bool any = false, all = true;
#pragma unroll 8
    for (int j = 0; j < 64; j++) {
        int m = mask[n * TT + t * 64 + j];
        out[n * TT + t * 64 + j] = m ? -1.4426950e30f : 0.0f;
        any |= (m == 0);
        all &= (m == 0);
    }
    actg[n * 64 + t] = any ? (all ? 2 : 1) : 0;
    s_any[t] = any ? 1 : 0;
    __syncthreads();
    if (t == 0) {
        int na = 0;
        for (int j = 0; j < 64; j++)
            if (s_any[j]) na = j + 1;
        nag[n] = na;
    }
}

// ---------------------------------------------------------------------------
// fp32 -> bf16 hi/lo split
// ---------------------------------------------------------------------------
__device__ __forceinline__ void split4(float4 v, uint2& h, uint2& l) {
    bf162 h01 = __floats2bfloat162_rn(v.x, v.y);
    bf162 h23 = __floats2bfloat162_rn(v.z, v.w);
    float2 f01 = __bfloat1622float2(h01);
    float2 f23 = __bfloat1622float2(h23);
    bf162 l01 = __floats2bfloat162_rn(v.x - f01.x, v.y - f01.y);
    bf162 l23 = __floats2bfloat162_rn(v.z - f23.x, v.w - f23.y);
    h = make_uint2(*(u32*)&h01, *(u32*)&h23);
    l = make_uint2(*(u32*)&l01, *(u32*)&l23);
}

__global__ void split_kernel(const float* __restrict__ in, bf16* __restrict__ h,
                             bf16* __restrict__ l, int n4) {
    int i = blockIdx.x * blockDim.x + threadIdx.x;
    if (i >= n4) return;
    uint2 hh, ll;
    split4(reinterpret_cast<const float4*>(in)[i], hh, ll);
    reinterpret_cast<uint2*>(h)[i] = hh;
    reinterpret_cast<uint2*>(l)[i] = ll;
}

__global__ void split4w_kernel(const float* __restrict__ W0, const float* __restrict__ W1,
                               const float* __restrict__ W2, const float* __restrict__ W3,
                               bf16* __restrict__ h0, bf16* __restrict__ l0,
                               bf16* __restrict__ h1, bf16* __restrict__ l1,
                               bf16* __restrict__ h2, bf16* __restrict__ l2,
                               bf16* __restrict__ h3, bf16* __restrict__ l3, int n4) {
    int i = blockIdx.x * blockDim.x + threadIdx.x;
    int w = i / n4, j = i - w * n4;
    if (w >= 4) return;
    const float* in = (w == 0) ? W0 : (w == 1) ? W1 : (w == 2) ? W2 : W3;
    bf16* h = (w == 0) ? h0 : (w == 1) ? h1 : (w == 2) ? h2 : h3;
    bf16* l = (w == 0) ? l0 : (w == 1) ? l1 : (w == 2) ? l2 : l3;
    uint2 hh, ll;
    split4(reinterpret_cast<const float4*>(in)[j], hh, ll);
    reinterpret_cast<uint2*>(h)[j] = hh;
    reinterpret_cast<uint2*>(l)[j] = ll;
}

// ---------------------------------------------------------------------------
// Shared GEMM mainloop body (bf16x3, 3-stage cp.async, 128x128, BK=32).
// ---------------------------------------------------------------------------
struct GemmCore {
    float acc[4][4][4];

    __device__ __forceinline__ void run(char* smraw, int tid, int lane,
                                        int wm, int wn, int row0, int col0,
                                        const bf16* Ah, const bf16* Al,
                                        const bf16* Bh, const bf16* Bl) {
#pragma unroll
        for (int a = 0; a < 4; a++)
#pragma unroll
            for (int b = 0; b < 4; b++)
#pragma unroll
                for (int c = 0; c < 4; c++) acc[a][b][c] = 0.0f;

        auto load_stage = [&](int s) {
            char* base = smraw + (s % 3) * 32768;
            u32 ab = s2u(base), bb = ab + 16384;
            int k0 = s * 32;
#pragma unroll
            for (int i = tid; i < 1024; i += 256) {
                int r = i >> 3, c = i & 7;
                const bf16* asrc = (c < 4)
                    ? &Ah[(size_t)(row0 + r) * DM + k0 + c * 8]
                    : &Al[(size_t)(row0 + r) * DM + k0 + (c - 4) * 8];
                cpa16(ab + swz(r, c), asrc);
                const bf16* bsrc = (c < 4)
                    ? &Bh[(size_t)(col0 + r) * DM + k0 + c * 8]
                    : &Bl[(size_t)(col0 + r) * DM + k0 + (c - 4) * 8];
                cpa16(bb + swz(r, c), bsrc);
            }
        };

        load_stage(0); CP_COMMIT();
        load_stage(1); CP_COMMIT();

        const int NS = DM / 32;  // 24
#pragma unroll 1
        for (int s = 0; s < NS; s++) {
            if (s + 1 < NS) { CP_WAIT(1); } else { CP_WAIT(0); }
            __syncthreads();

            u32 ab = s2u(smraw + (s % 3) * 32768), bb = ab + 16384;
#pragma unroll
            for (int kt = 0; kt < 2; kt++) {
                const int ch = 2 * kt, cl = 4 + 2 * kt;
                u32 bhf[4][2], blf[4][2];
#pragma unroll
                for (int half = 0; half < 2; half++) {
                    u32 r0, r1, r2, r3;
                    ldsm4(r0, r1, r2, r3, frag_addr(bb, wn * 32 + half * 16, ch, lane));
                    bhf[2 * half][0] = r0; bhf[2 * half + 1][0] = r1;
                    bhf[2 * half][1] = r2; bhf[2 * half + 1][1] = r3;
                    ldsm4(r0, r1, r2, r3, frag_addr(bb, wn * 32 + half * 16, cl, lane));
                    blf[2 * half][0] = r0; blf[2 * half + 1][0] = r1;
                    blf[2 * half][1] = r2; blf[2 * half + 1][1] = r3;
                }
#pragma unroll
                for (int mt = 0; mt < 4; mt++) {
                    u32 ah4[4], al4[4];
                    ldsm4(ah4[0], ah4[1], ah4[2], ah4[3],
                          frag_addr(ab, wm * 64 + mt * 16, ch, lane));
                    ldsm4(al4[0], al4[1], al4[2], al4[3],
                          frag_addr(ab, wm * 64 + mt * 16, cl, lane));
#pragma unroll
                    for (int nt = 0; nt < 4; nt++) {
                        mma16816(acc[mt][nt], ah4[0], ah4[1], ah4[2], ah4[3],
                                 bhf[nt][0], bhf[nt][1]);
                        mma16816(acc[mt][nt], ah4[0], ah4[1], ah4[2], ah4[3],
                                 blf[nt][0], blf[nt][1]);
                        mma16816(acc[mt][nt], al4[0], al4[1], al4[2], al4[3],
                                 bhf[nt][0], bhf[nt][1]);
                    }
                }
            }
            if (s + 2 < NS) { load_stage(s + 2); CP_COMMIT(); }
        }
    }
};

// ---------------------------------------------------------------------------
// Fused Q/K/V projection: blockIdx.z selects weight/bias/scale/output.
// ---------------------------------------------------------------------------
__global__ __launch_bounds__(256, 2)
void gemm_qkv_kernel(const bf16* __restrict__ Xh, const bf16* __restrict__ Xl,
                     const bf16* __restrict__ Wqh, const bf16* __restrict__ Wql,
                     const bf16* __restrict__ Wkh, const bf16* __restrict__ Wkl,
                     const bf16* __restrict__ Wvh, const bf16* __restrict__ Wvl,
                     const float* __restrict__ bq, const float* __restrict__ bk,
                     const float* __restrict__ bv,
                     bf16* __restrict__ Qh, bf16* __restrict__ Ql,
                     bf16* __restrict__ Kh, bf16* __restrict__ Kl,
                     bf16* __restrict__ Vh, bf16* __restrict__ Vl) {
    extern __shared__ char smraw[];
    const int tid = threadIdx.x, lane = tid & 31, wid = tid >> 5;
    const int wm = wid >> 2, wn = wid & 3;
    const int row0 = blockIdx.x * 128, col0 = blockIdx.y * 128;
    const int w = blockIdx.z;

    const bf16* Bh = (w == 0) ? Wqh : (w == 1) ? Wkh : Wvh;
    const bf16* Bl = (w == 0) ? Wql : (w == 1) ? Wkl : Wvl;
    const float* bias = (w == 0) ? bq : (w == 1) ? bk : bv;
    bf16* Ch = (w == 0) ? Qh : (w == 1) ? Kh : Vh;
    bf16* Cl = (w == 0) ? Ql : (w == 1) ? Kl : Vl;
    const float cscale = (w == 0) ? QSCALE : 1.0f;

    GemmCore core;
    core.run(smraw, tid, lane, wm, wn, row0, col0, Xh, Xl, Bh, Bl);

    const int g = lane >> 2, t4 = lane & 3;
#pragma unroll
    for (int mt = 0; mt < 4; mt++)
#pragma unroll
        for (int nt = 0; nt < 4; nt++) {
            int col = col0 + wn * 32 + nt * 8 + t4 * 2;
            float bv0 = bias[col], bv1 = bias[col + 1];
#pragma unroll
            for (int half = 0; half < 2; half++) {
                int row = row0 + wm * 64 + mt * 16 + g + half * 8;
                float c0 = (core.acc[mt][nt][2 * half] + bv0) * cscale;
                float c1 = (core.acc[mt][nt][2 * half + 1] + bv1) * cscale;
                int n = row >> 12, t = row & (TT - 1);
                int h = col >> 6, d = col & 63;
                size_t idx = (((size_t)(n * NH + h)) * TT + t) * DH + d;
                bf162 hi = __floats2bfloat162_rn(c0, c1);
                float2 hf = __bfloat1622float2(hi);
                bf162 lo = __floats2bfloat162_rn(c0 - hf.x, c1 - hf.y);
                *reinterpret_cast<bf162*>(&Ch[idx]) = hi;
                *reinterpret_cast<bf162*>(&Cl[idx]) = lo;
            }
        }
}

// ---------------------------------------------------------------------------
// Output projection: fp32 epilogue to C [M,768].
// ---------------------------------------------------------------------------
__global__ __launch_bounds__(256, 2)
void gemm_out_kernel(const bf16* __restrict__ Ahg, const bf16* __restrict__ Alg,
                     const bf16* __restrict__ Bh, const bf16* __restrict__ Bl,
                     const float* __restrict__ bias, float* __restrict__ C) {
    extern __shared__ char smraw[];
    const int tid = threadIdx.x, lane = tid & 31, wid = tid >> 5;
    const int wm = wid >> 2, wn = wid & 3;
    const int row0 = blockIdx.x * 128, col0 = blockIdx.y * 128;

    GemmCore core;
    core.run(smraw, tid, lane, wm, wn, row0, col0, Ahg, Alg, Bh, Bl);

    const int g = lane >> 2, t4 = lane & 3;
#pragma unroll
    for (int mt = 0; mt < 4; mt++)
#pragma unroll
        for (int nt = 0; nt < 4; nt++) {
            int col = col0 + wn * 32 + nt * 8 + t4 * 2;
            float bv0 = bias[col], bv1 = bias[col + 1];
#pragma unroll
            for (int half = 0; half < 2; half++) {
                int row = row0 + wm * 64 + mt * 16 + g + half * 8;
                float c0 = core.acc[mt][nt][2 * half] + bv0;
                float c1 = core.acc[mt][nt][2 * half + 1] + bv1;
                *reinterpret_cast<float2*>(&C[(size_t)row * DM + col]) =
                    make_float2(c0, c1);
            }
        }
}

// ---------------------------------------------------------------------------
// Flash attention via mma.sync bf16x3, cp.async double-buffered K/V tiles with
// SPLIT K/V commit groups: S waits only for K; PV waits for V.
// Per-tile commit order: K(kb+1), V(kb+1); wait_group(3) -> K(kb) ready,
// wait_group(2) -> V(kb) ready. Final tile: wait(1)/wait(0).
// ---------------------------------------------------------------------------
__global__ __launch_bounds__(256, 2)
void flash_mma_kernel(const bf16* __restrict__ Qhg, const bf16* __restrict__ Qlg,
                      const bf16* __restrict__ Khg, const bf16* __restrict__ Klg,
                      const bf16* __restrict__ Vhg, const bf16* __restrict__ Vlg,
                      const float* __restrict__ mbf,
                      const int* __restrict__ actg, const int* __restrict__ nag,
                      bf16* __restrict__ Aho, bf16* __restrict__ Alo) {
    extern __shared__ char smraw[];
    __shared__ int act_s[64];
    const u32 QhB = s2u(smraw), QlB = QhB + 16384;

    const int n = blockIdx.z, h = blockIdx.y;
    const int q0 = blockIdx.x * 128;
    const size_t hb = ((size_t)(n * NH + h)) * TT * DH;
    const float* mb = mbf + (size_t)n * TT;

    const int tid = threadIdx.x, lane = tid & 31, wid = tid >> 5;
    const int g = lane >> 2, t4 = lane & 3;

    // Stage Q hi/lo (its own commit group; drains with the first K wait)
#pragma unroll
    for (int i = tid; i < 2048; i += 256) {
        int arr = i >> 10, r = (i >> 3) & 127, c = i & 7;
        const bf16* src = (arr ? Qlg : Qhg) + hb + (size_t)(q0 + r) * DH + c * 8;
        cpa16(QhB + arr * 16384 + swz(r, c), src);
    }
    CP_COMMIT();

    if (tid < 64) act_s[tid] = actg[n * 64 + tid];
    const int na = nag[n];
    __syncthreads();

    // K half of a KV stage (Kh+Kl, 16KB)
    auto load_k = [&](int kb) {
        u32 base = s2u(smraw + 32768 + (kb & 1) * 32768);
        int c0 = kb * 64;
#pragma unroll
        for (int i = tid; i < 1024; i += 256) {
            int arr = i >> 9, r = (i >> 3) & 63, c = i & 7;
            const bf16* gsrc = (arr == 0) ? Khg : Klg;
            cpa16(base + arr * 8192 + swz(r, c),
                  gsrc + hb + (size_t)(c0 + r) * DH + c * 8);
        }
    };
    // V half of a KV stage (Vh+Vl, 16KB)
    auto load_v = [&](int kb) {
        u32 base = s2u(smraw + 32768 + (kb & 1) * 32768) + 16384;
        int c0 = kb * 64;
#pragma unroll
        for (int i = tid; i < 1024; i += 256) {
            int arr = i >> 9, r = (i >> 3) & 63, c = i & 7;
            const bf16* gsrc = (arr == 0) ? Vhg : Vlg;
            cpa16(base + arr * 8192 + swz(r, c),
                  gsrc + hb + (size_t)(c0 + r) * DH + c * 8);
        }
    };

    float oacc[8][4];
#pragma unroll
    for (int a = 0; a < 8; a++)
#pragma unroll
        for (int b = 0; b < 4; b++) oacc[a][b] = 0.0f;
    float mrow0 = -1e30f, mrow1 = -1e30f, lrow0 = 0.0f, lrow1 = 0.0f;

    if (na > 0) {
        load_k(0); CP_COMMIT();
        load_v(0); CP_COMMIT();
    }

#pragma unroll 1
    for (int kb = 0; kb < na; kb++) {
        const bool more = (kb + 1 < na);
        if (more) {
            load_k(kb + 1); CP_COMMIT();
            load_v(kb + 1); CP_COMMIT();
        }

        const int af = act_s[kb];
        const int c0 = kb * 64;
        u32 KhB = s2u(smraw + 32768 + (kb & 1) * 32768);
        u32 KlB = KhB + 8192, VhB = KhB + 16384, VlB = KhB + 24576;

        // ---- wait for K(kb) (allow V(kb) + next K/V pending) ----
        if (more) { CP_WAIT(3); } else { CP_WAIT(1); }
        __syncthreads();

        float sacc[8][4];
        if (af) {
            // ---- S = Q K^T (t-domain: Q carries 0.125*log2e) ----
#pragma unroll
            for (int a = 0; a < 8; a++)
#pragma unroll
                for (int b = 0; b < 4; b++) sacc[a][b] = 0.0f;

#pragma unroll
            for (int kt = 0; kt < 4; kt++) {
                u32 qh[4], ql[4];
                ldsm4(qh[0], qh[1], qh[2], qh[3],
                      frag_addr(QhB, wid * 16, kt * 2, lane));
                ldsm4(ql[0], ql[1], ql[2], ql[3],
                      frag_addr(QlB, wid * 16, kt * 2, lane));
#pragma unroll
                for (int hf = 0; hf < 4; hf++) {
                    u32 k0r, k1r, k2r, k3r, l0r, l1r, l2r, l3r;
                    ldsm4(k0r, k1r, k2r, k3r,
                          frag_addr(KhB, hf * 16, kt * 2, lane));
                    ldsm4(l0r, l1r, l2r, l3r,
                          frag_addr(KlB, hf * 16, kt * 2, lane));
                    mma16816(sacc[2 * hf],     qh[0], qh[1], qh[2], qh[3], k0r, k2r);
                    mma16816(sacc[2 * hf],     qh[0], qh[1], qh[2], qh[3], l0r, l2r);
                    mma16816(sacc[2 * hf],     ql[0], ql[1], ql[2], ql[3], k0r, k2r);
                    mma16816(sacc[2 * hf + 1], qh[0], qh[1], qh[2], qh[3], k1r, k3r);
                    mma16816(sacc[2 * hf + 1], qh[0], qh[1], qh[2], qh[3], l1r, l3r);
                    mma16816(sacc[2 * hf + 1], ql[0], ql[1], ql[2], ql[3], k1r, k3r);
                }
            }

            if (af == 1) {
#pragma unroll
                for (int nt = 0; nt < 8; nt++) {
                    float2 mk = *reinterpret_cast<const float2*>(
                        &mb[c0 + nt * 8 + t4 * 2]);
                    sacc[nt][0] += mk.x;
                    sacc[nt][1] += mk.y;
                    sacc[nt][2] += mk.x;
                    sacc[nt][3] += mk.y;
                }
            }

            // ---- online softmax (base-2 domain) ----
            float rmax0 = -1e30f, rmax1 = -1e30f;
#pragma unroll
            for (int nt = 0; nt < 8; nt++) {
                rmax0 = fmaxf(rmax0, fmaxf(sacc[nt][0], sacc[nt][1]));
                rmax1 = fmaxf(rmax1, fmaxf(sacc[nt][2], sacc[nt][3]));
            }
            rmax0 = fmaxf(rmax0, __shfl_xor_sync(0xffffffffu, rmax0, 1));
            rmax0 = fmaxf(rmax0, __shfl_xor_sync(0xffffffffu, rmax0, 2));
            rmax1 = fmaxf(rmax1, __shfl_xor_sync(0xffffffffu, rmax1, 1));
            rmax1 = fmaxf(rmax1, __shfl_xor_sync(0xffffffffu, rmax1, 2));
            float mp0 = mrow0, mp1 = mrow1;
            float mn0 = fmaxf(mrow0, rmax0), mn1 = fmaxf(mrow1, rmax1);
            float corr0 = ex2(mp0 - mn0), corr1 = ex2(mp1 - mn1);
            mrow0 = mn0; mrow1 = mn1;
            float rs0 = 0.0f, rs1 = 0.0f;
#pragma unroll
            for (int nt = 0; nt < 8; nt++) {
                sacc[nt][0] = ex2(sacc[nt][0] - mn0);
                sacc[nt][1] = ex2(sacc[nt][1] - mn0);
                sacc[nt][2] = ex2(sacc[nt][2] - mn1);
                sacc[nt][3] = ex2(sacc[nt][3] - mn1);
                rs0 += sacc[nt][0] + sacc[nt][1];
                rs1 += sacc[nt][2] + sacc[nt][3];
            }
            rs0 += __shfl_xor_sync(0xffffffffu, rs0, 1);
            rs0 += __shfl_xor_sync(0xffffffffu, rs0, 2);
            rs1 += __shfl_xor_sync(0xffffffffu, rs1, 1);
            rs1 += __shfl_xor_sync(0xffffffffu, rs1, 2);
            lrow0 = lrow0 * corr0 + rs0;
            lrow1 = lrow1 * corr1 + rs1;
            if (mn0 != mp0 || mn1 != mp1) {
#pragma unroll
                for (int dt = 0; dt < 8; dt++) {
                    oacc[dt][0] *= corr0; oacc[dt][1] *= corr0;
                    oacc[dt][2] *= corr1; oacc[dt][3] *= corr1;
                }
            }
        }

        // ---- wait for V(kb) (allow next K/V pending) ----
        if (more) { CP_WAIT(2); } else { CP_WAIT(0); }
        __syncthreads();

        if (af) {
            // ---- O += P V ----
#pragma unroll
            for (int j = 0; j < 4; j++) {
                u32 pa_h[4], pa_l[4];
                {
                    bf162 h0 = __floats2bfloat162_rn(sacc[2 * j][0], sacc[2 * j][1]);
                    bf162 h1 = __floats2bfloat162_rn(sacc[2 * j][2], sacc[2 * j][3]);
                    bf162 h2 = __floats2bfloat162_rn(sacc[2 * j + 1][0], sacc[2 * j + 1][1]);
                    bf162 h3 = __floats2bfloat162_rn(sacc[2 * j + 1][2], sacc[2 * j + 1][3]);
                    float2 f0 = __bfloat1622float2(h0), f1 = __bfloat1622float2(h1);
                    float2 f2 = __bfloat1622float2(h2), f3 = __bfloat1622float2(h3);
                    pa_h[0] = *(u32*)&h0; pa_h[1] = *(u32*)&h1;
                    pa_h[2] = *(u32*)&h2; pa_h[3] = *(u32*)&h3;
                    pa_l[0] = pkbf(sacc[2 * j][0] - f0.x, sacc[2 * j][1] - f0.y);
                    pa_l[1] = pkbf(sacc[2 * j][2] - f1.x, sacc[2 * j][3] - f1.y);
                    pa_l[2] = pkbf(sacc[2 * j + 1][0] - f2.x, sacc[2 * j + 1][1] - f2.y);
                    pa_l[3] = pkbf(sacc[2 * j + 1][2] - f3.x, sacc[2 * j + 1][3] - f3.y);
                }
#pragma unroll
                for (int c = 0; c < 4; c++) {
                    u32 v0, v1, v2, v3, w0, w1, w2, w3;
                    ldsm4t(v0, v1, v2, v3, frag_addr(VhB, j * 16, c * 2, lane));
                    ldsm4t(w0, w1, w2, w3, frag_addr(VlB, j * 16, c * 2, lane));
                    mma16816(oacc[2 * c],     pa_h[0], pa_h[1], pa_h[2], pa_h[3], v0, v1);
                    mma16816(oacc[2 * c],     pa_h[0], pa_h[1], pa_h[2], pa_h[3], w0, w1);
                    mma16816(oacc[2 * c],     pa_l[0], pa_l[1], pa_l[2], pa_l[3], v0, v1);
                    mma16816(oacc[2 * c + 1], pa_h[0], pa_h[1], pa_h[2], pa_h[3], v2, v3);
                    mma16816(oacc[2 * c + 1], pa_h[0], pa_h[1], pa_h[2], pa_h[3], w2, w3);
                    mma16816(oacc[2 * c + 1], pa_l[0], pa_l[1], pa_l[2], pa_l[3], v2, v3);
                }
            }
        }
        __syncthreads();   // all reads of buffer kb done before kb+2 loads
    }

    // ---- normalize + split-write [n, t, h*64 + d] as bf16 hi/lo ----
    float inv0 = 1.0f / lrow0, inv1 = 1.0f / lrow1;
#pragma unroll
    for (int dt = 0; dt < 8; dt++) {
        int col = h * DH + dt * 8 + t4 * 2;
        size_t r1 = (size_t)n * TT + q0 + wid * 16 + g;
        float a0 = oacc[dt][0] * inv0, a1 = oacc[dt][1] * inv0;
        float b0 = oacc[dt][2] * inv1, b1 = oacc[dt][3] * inv1;
        bf162 ha = __floats2bfloat162_rn(a0, a1);
        float2 fa = __bfloat1622float2(ha);
        bf162 la = __floats2bfloat162_rn(a0 - fa.x, a1 - fa.y);
        bf162 hbv = __floats2bfloat162_rn(b0, b1);
        float2 fb = __bfloat1622float2(hbv);
        bf162 lb = __floats2bfloat162_rn(b0 - fb.x, b1 - fb.y);
        *reinterpret_cast<bf162*>(&Aho[r1 * DM + col]) = ha;
        *reinterpret_cast<bf162*>(&Alo[r1 * DM + col]) = la;
        *reinterpret_cast<bf162*>(&Aho[(r1 + 8) * DM + col]) = hbv;
        *reinterpret_cast<bf162*>(&Alo[(r1 + 8) * DM + col]) = lb;
    }
}

// ---------------------------------------------------------------------------
// Launch
// ---------------------------------------------------------------------------
extern "C" void kernel_launch(void* const* d_in, const int* in_sizes, int n_in,
                              void* d_out, int out_size) {
    const float* x  = (const float*)d_in[0];
    const int*   mask = (const int*)d_in[1];
    const float* Wq = (const float*)d_in[2];
    const float* bq = (const float*)d_in[3];
    const float* Wk = (const float*)d_in[4];
    const float* bk = (const float*)d_in[5];
    const float* Wv = (const float*)d_in[6];
    const float* bv = (const float*)d_in[7];
    const float* Wo = (const float*)d_in[8];
    const float* bo = (const float*)d_in[9];
    float* out = (float*)d_out;

    bf16 *xh, *xl, *wqh, *wql, *wkh, *wkl, *wvh, *wvl, *woh, *wol;
    bf16 *qh, *ql, *kh, *kl, *vh, *vl, *ah, *al;
    float *mf;
    int *actg, *nag;
    cudaGetSymbolAddress((void**)&xh, g_xh);
    cudaGetSymbolAddress((void**)&xl, g_xl);
    cudaGetSymbolAddress((void**)&wqh, g_wqh);
    cudaGetSymbolAddress((void**)&wql, g_wql);
    cudaGetSymbolAddress((void**)&wkh, g_wkh);
    cudaGetSymbolAddress((void**)&wkl, g_wkl);
    cudaGetSymbolAddress((void**)&wvh, g_wvh);
    cudaGetSymbolAddress((void**)&wvl, g_wvl);
    cudaGetSymbolAddress((void**)&woh, g_woh);
    cudaGetSymbolAddress((void**)&wol, g_wol);
    cudaGetSymbolAddress((void**)&qh, g_qh);
    cudaGetSymbolAddress((void**)&ql, g_ql);
    cudaGetSymbolAddress((void**)&kh, g_kh);
    cudaGetSymbolAddress((void**)&kl, g_kl);
    cudaGetSymbolAddress((void**)&vh, g_vh);
    cudaGetSymbolAddress((void**)&vl, g_vl);
    cudaGetSymbolAddress((void**)&ah, g_ah);
    cudaGetSymbolAddress((void**)&al, g_al);
    cudaGetSymbolAddress((void**)&mf, g_maskf);
    cudaGetSymbolAddress((void**)&actg, g_act);
    cudaGetSymbolAddress((void**)&nag, g_na);

    cudaFuncSetAttribute(gemm_qkv_kernel,
                         cudaFuncAttributeMaxDynamicSharedMemorySize, 98304);
    cudaFuncSetAttribute(gemm_out_kernel,
                         cudaFuncAttributeMaxDynamicSharedMemorySize, 98304);
    cudaFuncSetAttribute(flash_mma_kernel,
                         cudaFuncAttributeMaxDynamicSharedMemorySize, 98304);

    prep_mask_kernel<<<NB, 64>>>(mask, mf, actg, nag);

    const int xn4 = MROWS * DM / 4;
    const int wn4 = DM * DM / 4;
    split_kernel<<<(xn4 + 255) / 256, 256>>>(x, xh, xl, xn4);
    split4w_kernel<<<(4 * wn4 + 255) / 256, 256>>>(
        Wq, Wk, Wv, Wo, wqh, wql, wkh, wkl, wvh, wvl, woh, wol, wn4);

    dim3 qkvgrid(MROWS / 128, DM / 128, 3);
    gemm_qkv_kernel<<<qkvgrid, 256, 98304>>>(
        xh, xl, wqh, wql, wkh, wkl, wvh, wvl, bq, bk, bv,
        qh, ql, kh, kl, vh, vl);

    dim3 agrid(TT / 128, NH, NB);
    flash_mma_kernel<<<agrid, 256, 98304>>>(qh, ql, kh, kl, vh, vl, mf,
                                            actg, nag, ah, al);

    dim3 ogrid(MROWS / 128, DM / 128);
    gemm_out_kernel<<<ogrid, 256, 98304>>>(ah, al, woh, wol, bo, out);
}

// round 13
// speedup vs baseline: 3.7206x; 1.0203x over previous
#include <cuda_runtime.h>
#include <cuda_bf16.h>
#include <cstdint>

#define NB 2
#define TT 4096
#define DM 768
#define NH 12
#define DH 64
#define MROWS (NB * TT)   // 8192

typedef uint32_t u32;
typedef __nv_bfloat16 bf16;
typedef __nv_bfloat162 bf162;

#define QSCALE 0.18033688011112042f   // 0.125 * log2(e)

// ---------------------------------------------------------------------------
// Scratch in __device__ globals (allocation-free rule)
// ---------------------------------------------------------------------------
__device__ bf16 g_xh[(size_t)MROWS * DM];
__device__ bf16 g_xl[(size_t)MROWS * DM];
__device__ bf16 g_wqh[(size_t)DM * DM];
__device__ bf16 g_wql[(size_t)DM * DM];
__device__ bf16 g_wkh[(size_t)DM * DM];
__device__ bf16 g_wkl[(size_t)DM * DM];
__device__ bf16 g_wvh[(size_t)DM * DM];
__device__ bf16 g_wvl[(size_t)DM * DM];
__device__ bf16 g_woh[(size_t)DM * DM];
__device__ bf16 g_wol[(size_t)DM * DM];
__device__ bf16 g_qh[(size_t)MROWS * DM];
__device__ bf16 g_ql[(size_t)MROWS * DM];
__device__ bf16 g_kh[(size_t)MROWS * DM];
__device__ bf16 g_kl[(size_t)MROWS * DM];
__device__ bf16 g_vh[(size_t)MROWS * DM];
__device__ bf16 g_vl[(size_t)MROWS * DM];
__device__ bf16 g_ah[(size_t)MROWS * DM];
__device__ bf16 g_al[(size_t)MROWS * DM];
__device__ float g_maskf[(size_t)NB * TT];   // t-domain: 0 or -1e30*log2e
__device__ int   g_act[NB * 64];             // 0=skip, 1=partial, 2=full
__device__ int   g_na[NB];                   // last active tile + 1

// ---------------------------------------------------------------------------
// Helpers
// ---------------------------------------------------------------------------
__device__ __forceinline__ u32 s2u(const void* p) {
    return (u32)__cvta_generic_to_shared(p);
}
// L2-only (cg) 16B async copy — staged tiles are stream-once
__device__ __forceinline__ void cpa16(u32 dst, const void* src) {
    asm volatile("cp.async.cg.shared.global [%0], [%1], 16;" :: "r"(dst), "l"(src));
}
#define CP_COMMIT()  asm volatile("cp.async.commit_group;")
#define CP_WAIT(N)   asm volatile("cp.async.wait_group %0;" :: "n"(N))

__device__ __forceinline__ void ldsm4(u32& r0, u32& r1, u32& r2, u32& r3, u32 a) {
    asm volatile("ldmatrix.sync.aligned.m8n8.x4.shared.b16 {%0,%1,%2,%3},[%4];"
                 : "=r"(r0), "=r"(r1), "=r"(r2), "=r"(r3) : "r"(a));
}
__device__ __forceinline__ void ldsm4t(u32& r0, u32& r1, u32& r2, u32& r3, u32 a) {
    asm volatile("ldmatrix.sync.aligned.m8n8.x4.trans.shared.b16 {%0,%1,%2,%3},[%4];"
                 : "=r"(r0), "=r"(r1), "=r"(r2), "=r"(r3) : "r"(a));
}
__device__ __forceinline__ void mma16816(float* c, u32 a0, u32 a1, u32 a2, u32 a3,
                                         u32 b0, u32 b1) {
    asm volatile(
        "mma.sync.aligned.m16n8k16.row.col.f32.bf16.bf16.f32 "
        "{%0,%1,%2,%3},{%4,%5,%6,%7},{%8,%9},{%0,%1,%2,%3};"
        : "+f"(c[0]), "+f"(c[1]), "+f"(c[2]), "+f"(c[3])
        : "r"(a0), "r"(a1), "r"(a2), "r"(a3), "r"(b0), "r"(b1));
}
__device__ __forceinline__ u32 pkbf(float lo, float hi) {
    bf162 t = __floats2bfloat162_rn(lo, hi);
    return *reinterpret_cast<u32*>(&t);
}
__device__ __forceinline__ float ex2(float x) {
    float y;
    asm("ex2.approx.ftz.f32 %0, %1;" : "=f"(y) : "f"(x));
    return y;
}
// Swizzled byte offset in a tile with 128B rows (8x 16B chunks per row)
__device__ __forceinline__ u32 swz(int row, int chunk) {
    return (u32)(row * 128 + ((chunk ^ (row & 7)) << 4));
}
__device__ __forceinline__ u32 frag_addr(u32 base, int r0, int c0, int lane) {
    return base + swz(r0 + (lane & 15), c0 + (lane >> 4));
}

// ---------------------------------------------------------------------------
// Mask prep
// ---------------------------------------------------------------------------
__global__ void prep_mask_kernel(const int* __restrict__ mask,
                                 float* __restrict__ out,
                                 int* __restrict__ actg, int* __restrict__ nag) {
    __shared__ int s_any[64];
    const int n = blockIdx.x, t = threadIdx.x;
    bool any = false, all = true;
#pragma unroll 8
    for (int j = 0; j < 64; j++) {
        int m = mask[n * TT + t * 64 + j];
        out[n * TT + t * 64 + j] = m ? -1.4426950e30f : 0.0f;
        any |= (m == 0);
        all &= (m == 0);
    }
    actg[n * 64 + t] = any ? (all ? 2 : 1) : 0;
    s_any[t] = any ? 1 : 0;
    __syncthreads();
    if (t == 0) {
        int na = 0;
        for (int j = 0; j < 64; j++)
            if (s_any[j]) na = j + 1;
        nag[n] = na;
    }
}

// ---------------------------------------------------------------------------
// fp32 -> bf16 hi/lo split
// ---------------------------------------------------------------------------
__device__ __forceinline__ void split4(float4 v, uint2& h, uint2& l) {
    bf162 h01 = __floats2bfloat162_rn(v.x, v.y);
    bf162 h23 = __floats2bfloat162_rn(v.z, v.w);
    float2 f01 = __bfloat1622float2(h01);
    float2 f23 = __bfloat1622float2(h23);
    bf162 l01 = __floats2bfloat162_rn(v.x - f01.x, v.y - f01.y);
    bf162 l23 = __floats2bfloat162_rn(v.z - f23.x, v.w - f23.y);
    h = make_uint2(*(u32*)&h01, *(u32*)&h23);
    l = make_uint2(*(u32*)&l01, *(u32*)&l23);
}

__global__ void split_kernel(const float* __restrict__ in, bf16* __restrict__ h,
                             bf16* __restrict__ l, int n4) {
    int i = blockIdx.x * blockDim.x + threadIdx.x;
    if (i >= n4) return;
    uint2 hh, ll;
    split4(reinterpret_cast<const float4*>(in)[i], hh, ll);
    reinterpret_cast<uint2*>(h)[i] = hh;
    reinterpret_cast<uint2*>(l)[i] = ll;
}

__global__ void split4w_kernel(const float* __restrict__ W0, const float* __restrict__ W1,
                               const float* __restrict__ W2, const float* __restrict__ W3,
                               bf16* __restrict__ h0, bf16* __restrict__ l0,
                               bf16* __restrict__ h1, bf16* __restrict__ l1,
                               bf16* __restrict__ h2, bf16* __restrict__ l2,
                               bf16* __restrict__ h3, bf16* __restrict__ l3, int n4) {
    int i = blockIdx.x * blockDim.x + threadIdx.x;
    int w = i / n4, j = i - w * n4;
    if (w >= 4) return;
    const float* in = (w == 0) ? W0 : (w == 1) ? W1 : (w == 2) ? W2 : W3;
    bf16* h = (w == 0) ? h0 : (w == 1) ? h1 : (w == 2) ? h2 : h3;
    bf16* l = (w == 0) ? l0 : (w == 1) ? l1 : (w == 2) ? l2 : l3;
    uint2 hh, ll;
    split4(reinterpret_cast<const float4*>(in)[j], hh, ll);
    reinterpret_cast<uint2*>(h)[j] = hh;
    reinterpret_cast<uint2*>(l)[j] = ll;
}

// ---------------------------------------------------------------------------
// 128x128 GEMM mainloop (bf16x3, 3-stage cp.async, BK=32). Used by qkv.
// ---------------------------------------------------------------------------
struct GemmCore {
    float acc[4][4][4];

    __device__ __forceinline__ void run(char* smraw, int tid, int lane,
                                        int wm, int wn, int row0, int col0,
                                        const bf16* Ah, const bf16* Al,
                                        const bf16* Bh, const bf16* Bl) {
#pragma unroll
        for (int a = 0; a < 4; a++)
#pragma unroll
            for (int b = 0; b < 4; b++)
#pragma unroll
                for (int c = 0; c < 4; c++) acc[a][b][c] = 0.0f;

        auto load_stage = [&](int s) {
            char* base = smraw + (s % 3) * 32768;
            u32 ab = s2u(base), bb = ab + 16384;
            int k0 = s * 32;
#pragma unroll
            for (int i = tid; i < 1024; i += 256) {
                int r = i >> 3, c = i & 7;
                const bf16* asrc = (c < 4)
                    ? &Ah[(size_t)(row0 + r) * DM + k0 + c * 8]
                    : &Al[(size_t)(row0 + r) * DM + k0 + (c - 4) * 8];
                cpa16(ab + swz(r, c), asrc);
                const bf16* bsrc = (c < 4)
                    ? &Bh[(size_t)(col0 + r) * DM + k0 + c * 8]
                    : &Bl[(size_t)(col0 + r) * DM + k0 + (c - 4) * 8];
                cpa16(bb + swz(r, c), bsrc);
            }
        };

        load_stage(0); CP_COMMIT();
        load_stage(1); CP_COMMIT();

        const int NS = DM / 32;  // 24
#pragma unroll 1
        for (int s = 0; s < NS; s++) {
            if (s + 1 < NS) { CP_WAIT(1); } else { CP_WAIT(0); }
            __syncthreads();

            u32 ab = s2u(smraw + (s % 3) * 32768), bb = ab + 16384;
#pragma unroll
            for (int kt = 0; kt < 2; kt++) {
                const int ch = 2 * kt, cl = 4 + 2 * kt;
                u32 bhf[4][2], blf[4][2];
#pragma unroll
                for (int half = 0; half < 2; half++) {
                    u32 r0, r1, r2, r3;
                    ldsm4(r0, r1, r2, r3, frag_addr(bb, wn * 32 + half * 16, ch, lane));
                    bhf[2 * half][0] = r0; bhf[2 * half + 1][0] = r1;
                    bhf[2 * half][1] = r2; bhf[2 * half + 1][1] = r3;
                    ldsm4(r0, r1, r2, r3, frag_addr(bb, wn * 32 + half * 16, cl, lane));
                    blf[2 * half][0] = r0; blf[2 * half + 1][0] = r1;
                    blf[2 * half][1] = r2; blf[2 * half + 1][1] = r3;
                }
#pragma unroll
                for (int mt = 0; mt < 4; mt++) {
                    u32 ah4[4], al4[4];
                    ldsm4(ah4[0], ah4[1], ah4[2], ah4[3],
                          frag_addr(ab, wm * 64 + mt * 16, ch, lane));
                    ldsm4(al4[0], al4[1], al4[2], al4[3],
                          frag_addr(ab, wm * 64 + mt * 16, cl, lane));
#pragma unroll
                    for (int nt = 0; nt < 4; nt++) {
                        mma16816(acc[mt][nt], ah4[0], ah4[1], ah4[2], ah4[3],
                                 bhf[nt][0], bhf[nt][1]);
                        mma16816(acc[mt][nt], ah4[0], ah4[1], ah4[2], ah4[3],
                                 blf[nt][0], blf[nt][1]);
                        mma16816(acc[mt][nt], al4[0], al4[1], al4[2], al4[3],
                                 bhf[nt][0], bhf[nt][1]);
                    }
                }
            }
            if (s + 2 < NS) { load_stage(s + 2); CP_COMMIT(); }
        }
    }
};

// ---------------------------------------------------------------------------
// Fused Q/K/V projection (128x128 tiles): blockIdx.z selects weight/output.
// ---------------------------------------------------------------------------
__global__ __launch_bounds__(256, 2)
void gemm_qkv_kernel(const bf16* __restrict__ Xh, const bf16* __restrict__ Xl,
                     const bf16* __restrict__ Wqh, const bf16* __restrict__ Wql,
                     const bf16* __restrict__ Wkh, const bf16* __restrict__ Wkl,
                     const bf16* __restrict__ Wvh, const bf16* __restrict__ Wvl,
                     const float* __restrict__ bq, const float* __restrict__ bk,
                     const float* __restrict__ bv,
                     bf16* __restrict__ Qh, bf16* __restrict__ Ql,
                     bf16* __restrict__ Kh, bf16* __restrict__ Kl,
                     bf16* __restrict__ Vh, bf16* __restrict__ Vl) {
    extern __shared__ char smraw[];
    const int tid = threadIdx.x, lane = tid & 31, wid = tid >> 5;
    const int wm = wid >> 2, wn = wid & 3;
    const int row0 = blockIdx.x * 128, col0 = blockIdx.y * 128;
    const int w = blockIdx.z;

    const bf16* Bh = (w == 0) ? Wqh : (w == 1) ? Wkh : Wvh;
    const bf16* Bl = (w == 0) ? Wql : (w == 1) ? Wkl : Wvl;
    const float* bias = (w == 0) ? bq : (w == 1) ? bk : bv;
    bf16* Ch = (w == 0) ? Qh : (w == 1) ? Kh : Vh;
    bf16* Cl = (w == 0) ? Ql : (w == 1) ? Kl : Vl;
    const float cscale = (w == 0) ? QSCALE : 1.0f;

    GemmCore core;
    core.run(smraw, tid, lane, wm, wn, row0, col0, Xh, Xl, Bh, Bl);

    const int g = lane >> 2, t4 = lane & 3;
#pragma unroll
    for (int mt = 0; mt < 4; mt++)
#pragma unroll
        for (int nt = 0; nt < 4; nt++) {
            int col = col0 + wn * 32 + nt * 8 + t4 * 2;
            float bv0 = bias[col], bv1 = bias[col + 1];
#pragma unroll
            for (int half = 0; half < 2; half++) {
                int row = row0 + wm * 64 + mt * 16 + g + half * 8;
                float c0 = (core.acc[mt][nt][2 * half] + bv0) * cscale;
                float c1 = (core.acc[mt][nt][2 * half + 1] + bv1) * cscale;
                int n = row >> 12, t = row & (TT - 1);
                int h = col >> 6, d = col & 63;
                size_t idx = (((size_t)(n * NH + h)) * TT + t) * DH + d;
                bf162 hi = __floats2bfloat162_rn(c0, c1);
                float2 hf = __bfloat1622float2(hi);
                bf162 lo = __floats2bfloat162_rn(c0 - hf.x, c1 - hf.y);
                *reinterpret_cast<bf162*>(&Ch[idx]) = hi;
                *reinterpret_cast<bf162*>(&Cl[idx]) = lo;
            }
        }
}

// ---------------------------------------------------------------------------
// Output projection: 64x128 tiles (halved CTA work -> better wave packing).
// 8 warps = 2m x 4n, warp tile 32x32 (mt 2 x nt 4). 3-stage cp.async.
// Stage: A 8KB + B 16KB = 24KB; 3 stages = 72KB.
// ---------------------------------------------------------------------------
__global__ __launch_bounds__(256, 2)
void gemm_out_kernel(const bf16* __restrict__ Ahg, const bf16* __restrict__ Alg,
                     const bf16* __restrict__ Bh, const bf16* __restrict__ Bl,
                     const float* __restrict__ bias, float* __restrict__ C) {
    extern __shared__ char smraw[];
    const int tid = threadIdx.x, lane = tid & 31, wid = tid >> 5;
    const int wm = wid >> 2, wn = wid & 3;
    const int row0 = blockIdx.x * 64, col0 = blockIdx.y * 128;

    float acc[2][4][4];
#pragma unroll
    for (int a = 0; a < 2; a++)
#pragma unroll
        for (int b = 0; b < 4; b++)
#pragma unroll
            for (int c = 0; c < 4; c++) acc[a][b][c] = 0.0f;

    auto load_stage = [&](int s) {
        char* base = smraw + (s % 3) * 24576;
        u32 ab = s2u(base), bb = ab + 8192;
        int k0 = s * 32;
        // A: 64 rows x 8 chunks = 512; B: 128 rows x 8 chunks = 1024
#pragma unroll
        for (int i = tid; i < 512; i += 256) {
            int r = i >> 3, c = i & 7;
            const bf16* asrc = (c < 4)
                ? &Ahg[(size_t)(row0 + r) * DM + k0 + c * 8]
                : &Alg[(size_t)(row0 + r) * DM + k0 + (c - 4) * 8];
            cpa16(ab + swz(r, c), asrc);
        }
#pragma unroll
        for (int i = tid; i < 1024; i += 256) {
            int r = i >> 3, c = i & 7;
            const bf16* bsrc = (c < 4)
                ? &Bh[(size_t)(col0 + r) * DM + k0 + c * 8]
                : &Bl[(size_t)(col0 + r) * DM + k0 + (c - 4) * 8];
            cpa16(bb + swz(r, c), bsrc);
        }
    };

    load_stage(0); CP_COMMIT();
    load_stage(1); CP_COMMIT();

    const int NS = DM / 32;  // 24
#pragma unroll 1
    for (int s = 0; s < NS; s++) {
        if (s + 1 < NS) { CP_WAIT(1); } else { CP_WAIT(0); }
        __syncthreads();

        u32 ab = s2u(smraw + (s % 3) * 24576), bb = ab + 8192;
#pragma unroll
        for (int kt = 0; kt < 2; kt++) {
            const int ch = 2 * kt, cl = 4 + 2 * kt;
            u32 bhf[4][2], blf[4][2];
#pragma unroll
            for (int half = 0; half < 2; half++) {
                u32 r0, r1, r2, r3;
                ldsm4(r0, r1, r2, r3, frag_addr(bb, wn * 32 + half * 16, ch, lane));
                bhf[2 * half][0] = r0; bhf[2 * half + 1][0] = r1;
                bhf[2 * half][1] = r2; bhf[2 * half + 1][1] = r3;
                ldsm4(r0, r1, r2, r3, frag_addr(bb, wn * 32 + half * 16, cl, lane));
                blf[2 * half][0] = r0; blf[2 * half + 1][0] = r1;
                blf[2 * half][1] = r2; blf[2 * half + 1][1] = r3;
            }
#pragma unroll
            for (int mt = 0; mt < 2; mt++) {
                u32 ah4[4], al4[4];
                ldsm4(ah4[0], ah4[1], ah4[2], ah4[3],
                      frag_addr(ab, wm * 32 + mt * 16, ch, lane));
                ldsm4(al4[0], al4[1], al4[2], al4[3],
                      frag_addr(ab, wm * 32 + mt * 16, cl, lane));
#pragma unroll
                for (int nt = 0; nt < 4; nt++) {
                    mma16816(acc[mt][nt], ah4[0], ah4[1], ah4[2], ah4[3],
                             bhf[nt][0], bhf[nt][1]);
                    mma16816(acc[mt][nt], ah4[0], ah4[1], ah4[2], ah4[3],
                             blf[nt][0], blf[nt][1]);
                    mma16816(acc[mt][nt], al4[0], al4[1], al4[2], al4[3],
                             bhf[nt][0], bhf[nt][1]);
                }
            }
        }
        if (s + 2 < NS) { load_stage(s + 2); CP_COMMIT(); }
    }

    const int g = lane >> 2, t4 = lane & 3;
#pragma unroll
    for (int mt = 0; mt < 2; mt++)
#pragma unroll
        for (int nt = 0; nt < 4; nt++) {
            int col = col0 + wn * 32 + nt * 8 + t4 * 2;
            float bv0 = bias[col], bv1 = bias[col + 1];
#pragma unroll
            for (int half = 0; half < 2; half++) {
                int row = row0 + wm * 32 + mt * 16 + g + half * 8;
                float c0 = acc[mt][nt][2 * half] + bv0;
                float c1 = acc[mt][nt][2 * half + 1] + bv1;
                *reinterpret_cast<float2*>(&C[(size_t)row * DM + col]) =
                    make_float2(c0, c1);
            }
        }
}

// ---------------------------------------------------------------------------
// P fragment conversion (fp32 sacc pair -> bf16 hi/lo A-fragments)
// ---------------------------------------------------------------------------
struct PFrag { u32 h[4], l[4]; };

__device__ __forceinline__ PFrag cvt_pfrag(const float s0[4], const float s1[4]) {
    PFrag p;
    bf162 h0 = __floats2bfloat162_rn(s0[0], s0[1]);
    bf162 h1 = __floats2bfloat162_rn(s0[2], s0[3]);
    bf162 h2 = __floats2bfloat162_rn(s1[0], s1[1]);
    bf162 h3 = __floats2bfloat162_rn(s1[2], s1[3]);
    float2 f0 = __bfloat1622float2(h0), f1 = __bfloat1622float2(h1);
    float2 f2 = __bfloat1622float2(h2), f3 = __bfloat1622float2(h3);
    p.h[0] = *(u32*)&h0; p.h[1] = *(u32*)&h1;
    p.h[2] = *(u32*)&h2; p.h[3] = *(u32*)&h3;
    p.l[0] = pkbf(s0[0] - f0.x, s0[1] - f0.y);
    p.l[1] = pkbf(s0[2] - f1.x, s0[3] - f1.y);
    p.l[2] = pkbf(s1[0] - f2.x, s1[1] - f2.y);
    p.l[3] = pkbf(s1[2] - f3.x, s1[3] - f3.y);
    return p;
}

// ---------------------------------------------------------------------------
// Flash attention (split K/V waits, pipelined P conversion).
// ---------------------------------------------------------------------------
__global__ __launch_bounds__(256, 2)
void flash_mma_kernel(const bf16* __restrict__ Qhg, const bf16* __restrict__ Qlg,
                      const bf16* __restrict__ Khg, const bf16* __restrict__ Klg,
                      const bf16* __restrict__ Vhg, const bf16* __restrict__ Vlg,
                      const float* __restrict__ mbf,
                      const int* __restrict__ actg, const int* __restrict__ nag,
                      bf16* __restrict__ Aho, bf16* __restrict__ Alo) {
    extern __shared__ char smraw[];
    __shared__ int act_s[64];
    const u32 QhB = s2u(smraw), QlB = QhB + 16384;

    const int n = blockIdx.z, h = blockIdx.y;
    const int q0 = blockIdx.x * 128;
    const size_t hb = ((size_t)(n * NH + h)) * TT * DH;
    const float* mb = mbf + (size_t)n * TT;

    const int tid = threadIdx.x, lane = tid & 31, wid = tid >> 5;
    const int g = lane >> 2, t4 = lane & 3;

#pragma unroll
    for (int i = tid; i < 2048; i += 256) {
        int arr = i >> 10, r = (i >> 3) & 127, c = i & 7;
        const bf16* src = (arr ? Qlg : Qhg) + hb + (size_t)(q0 + r) * DH + c * 8;
        cpa16(QhB + arr * 16384 + swz(r, c), src);
    }
    CP_COMMIT();

    if (tid < 64) act_s[tid] = actg[n * 64 + tid];
    const int na = nag[n];
    __syncthreads();

    auto load_k = [&](int kb) {
        u32 base = s2u(smraw + 32768 + (kb & 1) * 32768);
        int c0 = kb * 64;
#pragma unroll
        for (int i = tid; i < 1024; i += 256) {
            int arr = i >> 9, r = (i >> 3) & 63, c = i & 7;
            const bf16* gsrc = (arr == 0) ? Khg : Klg;
            cpa16(base + arr * 8192 + swz(r, c),
                  gsrc + hb + (size_t)(c0 + r) * DH + c * 8);
        }
    };
    auto load_v = [&](int kb) {
        u32 base = s2u(smraw + 32768 + (kb & 1) * 32768) + 16384;
        int c0 = kb * 64;
#pragma unroll
        for (int i = tid; i < 1024; i += 256) {
            int arr = i >> 9, r = (i >> 3) & 63, c = i & 7;
            const bf16* gsrc = (arr == 0) ? Vhg : Vlg;
            cpa16(base + arr * 8192 + swz(r, c),
                  gsrc + hb + (size_t)(c0 + r) * DH + c * 8);
        }
    };

    float oacc[8][4];
#pragma unroll
    for (int a = 0; a < 8; a++)
#pragma unroll
        for (int b = 0; b < 4; b++) oacc[a][b] = 0.0f;
    float mrow0 = -1e30f, mrow1 = -1e30f, lrow0 = 0.0f, lrow1 = 0.0f;

    if (na > 0) {
        load_k(0); CP_COMMIT();
        load_v(0); CP_COMMIT();
    }

#pragma unroll 1
    for (int kb = 0; kb < na; kb++) {
        const bool more = (kb + 1 < na);
        if (more) {
            load_k(kb + 1); CP_COMMIT();
            load_v(kb + 1); CP_COMMIT();
        }

        const int af = act_s[kb];
        const int c0 = kb * 64;
        u32 KhB = s2u(smraw + 32768 + (kb & 1) * 32768);
        u32 KlB = KhB + 8192, VhB = KhB + 16384, VlB = KhB + 24576;

        // ---- wait for K(kb) ----
        if (more) { CP_WAIT(3); } else { CP_WAIT(1); }
        __syncthreads();

        float sacc[8][4];
        if (af) {
            // ---- S = Q K^T ----
#pragma unroll
            for (int a = 0; a < 8; a++)
#pragma unroll
                for (int b = 0; b < 4; b++) sacc[a][b] = 0.0f;

#pragma unroll
            for (int kt = 0; kt < 4; kt++) {
                u32 qh[4], ql[4];
                ldsm4(qh[0], qh[1], qh[2], qh[3],
                      frag_addr(QhB, wid * 16, kt * 2, lane));
                ldsm4(ql[0], ql[1], ql[2], ql[3],
                      frag_addr(QlB, wid * 16, kt * 2, lane));
#pragma unroll
                for (int hf = 0; hf < 4; hf++) {
                    u32 k0r, k1r, k2r, k3r, l0r, l1r, l2r, l3r;
                    ldsm4(k0r, k1r, k2r, k3r,
                          frag_addr(KhB, hf * 16, kt * 2, lane));
                    ldsm4(l0r, l1r, l2r, l3r,
                          frag_addr(KlB, hf * 16, kt * 2, lane));
                    mma16816(sacc[2 * hf],     qh[0], qh[1], qh[2], qh[3], k0r, k2r);
                    mma16816(sacc[2 * hf],     qh[0], qh[1], qh[2], qh[3], l0r, l2r);
                    mma16816(sacc[2 * hf],     ql[0], ql[1], ql[2], ql[3], k0r, k2r);
                    mma16816(sacc[2 * hf + 1], qh[0], qh[1], qh[2], qh[3], k1r, k3r);
                    mma16816(sacc[2 * hf + 1], qh[0], qh[1], qh[2], qh[3], l1r, l3r);
                    mma16816(sacc[2 * hf + 1], ql[0], ql[1], ql[2], ql[3], k1r, k3r);
                }
            }

            if (af == 1) {
#pragma unroll
                for (int nt = 0; nt < 8; nt++) {
                    float2 mk = *reinterpret_cast<const float2*>(
                        &mb[c0 + nt * 8 + t4 * 2]);
                    sacc[nt][0] += mk.x;
                    sacc[nt][1] += mk.y;
                    sacc[nt][2] += mk.x;
                    sacc[nt][3] += mk.y;
                }
            }

            // ---- online softmax (base-2 domain) ----
            float rmax0 = -1e30f, rmax1 = -1e30f;
#pragma unroll
            for (int nt = 0; nt < 8; nt++) {
                rmax0 = fmaxf(rmax0, fmaxf(sacc[nt][0], sacc[nt][1]));
                rmax1 = fmaxf(rmax1, fmaxf(sacc[nt][2], sacc[nt][3]));
            }
            rmax0 = fmaxf(rmax0, __shfl_xor_sync(0xffffffffu, rmax0, 1));
            rmax0 = fmaxf(rmax0, __shfl_xor_sync(0xffffffffu, rmax0, 2));
            rmax1 = fmaxf(rmax1, __shfl_xor_sync(0xffffffffu, rmax1, 1));
            rmax1 = fmaxf(rmax1, __shfl_xor_sync(0xffffffffu, rmax1, 2));
            float mp0 = mrow0, mp1 = mrow1;
            float mn0 = fmaxf(mrow0, rmax0), mn1 = fmaxf(mrow1, rmax1);
            float corr0 = ex2(mp0 - mn0), corr1 = ex2(mp1 - mn1);
            mrow0 = mn0; mrow1 = mn1;
            float rs0 = 0.0f, rs1 = 0.0f;
#pragma unroll
            for (int nt = 0; nt < 8; nt++) {
                sacc[nt][0] = ex2(sacc[nt][0] - mn0);
                sacc[nt][1] = ex2(sacc[nt][1] - mn0);
                sacc[nt][2] = ex2(sacc[nt][2] - mn1);
                sacc[nt][3] = ex2(sacc[nt][3] - mn1);
                rs0 += sacc[nt][0] + sacc[nt][1];
                rs1 += sacc[nt][2] + sacc[nt][3];
            }
            rs0 += __shfl_xor_sync(0xffffffffu, rs0, 1);
            rs0 += __shfl_xor_sync(0xffffffffu, rs0, 2);
            rs1 += __shfl_xor_sync(0xffffffffu, rs1, 1);
            rs1 += __shfl_xor_sync(0xffffffffu, rs1, 2);
            lrow0 = lrow0 * corr0 + rs0;
            lrow1 = lrow1 * corr1 + rs1;
            if (mn0 != mp0 || mn1 != mp1) {
#pragma unroll
                for (int dt = 0; dt < 8; dt++) {
                    oacc[dt][0] *= corr0; oacc[dt][1] *= corr0;
                    oacc[dt][2] *= corr1; oacc[dt][3] *= corr1;
                }
            }
        }

        // ---- convert j=0's P fragments BEFORE the V wait (off critical path) --
        PFrag pa;
        if (af) pa = cvt_pfrag(sacc[0], sacc[1]);

        // ---- wait for V(kb) ----
        if (more) { CP_WAIT(2); } else { CP_WAIT(0); }
        __syncthreads();

        if (af) {
            // ---- O += P V (convert j+1 while issuing j's MMAs) ----
#pragma unroll
            for (int j = 0; j < 4; j++) {
                PFrag pnext;
                if (j < 3) pnext = cvt_pfrag(sacc[2 * j + 2], sacc[2 * j + 3]);
#pragma unroll
                for (int c = 0; c < 4; c++) {
                    u32 v0, v1, v2, v3, w0, w1, w2, w3;
                    ldsm4t(v0, v1, v2, v3, frag_addr(VhB, j * 16, c * 2, lane));
                    ldsm4t(w0, w1, w2, w3, frag_addr(VlB, j * 16, c * 2, lane));
                    mma16816(oacc[2 * c],     pa.h[0], pa.h[1], pa.h[2], pa.h[3], v0, v1);
                    mma16816(oacc[2 * c],     pa.h[0], pa.h[1], pa.h[2], pa.h[3], w0, w1);
                    mma16816(oacc[2 * c],     pa.l[0], pa.l[1], pa.l[2], pa.l[3], v0, v1);
                    mma16816(oacc[2 * c + 1], pa.h[0], pa.h[1], pa.h[2], pa.h[3], v2, v3);
                    mma16816(oacc[2 * c + 1], pa.h[0], pa.h[1], pa.h[2], pa.h[3], w2, w3);
                    mma16816(oacc[2 * c + 1], pa.l[0], pa.l[1], pa.l[2], pa.l[3], v2, v3);
                }
                if (j < 3) pa = pnext;
            }
        }
        __syncthreads();   // all reads of buffer kb done before kb+2 loads
    }

    // ---- normalize + split-write [n, t, h*64 + d] as bf16 hi/lo ----
    float inv0 = 1.0f / lrow0, inv1 = 1.0f / lrow1;
#pragma unroll
    for (int dt = 0; dt < 8; dt++) {
        int col = h * DH + dt * 8 + t4 * 2;
        size_t r1 = (size_t)n * TT + q0 + wid * 16 + g;
        float a0 = oacc[dt][0] * inv0, a1 = oacc[dt][1] * inv0;
        float b0 = oacc[dt][2] * inv1, b1 = oacc[dt][3] * inv1;
        bf162 ha = __floats2bfloat162_rn(a0, a1);
        float2 fa = __bfloat1622float2(ha);
        bf162 la = __floats2bfloat162_rn(a0 - fa.x, a1 - fa.y);
        bf162 hbv = __floats2bfloat162_rn(b0, b1);
        float2 fb = __bfloat1622float2(hbv);
        bf162 lb = __floats2bfloat162_rn(b0 - fb.x, b1 - fb.y);
        *reinterpret_cast<bf162*>(&Aho[r1 * DM + col]) = ha;
        *reinterpret_cast<bf162*>(&Alo[r1 * DM + col]) = la;
        *reinterpret_cast<bf162*>(&Aho[(r1 + 8) * DM + col]) = hbv;
        *reinterpret_cast<bf162*>(&Alo[(r1 + 8) * DM + col]) = lb;
    }
}

// ---------------------------------------------------------------------------
// Launch
// ---------------------------------------------------------------------------
extern "C" void kernel_launch(void* const* d_in, const int* in_sizes, int n_in,
                              void* d_out, int out_size) {
    const float* x  = (const float*)d_in[0];
    const int*   mask = (const int*)d_in[1];
    const float* Wq = (const float*)d_in[2];
    const float* bq = (const float*)d_in[3];
    const float* Wk = (const float*)d_in[4];
    const float* bk = (const float*)d_in[5];
    const float* Wv = (const float*)d_in[6];
    const float* bv = (const float*)d_in[7];
    const float* Wo = (const float*)d_in[8];
    const float* bo = (const float*)d_in[9];
    float* out = (float*)d_out;

    bf16 *xh, *xl, *wqh, *wql, *wkh, *wkl, *wvh, *wvl, *woh, *wol;
    bf16 *qh, *ql, *kh, *kl, *vh, *vl, *ah, *al;
    float *mf;
    int *actg, *nag;
    cudaGetSymbolAddress((void**)&xh, g_xh);
    cudaGetSymbolAddress((void**)&xl, g_xl);
    cudaGetSymbolAddress((void**)&wqh, g_wqh);
    cudaGetSymbolAddress((void**)&wql, g_wql);
    cudaGetSymbolAddress((void**)&wkh, g_wkh);
    cudaGetSymbolAddress((void**)&wkl, g_wkl);
    cudaGetSymbolAddress((void**)&wvh, g_wvh);
    cudaGetSymbolAddress((void**)&wvl, g_wvl);
    cudaGetSymbolAddress((void**)&woh, g_woh);
    cudaGetSymbolAddress((void**)&wol, g_wol);
    cudaGetSymbolAddress((void**)&qh, g_qh);
    cudaGetSymbolAddress((void**)&ql, g_ql);
    cudaGetSymbolAddress((void**)&kh, g_kh);
    cudaGetSymbolAddress((void**)&kl, g_kl);
    cudaGetSymbolAddress((void**)&vh, g_vh);
    cudaGetSymbolAddress((void**)&vl, g_vl);
    cudaGetSymbolAddress((void**)&ah, g_ah);
    cudaGetSymbolAddress((void**)&al, g_al);
    cudaGetSymbolAddress((void**)&mf, g_maskf);
    cudaGetSymbolAddress((void**)&actg, g_act);
    cudaGetSymbolAddress((void**)&nag, g_na);

    cudaFuncSetAttribute(gemm_qkv_kernel,
                         cudaFuncAttributeMaxDynamicSharedMemorySize, 98304);
    cudaFuncSetAttribute(gemm_out_kernel,
                         cudaFuncAttributeMaxDynamicSharedMemorySize, 73728);
    cudaFuncSetAttribute(flash_mma_kernel,
                         cudaFuncAttributeMaxDynamicSharedMemorySize, 98304);

    prep_mask_kernel<<<NB, 64>>>(mask, mf, actg, nag);

    const int xn4 = MROWS * DM / 4;
    const int wn4 = DM * DM / 4;
    split_kernel<<<(xn4 + 255) / 256, 256>>>(x, xh, xl, xn4);
    split4w_kernel<<<(4 * wn4 + 255) / 256, 256>>>(
        Wq, Wk, Wv, Wo, wqh, wql, wkh, wkl, wvh, wvl, woh, wol, wn4);

    dim3 qkvgrid(MROWS / 128, DM / 128, 3);
    gemm_qkv_kernel<<<qkvgrid, 256, 98304>>>(
        xh, xl, wqh, wql, wkh, wkl, wvh, wvl, bq, bk, bv,
        qh, ql, kh, kl, vh, vl);

    dim3 agrid(TT / 128, NH, NB);
    flash_mma_kernel<<<agrid, 256, 98304>>>(qh, ql, kh, kl, vh, vl, mf,
                                            actg, nag, ah, al);

    dim3 ogrid(MROWS / 64, DM / 128);
    gemm_out_kernel<<<ogrid, 256, 73728>>>(ah, al, woh, wol, bo, out);
}